// round 10
// baseline (speedup 1.0000x reference)
#include <cuda_runtime.h>
#include <cuda_fp16.h>
#include <cstdint>

// ---------------------------------------------------------------------------
// Problem constants (fixed shapes)
// ---------------------------------------------------------------------------
#define S      4096
#define DIMM   4096
#define HQ     32
#define HKV    8
#define HD     128
#define NQKV   6144          // (HQ + 2*HKV) * HD
#define TB     512           // S / 8 blocks
#define SINKB  4             // ceil(30/8)
#define WINST  508           // window start block
#define MBTOP  100           // heavy blocks
#define KLBLK  108           // 4 sink + 4 window + 100 heavy
#define KSEL   (KLBLK * 8)   // 864 selected tokens per head
#define NEGF   (-1e30f)
#define SCALE  0.08838834764831845f   // 1/sqrt(128)

// ---------------------------------------------------------------------------
// Scratch (static device globals — no runtime allocation allowed)
// ---------------------------------------------------------------------------
__device__ float g_krep[TB * HKV * HD];       // per-block mean keys
__device__ float g_qmean[HQ * HD];            // mean query per head
__device__ float g_qpart[16][HQ * HD];        // partial q sums (deterministic 2-stage)
__device__ int   g_blk[HQ * KLBLK];           // selected block ids per head

// fp16 hi/lo split operands
__device__ __align__(16) __half g_xh[(size_t)S * DIMM];
__device__ __align__(16) __half g_xl[(size_t)S * DIMM];
__device__ __align__(16) __half g_wqh[(size_t)NQKV * DIMM];
__device__ __align__(16) __half g_wql[(size_t)NQKV * DIMM];
__device__ __align__(16) __half g_woh[(size_t)DIMM * DIMM];   // hi only (WO is fp16 x1)
__device__ __align__(16) __half g_ath[(size_t)S * DIMM];      // attention out (hi only)
__device__ __align__(16) __half g_qh[(size_t)S * NQKV];       // roped qkv hi
__device__ __align__(16) __half g_ql[(size_t)S * NQKV];       // roped qkv lo

// ---------------------------------------------------------------------------
// asm helpers (base-ISA only; no tcgen05 on this toolchain)
// ---------------------------------------------------------------------------
__device__ __forceinline__ uint32_t smem_to_u32(const void* smem_ptr) {
    uint32_t addr;
    asm("{ .reg .u64 tmp; cvta.to.shared.u64 tmp, %1; cvt.u32.u64 %0, tmp; }"
        : "=r"(addr) : "l"(smem_ptr));
    return addr;
}

__device__ __forceinline__ void ldsm4(uint32_t* r, uint32_t addr) {
    asm volatile("ldmatrix.sync.aligned.m8n8.x4.shared.b16 {%0,%1,%2,%3}, [%4];"
        : "=r"(r[0]), "=r"(r[1]), "=r"(r[2]), "=r"(r[3]) : "r"(addr));
}

__device__ __forceinline__ void ldsm4t(uint32_t* r, uint32_t addr) {
    asm volatile("ldmatrix.sync.aligned.m8n8.x4.trans.shared.b16 {%0,%1,%2,%3}, [%4];"
        : "=r"(r[0]), "=r"(r[1]), "=r"(r[2]), "=r"(r[3]) : "r"(addr));
}

__device__ __forceinline__ void mma_f16(float* d, const uint32_t* a, const uint32_t* b) {
    asm volatile("mma.sync.aligned.m16n8k16.row.col.f32.f16.f16.f32 "
        "{%0,%1,%2,%3}, {%4,%5,%6,%7}, {%8,%9}, {%0,%1,%2,%3};"
        : "+f"(d[0]), "+f"(d[1]), "+f"(d[2]), "+f"(d[3])
        : "r"(a[0]), "r"(a[1]), "r"(a[2]), "r"(a[3]), "r"(b[0]), "r"(b[1]));
}

#define CP16(dst, src) \
    asm volatile("cp.async.cg.shared.global [%0], [%1], 16;" :: "r"(dst), "l"(src))
#define CP_COMMIT() asm volatile("cp.async.commit_group;" ::: "memory")
#define CP_WAIT(n)  asm volatile("cp.async.wait_group %0;" :: "n"(n) : "memory")

__device__ __forceinline__ uint32_t pack_f16(float a, float b) {
    __half2 h = __floats2half2_rn(a, b);
    return *(uint32_t*)&h;
}

// ---------------------------------------------------------------------------
// fp32 -> fp16 hi/lo split (pre-pass), float4 per thread
// ---------------------------------------------------------------------------
__global__ void split_kernel(const float* __restrict__ in,
                             __half* __restrict__ hi,
                             __half* __restrict__ lo, int n4)
{
    int i = blockIdx.x * blockDim.x + threadIdx.x;
    if (i >= n4) return;
    float4 v = ((const float4*)in)[i];
    __half h0 = __float2half_rn(v.x);
    __half h1 = __float2half_rn(v.y);
    __half h2 = __float2half_rn(v.z);
    __half h3 = __float2half_rn(v.w);
    __half l0 = __float2half_rn(v.x - __half2float(h0));
    __half l1 = __float2half_rn(v.y - __half2float(h1));
    __half l2 = __float2half_rn(v.z - __half2float(h2));
    __half l3 = __float2half_rn(v.w - __half2float(h3));
    uint2 H, L;
    H.x = ((uint32_t)__half_as_ushort(h1) << 16) | __half_as_ushort(h0);
    H.y = ((uint32_t)__half_as_ushort(h3) << 16) | __half_as_ushort(h2);
    L.x = ((uint32_t)__half_as_ushort(l1) << 16) | __half_as_ushort(l0);
    L.y = ((uint32_t)__half_as_ushort(l3) << 16) | __half_as_ushort(l2);
    ((uint2*)hi)[i] = H;
    ((uint2*)lo)[i] = L;
}

// hi-only variant (for wo weights — WO GEMM runs fp16 x1)
__global__ void split_hi_kernel(const float* __restrict__ in,
                                __half* __restrict__ hi, int n4)
{
    int i = blockIdx.x * blockDim.x + threadIdx.x;
    if (i >= n4) return;
    float4 v = ((const float4*)in)[i];
    uint2 H;
    H.x = pack_f16(v.x, v.y);
    H.y = pack_f16(v.z, v.w);
    ((uint2*)hi)[i] = H;
}

// ---------------------------------------------------------------------------
// Tensor-core GEMM:  acc = A @ B^T, fp16 operands, fp32 acc.
// MODE 1 (QKV): x3 products (Ah·Bh + Ah·Bl + Al·Bh); epilogue applies RoPE and
//               writes fp16 hi/lo directly to g_qh/g_ql (no fp32 output at all).
// MODE 0 (WO):  x1 product (Ah·Bh), fp32 C out, 3 CTAs/SM.
// 128x128 tile, BK=32, 256 threads, swizzled smem, 3-stage pipeline.
// ---------------------------------------------------------------------------
#define GTILE 8192                      // 128 rows x 64 bytes per variant

template<int MODE>
__global__ __launch_bounds__(256, MODE == 0 ? 3 : 2)
void gemm_f16(const __half* __restrict__ Ah, const __half* __restrict__ Al,
              const __half* __restrict__ Bh, const __half* __restrict__ Bl,
              float* __restrict__ C, const float* __restrict__ fc, int N, int K)
{
    constexpr bool FULL = (MODE == 1);
    constexpr uint32_t AHI = 0;
    constexpr uint32_t ALO = GTILE;                      // FULL only
    constexpr uint32_t BHI = FULL ? 2 * GTILE : GTILE;
    constexpr uint32_t BLO = 3 * GTILE;                  // FULL only
    constexpr uint32_t GB  = (FULL ? 4 : 2) * GTILE;

    extern __shared__ char smc[];
    const uint32_t sbase = smem_to_u32(smc);
    const int tid  = threadIdx.x;
    const int lane = tid & 31;
    const int wid  = tid >> 5;
    const int wm0  = (wid >> 2) << 6;
    const int wn0  = (wid & 3) << 5;
    const int bm   = blockIdx.y << 7;
    const int bn   = blockIdx.x << 7;

    float acc[4][4][4];
#pragma unroll
    for (int i = 0; i < 4; ++i)
#pragma unroll
        for (int j = 0; j < 4; ++j)
#pragma unroll
            for (int q = 0; q < 4; ++q) acc[i][j][q] = 0.f;

    const int nch = K >> 5;

    auto issue = [&](int cc, uint32_t boff) {
        const int kb = cc << 5;
#pragma unroll
        for (int i2 = 0; i2 < 2; ++i2) {
            int u   = tid + (i2 << 8);
            int row = u >> 2;
            int k   = u & 3;
            int sw  = k ^ ((row >> 1) & 3);
            uint32_t d = sbase + boff + (uint32_t)(row * 64 + sw * 16);
            const int ge = kb + (k << 3);
            CP16(d + AHI, Ah + (size_t)(bm + row) * K + ge);
            CP16(d + BHI, Bh + (size_t)(bn + row) * K + ge);
            if (FULL) {
                CP16(d + ALO, Al + (size_t)(bm + row) * K + ge);
                CP16(d + BLO, Bl + (size_t)(bn + row) * K + ge);
            }
        }
    };

    // fragment address components (swizzled layout)
    const int ar = lane & 15;
    const int ac = lane >> 4;
    const int br = (lane & 7) + (((lane >> 4) & 1) << 3);
    const int bc = (lane >> 3) & 1;

    issue(0, 0u);   CP_COMMIT();
    issue(1, GB);   CP_COMMIT();

    for (int c = 0; c < nch; ++c) {
        CP_WAIT(1);
        __syncthreads();

        if (c + 2 < nch) issue(c + 2, (uint32_t)((c + 2) % 3) * GB);
        CP_COMMIT();

        const uint32_t boff = (uint32_t)(c % 3) * GB;
#pragma unroll
        for (int ks = 0; ks < 2; ++ks) {
            uint32_t ahi[4][4], bhi[2][4];
            uint32_t alo[4][4], blo[2][4];
            const int kc2 = ks << 1;
#pragma unroll
            for (int mt = 0; mt < 4; ++mt) {
                int r_ = wm0 + (mt << 4) + ar;
                int sw = (kc2 + ac) ^ ((r_ >> 1) & 3);
                uint32_t off = (uint32_t)(r_ * 64 + sw * 16);
                ldsm4(ahi[mt], sbase + boff + AHI + off);
                if (FULL) ldsm4(alo[mt], sbase + boff + ALO + off);
            }
#pragma unroll
            for (int np = 0; np < 2; ++np) {
                int r_ = wn0 + (np << 4) + br;
                int sw = (kc2 + bc) ^ ((r_ >> 1) & 3);
                uint32_t off = (uint32_t)(r_ * 64 + sw * 16);
                ldsm4(bhi[np], sbase + boff + BHI + off);
                if (FULL) ldsm4(blo[np], sbase + boff + BLO + off);
            }
            // pass 1: hi*hi
#pragma unroll
            for (int mt = 0; mt < 4; ++mt)
#pragma unroll
                for (int nt = 0; nt < 4; ++nt)
                    mma_f16(acc[mt][nt], ahi[mt], &bhi[nt >> 1][(nt & 1) << 1]);
            if (FULL) {
                // pass 2: hi*lo
#pragma unroll
                for (int mt = 0; mt < 4; ++mt)
#pragma unroll
                    for (int nt = 0; nt < 4; ++nt)
                        mma_f16(acc[mt][nt], ahi[mt], &blo[nt >> 1][(nt & 1) << 1]);
                // pass 3: lo*hi
#pragma unroll
                for (int mt = 0; mt < 4; ++mt)
#pragma unroll
                    for (int nt = 0; nt < 4; ++nt)
                        mma_f16(acc[mt][nt], alo[mt], &bhi[nt >> 1][(nt & 1) << 1]);
            }
        }
    }

    const int er = lane >> 2;
    const int ec = (lane & 3) << 1;

    if (MODE == 0) {
        // plain fp32 C writeout
#pragma unroll
        for (int mt = 0; mt < 4; ++mt) {
#pragma unroll
            for (int nt = 0; nt < 4; ++nt) {
                int r0 = bm + wm0 + (mt << 4) + er;
                int c0 = bn + wn0 + (nt << 3) + ec;
                *(float2*)(C + (size_t)r0 * N + c0)       = make_float2(acc[mt][nt][0], acc[mt][nt][1]);
                *(float2*)(C + (size_t)(r0 + 8) * N + c0) = make_float2(acc[mt][nt][2], acc[mt][nt][3]);
            }
        }
    } else {
        // fused RoPE + fp16 hi/lo split writeout (cols pair (c0, c0+1), c0 even)
#pragma unroll
        for (int mt = 0; mt < 4; ++mt) {
#pragma unroll
            for (int nt = 0; nt < 4; ++nt) {
                int c0 = bn + wn0 + (nt << 3) + ec;
                int hh = c0 >> 7;                    // head 0..47
#pragma unroll
                for (int rr = 0; rr < 2; ++rr) {
                    int r = bm + wm0 + (mt << 4) + er + (rr << 3);
                    float a0 = acc[mt][nt][(rr << 1) + 0];
                    float a1 = acc[mt][nt][(rr << 1) + 1];
                    if (hh < 40) {                   // rope q + k heads
                        float2 f = *(const float2*)&fc[r * HD + (c0 & 127)];
                        float o0 = a0 * f.x - a1 * f.y;
                        float o1 = a1 * f.x + a0 * f.y;
                        a0 = o0; a1 = o1;
                    }
                    __half h0 = __float2half_rn(a0);
                    __half h1 = __float2half_rn(a1);
                    uint32_t hw = ((uint32_t)__half_as_ushort(h1) << 16) | __half_as_ushort(h0);
                    uint32_t lw = pack_f16(a0 - __half2float(h0), a1 - __half2float(h1));
                    size_t base = (size_t)r * NQKV + c0;
                    *(uint32_t*)&g_qh[base] = hw;
                    *(uint32_t*)&g_ql[base] = lw;
                }
            }
        }
    }
}

// ---------------------------------------------------------------------------
// Per-block key means (8 tokens per block) — reads fp16 hi+lo
// ---------------------------------------------------------------------------
__global__ void kmean_kernel()
{
    int idx = blockIdx.x * blockDim.x + threadIdx.x;   // TB*HKV*HD threads
    int d  = idx & 127;
    int hl = (idx >> 7) & 7;
    int t  = idx >> 10;
    size_t base = (size_t)(t * 8) * NQKV + HQ * HD + hl * HD + d;
    float s = 0.f;
#pragma unroll
    for (int i = 0; i < 8; ++i) {
        size_t o = base + (size_t)i * NQKV;
        s += __half2float(g_qh[o]) + __half2float(g_ql[o]);
    }
    g_krep[idx] = s * 0.125f;
}

// ---------------------------------------------------------------------------
// Mean query per head — deterministic 2-stage, reads fp16 hi+lo
// ---------------------------------------------------------------------------
__global__ void qmean_part_kernel()
{
    int h = blockIdx.x, chunk = blockIdx.y, d = threadIdx.x;
    size_t base = (size_t)(chunk * 256) * NQKV + h * HD + d;
    float s = 0.f;
#pragma unroll 4
    for (int i = 0; i < 256; ++i) {
        size_t o = base + (size_t)i * NQKV;
        s += __half2float(g_qh[o]) + __half2float(g_ql[o]);
    }
    g_qpart[chunk][h * HD + d] = s;
}

__global__ void qmean_final_kernel()
{
    int idx = blockIdx.x * blockDim.x + threadIdx.x;
    float s = 0.f;
#pragma unroll
    for (int i = 0; i < 16; ++i) s += g_qpart[i][idx];
    g_qmean[idx] = s * (1.f / 4096.f);
}

// ---------------------------------------------------------------------------
// Scores + top-k block selection. One block per head, 512 threads.
// ---------------------------------------------------------------------------
__global__ void scores_topk_kernel()
{
    __shared__ float qm[HD];
    __shared__ float sc[TB];
    __shared__ float rv[TB];
    __shared__ int   ri[TB];

    const int h  = blockIdx.x;
    const int t  = threadIdx.x;
    const int hl = h >> 2;

    if (t < HD) qm[t] = g_qmean[h * HD + t];
    __syncthreads();

    float s = 0.f;
    const float* kr = &g_krep[(t * HKV + hl) * HD];
#pragma unroll 8
    for (int d = 0; d < HD; ++d) s += qm[d] * kr[d];
    s *= SCALE;

    bool masked = (t < SINKB) || (t >= WINST);
    sc[t] = masked ? NEGF : s;

    if (t < 4) {
        g_blk[h * KLBLK + t]     = t;
        g_blk[h * KLBLK + 4 + t] = WINST + t;
    }
    __syncthreads();

    for (int pick = 0; pick < MBTOP; ++pick) {
        rv[t] = sc[t];
        ri[t] = t;
        __syncthreads();
        for (int off = 256; off > 0; off >>= 1) {
            if (t < off) {
                float v2 = rv[t + off];
                int   i2 = ri[t + off];
                if (v2 > rv[t] || (v2 == rv[t] && i2 < ri[t])) { rv[t] = v2; ri[t] = i2; }
            }
            __syncthreads();
        }
        if (t == 0) {
            g_blk[h * KLBLK + 8 + pick] = ri[0];
            sc[ri[0]] = -2e30f;
        }
        __syncthreads();
    }
}

// ---------------------------------------------------------------------------
// Tensor-core flash attention over 864 selected tokens per head (fp16 x3).
// grid = (S/64, HQ), 128 threads (4 warps, each owns 16 q-rows).
// ---------------------------------------------------------------------------
#define ASTRIDE 272                 // smem row stride in bytes (136 fp16)
#define QH_OFF  0
#define QL_OFF  17408
#define KH_OFF  34816
#define KL_OFF  43520
#define VH_OFF  52224
#define VL_OFF  60928
#define TOK_OFF 69632
#define FLG_OFF 69760
#define SMEM_ATTN 69824

__global__ __launch_bounds__(128)
void attn_mma_kernel()
{
    extern __shared__ char smb[];
    const uint32_t sb = smem_to_u32(smb);
    int* toks = (int*)(smb + TOK_OFF);
    int* sflg = (int*)(smb + FLG_OFF);

    const int tid  = threadIdx.x;
    const int lane = tid & 31;
    const int wid  = tid >> 5;
    const int h    = blockIdx.y;
    const int q0   = blockIdx.x << 6;
    const int hl   = h >> 2;
    const int m0   = wid << 4;

    const int er = lane >> 2;
    const int ec = (lane & 3) << 1;

    // load Q tile rows q0..q0+63, head slice (hi+lo)
    {
        const size_t qcol = (size_t)h * HD;
        for (int t = tid; t < 1024; t += 128) {
            int r = t >> 4, ch = t & 15;
            uint32_t d = sb + (uint32_t)(r * ASTRIDE + ch * 16);
            const size_t src = (size_t)(q0 + r) * NQKV + qcol + ch * 8;
            CP16(d + QH_OFF, g_qh + src);
            CP16(d + QL_OFF, g_ql + src);
        }
    }
    CP_COMMIT();

    float oacc[16][4];
#pragma unroll
    for (int i = 0; i < 16; ++i)
#pragma unroll
        for (int j = 0; j < 4; ++j) oacc[i][j] = 0.f;
    float mrow0 = NEGF, mrow1 = NEGF, lrow0 = 0.f, lrow1 = 0.f;

    CP_WAIT(0);
    __syncthreads();

    for (int kt = 0; kt < KSEL / 32; ++kt) {
        if (tid < 32) {
            int j = kt * 32 + tid;
            int b = g_blk[h * KLBLK + (j >> 3)];
            toks[tid] = (b << 3) + (j & 7);
        }
        __syncthreads();
        if (tid == 0) {
            int mn = toks[0];
#pragma unroll
            for (int i = 1; i < 32; ++i) mn = min(mn, toks[i]);
            sflg[0] = (mn > q0 + 63);
        }
        __syncthreads();
        if (sflg[0]) continue;

        // gather K/V rows (hi+lo) via cp.async
        {
            const size_t kcol = (size_t)HQ * HD + (size_t)hl * HD;
            for (int t = tid; t < 512; t += 128) {
                int r = t >> 4, ch = t & 15;
                size_t src = (size_t)toks[r] * NQKV + kcol + ch * 8;
                uint32_t d = sb + (uint32_t)(r * ASTRIDE + ch * 16);
                CP16(d + KH_OFF, g_qh + src);
                CP16(d + KL_OFF, g_ql + src);
                CP16(d + VH_OFF, g_qh + src + HKV * HD);
                CP16(d + VL_OFF, g_ql + src + HKV * HD);
            }
        }
        CP_COMMIT(); CP_WAIT(0);
        __syncthreads();

        // ---- scores: S = Q @ K^T (64x32), fp16 x3 ----
        float sc[4][4];
#pragma unroll
        for (int i = 0; i < 4; ++i)
#pragma unroll
            for (int j = 0; j < 4; ++j) sc[i][j] = 0.f;

#pragma unroll
        for (int ks = 0; ks < 8; ++ks) {
            const int kc = ks << 4;
            uint32_t ah[4], al[4], kh0[4], kl0[4], kh1[4], kl1[4];
            uint32_t aoff = (uint32_t)((m0 + (lane & 15)) * ASTRIDE)
                          + (uint32_t)((kc + ((lane >> 4) << 3)) * 2);
            ldsm4(ah, sb + QH_OFF + aoff);
            ldsm4(al, sb + QL_OFF + aoff);
            uint32_t boff = (uint32_t)((((lane & 7) + (((lane >> 4) & 1) << 3)) * ASTRIDE))
                          + (uint32_t)((kc + (((lane >> 3) & 1) << 3)) * 2);
            ldsm4(kh0, sb + KH_OFF + boff);
            ldsm4(kl0, sb + KL_OFF + boff);
            ldsm4(kh1, sb + KH_OFF + boff + 16 * ASTRIDE);
            ldsm4(kl1, sb + KL_OFF + boff + 16 * ASTRIDE);
#pragma unroll
            for (int nt = 0; nt < 4; ++nt)
                mma_f16(sc[nt], ah, (nt < 2) ? &kh0[(nt & 1) << 1] : &kh1[(nt & 1) << 1]);
#pragma unroll
            for (int nt = 0; nt < 4; ++nt)
                mma_f16(sc[nt], ah, (nt < 2) ? &kl0[(nt & 1) << 1] : &kl1[(nt & 1) << 1]);
#pragma unroll
            for (int nt = 0; nt < 4; ++nt)
                mma_f16(sc[nt], al, (nt < 2) ? &kh0[(nt & 1) << 1] : &kh1[(nt & 1) << 1]);
        }

        // ---- scale + causal mask ----
        const int qr0 = q0 + m0 + er;
        const int qr1 = qr0 + 8;
#pragma unroll
        for (int nt = 0; nt < 4; ++nt) {
            int2 tt = *(int2*)&toks[(nt << 3) + ec];
            sc[nt][0] = (tt.x <= qr0) ? sc[nt][0] * SCALE : NEGF;
            sc[nt][1] = (tt.y <= qr0) ? sc[nt][1] * SCALE : NEGF;
            sc[nt][2] = (tt.x <= qr1) ? sc[nt][2] * SCALE : NEGF;
            sc[nt][3] = (tt.y <= qr1) ? sc[nt][3] * SCALE : NEGF;
        }

        // ---- online softmax on fragments (quad reductions) ----
        float mt0 = fmaxf(fmaxf(fmaxf(sc[0][0], sc[0][1]), fmaxf(sc[1][0], sc[1][1])),
                          fmaxf(fmaxf(sc[2][0], sc[2][1]), fmaxf(sc[3][0], sc[3][1])));
        float mt1 = fmaxf(fmaxf(fmaxf(sc[0][2], sc[0][3]), fmaxf(sc[1][2], sc[1][3])),
                          fmaxf(fmaxf(sc[2][2], sc[2][3]), fmaxf(sc[3][2], sc[3][3])));
        mt0 = fmaxf(mt0, __shfl_xor_sync(0xffffffffu, mt0, 1));
        mt0 = fmaxf(mt0, __shfl_xor_sync(0xffffffffu, mt0, 2));
        mt1 = fmaxf(mt1, __shfl_xor_sync(0xffffffffu, mt1, 1));
        mt1 = fmaxf(mt1, __shfl_xor_sync(0xffffffffu, mt1, 2));
        float mn0 = fmaxf(mrow0, mt0);
        float mn1 = fmaxf(mrow1, mt1);
        float cc0 = __expf(mrow0 - mn0);
        float cc1 = __expf(mrow1 - mn1);
        float ls0 = 0.f, ls1 = 0.f;
#pragma unroll
        for (int nt = 0; nt < 4; ++nt) {
            float p0 = (sc[nt][0] > -1e29f) ? __expf(sc[nt][0] - mn0) : 0.f;
            float p1 = (sc[nt][1] > -1e29f) ? __expf(sc[nt][1] - mn0) : 0.f;
            float p2 = (sc[nt][2] > -1e29f) ? __expf(sc[nt][2] - mn1) : 0.f;
            float p3 = (sc[nt][3] > -1e29f) ? __expf(sc[nt][3] - mn1) : 0.f;
            sc[nt][0] = p0; sc[nt][1] = p1; sc[nt][2] = p2; sc[nt][3] = p3;
            ls0 += p0 + p1; ls1 += p2 + p3;
        }
        ls0 += __shfl_xor_sync(0xffffffffu, ls0, 1);
        ls0 += __shfl_xor_sync(0xffffffffu, ls0, 2);
        ls1 += __shfl_xor_sync(0xffffffffu, ls1, 1);
        ls1 += __shfl_xor_sync(0xffffffffu, ls1, 2);
        lrow0 = lrow0 * cc0 + ls0;  mrow0 = mn0;
        lrow1 = lrow1 * cc1 + ls1;  mrow1 = mn1;

#pragma unroll
        for (int nt = 0; nt < 16; ++nt) {
            oacc[nt][0] *= cc0; oacc[nt][1] *= cc0;
            oacc[nt][2] *= cc1; oacc[nt][3] *= cc1;
        }

        // ---- pack P into A fragments (hi/lo, fp16) ----
        uint32_t ph[2][4], pl[2][4];
#pragma unroll
        for (int ks = 0; ks < 2; ++ks) {
#pragma unroll
            for (int hh = 0; hh < 2; ++hh) {
                int nt = (ks << 1) + hh;
                float p0 = sc[nt][0], p1 = sc[nt][1], p2 = sc[nt][2], p3 = sc[nt][3];
                uint32_t h01 = pack_f16(p0, p1);
                uint32_t h23 = pack_f16(p2, p3);
                ph[ks][(hh << 1) + 0] = h01;
                ph[ks][(hh << 1) + 1] = h23;
                __half2 b01 = *(__half2*)&h01;
                __half2 b23 = *(__half2*)&h23;
                pl[ks][(hh << 1) + 0] = pack_f16(p0 - __half2float(b01.x),
                                                 p1 - __half2float(b01.y));
                pl[ks][(hh << 1) + 1] = pack_f16(p2 - __half2float(b23.x),
                                                 p3 - __half2float(b23.y));
            }
        }

        // ---- O += P @ V (64x128), fp16 x3 ----
#pragma unroll
        for (int ks = 0; ks < 2; ++ks) {
#pragma unroll
            for (int ng = 0; ng < 8; ++ng) {
                uint32_t vh[4], vl[4];
                uint32_t voff = (uint32_t)(((ks << 4) + (lane & 15)) * ASTRIDE)
                              + (uint32_t)(((ng << 4) + ((lane >> 4) << 3)) * 2);
                ldsm4t(vh, sb + VH_OFF + voff);
                ldsm4t(vl, sb + VL_OFF + voff);
                mma_f16(oacc[2 * ng],     ph[ks], &vh[0]);
                mma_f16(oacc[2 * ng + 1], ph[ks], &vh[2]);
                mma_f16(oacc[2 * ng],     ph[ks], &vl[0]);
                mma_f16(oacc[2 * ng + 1], ph[ks], &vl[2]);
                mma_f16(oacc[2 * ng],     pl[ks], &vh[0]);
                mma_f16(oacc[2 * ng + 1], pl[ks], &vh[2]);
            }
        }
        __syncthreads();   // protect K/V smem before next tile's cp.async
    }

    // ---- epilogue: normalize, store fp16 (hi only — WO GEMM is fp16 x1) ----
    const float inv0 = 1.f / lrow0;
    const float inv1 = 1.f / lrow1;
    const int row0 = q0 + m0 + er;
    const int row1 = row0 + 8;
#pragma unroll
    for (int nt = 0; nt < 16; ++nt) {
        int col = h * HD + (nt << 3) + ec;
        *(uint32_t*)&g_ath[(size_t)row0 * DIMM + col] =
            pack_f16(oacc[nt][0] * inv0, oacc[nt][1] * inv0);
        *(uint32_t*)&g_ath[(size_t)row1 * DIMM + col] =
            pack_f16(oacc[nt][2] * inv1, oacc[nt][3] * inv1);
    }
}

// ---------------------------------------------------------------------------
// Host launcher
// ---------------------------------------------------------------------------
extern "C" void kernel_launch(void* const* d_in, const int* in_sizes, int n_in,
                              void* d_out, int out_size)
{
    (void)in_sizes; (void)n_in; (void)out_size;
    const float* x    = (const float*)d_in[0];
    const float* fc   = (const float*)d_in[1];
    const float* wqkv = (const float*)d_in[2];
    const float* wo   = (const float*)d_in[3];
    float* y = (float*)d_out;

    __half *xh, *xl, *wqh, *wql, *woh, *ath;
    cudaGetSymbolAddress((void**)&xh,  g_xh);  cudaGetSymbolAddress((void**)&xl,  g_xl);
    cudaGetSymbolAddress((void**)&wqh, g_wqh); cudaGetSymbolAddress((void**)&wql, g_wql);
    cudaGetSymbolAddress((void**)&woh, g_woh);
    cudaGetSymbolAddress((void**)&ath, g_ath);

    cudaFuncSetAttribute(attn_mma_kernel, cudaFuncAttributeMaxDynamicSharedMemorySize, SMEM_ATTN);
    cudaFuncSetAttribute(gemm_f16<1>, cudaFuncAttributeMaxDynamicSharedMemorySize, 3 * 4 * GTILE);
    cudaFuncSetAttribute(gemm_f16<0>, cudaFuncAttributeMaxDynamicSharedMemorySize, 3 * 2 * GTILE);

    // 0. split GEMM inputs to fp16 (x, wqkv: hi+lo; wo: hi only)
    {
        int n4x = (S * DIMM) / 4;
        split_kernel<<<(n4x + 255) / 256, 256>>>(x, xh, xl, n4x);
        int n4q = (NQKV * DIMM) / 4;
        split_kernel<<<(n4q + 255) / 256, 256>>>(wqkv, wqh, wql, n4q);
        int n4o = (DIMM * DIMM) / 4;
        split_hi_kernel<<<(n4o + 255) / 256, 256>>>(wo, woh, n4o);
    }

    // 1. QKV projection (fp16 x3) with fused RoPE + fp16 hi/lo split epilogue
    gemm_f16<1><<<dim3(NQKV / 128, S / 128), 256, 3 * 4 * GTILE>>>(
        xh, xl, wqh, wql, nullptr, fc, NQKV, DIMM);

    // 2. per-block key means + query mean (from fp16 hi+lo)
    kmean_kernel<<<(TB * HKV * HD) / 256, 256>>>();
    qmean_part_kernel<<<dim3(HQ, 16), 128>>>();
    qmean_final_kernel<<<(HQ * HD) / 128, 128>>>();

    // 3. scores + top-k block selection
    scores_topk_kernel<<<HQ, TB>>>();

    // 4. tensor-core sparse causal attention (fp16 x3)
    attn_mma_kernel<<<dim3(S / 64, HQ), 128, SMEM_ATTN>>>();

    // 5. output projection (fp16 x1 — final op, error unamplified; 3 CTAs/SM)
    gemm_f16<0><<<dim3(DIMM / 128, S / 128), 256, 3 * 2 * GTILE>>>(
        ath, nullptr, woh, nullptr, y, nullptr, DIMM, DIMM);
}

// round 11
// speedup vs baseline: 1.0559x; 1.0559x over previous
#include <cuda_runtime.h>
#include <cuda_fp16.h>
#include <cstdint>

// ---------------------------------------------------------------------------
// Problem constants (fixed shapes)
// ---------------------------------------------------------------------------
#define S      4096
#define DIMM   4096
#define HQ     32
#define HKV    8
#define HD     128
#define NQKV   6144          // (HQ + 2*HKV) * HD
#define TB     512           // S / 8 blocks
#define SINKB  4             // ceil(30/8)
#define WINST  508           // window start block
#define MBTOP  100           // heavy blocks
#define KLBLK  108           // 4 sink + 4 window + 100 heavy
#define KSEL   (KLBLK * 8)   // 864 selected tokens per head
#define NEGF   (-1e30f)
#define SCALE  0.08838834764831845f   // 1/sqrt(128)

// ---------------------------------------------------------------------------
// Scratch (static device globals — no runtime allocation allowed)
// ---------------------------------------------------------------------------
__device__ float g_qkv[(size_t)S * NQKV];     // qkv projections (q/k roped in-place)
__device__ float g_krep[TB * HKV * HD];       // per-block mean keys
__device__ float g_qmean[HQ * HD];            // mean query per head
__device__ float g_qpart[16][HQ * HD];        // partial q sums (deterministic 2-stage)
__device__ int   g_blk[HQ * KLBLK];           // selected block ids per head

// fp16 hi/lo split operands
__device__ __align__(16) __half g_xh[(size_t)S * DIMM];
__device__ __align__(16) __half g_xl[(size_t)S * DIMM];
__device__ __align__(16) __half g_wqh[(size_t)NQKV * DIMM];
__device__ __align__(16) __half g_wql[(size_t)NQKV * DIMM];
__device__ __align__(16) __half g_woh[(size_t)DIMM * DIMM];   // hi only (WO is fp16 x1)
__device__ __align__(16) __half g_ath[(size_t)S * DIMM];      // attention out (hi only)
__device__ __align__(16) __half g_qh[(size_t)S * NQKV];       // roped qkv hi
__device__ __align__(16) __half g_ql[(size_t)S * NQKV];       // roped qkv lo

// ---------------------------------------------------------------------------
// asm helpers (base-ISA only; no tcgen05 on this toolchain)
// ---------------------------------------------------------------------------
__device__ __forceinline__ uint32_t smem_to_u32(const void* smem_ptr) {
    uint32_t addr;
    asm("{ .reg .u64 tmp; cvta.to.shared.u64 tmp, %1; cvt.u32.u64 %0, tmp; }"
        : "=r"(addr) : "l"(smem_ptr));
    return addr;
}

__device__ __forceinline__ void ldsm4(uint32_t* r, uint32_t addr) {
    asm volatile("ldmatrix.sync.aligned.m8n8.x4.shared.b16 {%0,%1,%2,%3}, [%4];"
        : "=r"(r[0]), "=r"(r[1]), "=r"(r[2]), "=r"(r[3]) : "r"(addr));
}

__device__ __forceinline__ void ldsm4t(uint32_t* r, uint32_t addr) {
    asm volatile("ldmatrix.sync.aligned.m8n8.x4.trans.shared.b16 {%0,%1,%2,%3}, [%4];"
        : "=r"(r[0]), "=r"(r[1]), "=r"(r[2]), "=r"(r[3]) : "r"(addr));
}

__device__ __forceinline__ void mma_f16(float* d, const uint32_t* a, const uint32_t* b) {
    asm volatile("mma.sync.aligned.m16n8k16.row.col.f32.f16.f16.f32 "
        "{%0,%1,%2,%3}, {%4,%5,%6,%7}, {%8,%9}, {%0,%1,%2,%3};"
        : "+f"(d[0]), "+f"(d[1]), "+f"(d[2]), "+f"(d[3])
        : "r"(a[0]), "r"(a[1]), "r"(a[2]), "r"(a[3]), "r"(b[0]), "r"(b[1]));
}

#define CP16(dst, src) \
    asm volatile("cp.async.cg.shared.global [%0], [%1], 16;" :: "r"(dst), "l"(src))
#define CP_COMMIT() asm volatile("cp.async.commit_group;" ::: "memory")
#define CP_WAIT(n)  asm volatile("cp.async.wait_group %0;" :: "n"(n) : "memory")

__device__ __forceinline__ uint32_t pack_f16(float a, float b) {
    __half2 h = __floats2half2_rn(a, b);
    return *(uint32_t*)&h;
}

// ---------------------------------------------------------------------------
// fp32 -> fp16 hi/lo split (pre-pass), float4 per thread
// ---------------------------------------------------------------------------
__global__ void split_kernel(const float* __restrict__ in,
                             __half* __restrict__ hi,
                             __half* __restrict__ lo, int n4)
{
    int i = blockIdx.x * blockDim.x + threadIdx.x;
    if (i >= n4) return;
    float4 v = ((const float4*)in)[i];
    __half h0 = __float2half_rn(v.x);
    __half h1 = __float2half_rn(v.y);
    __half h2 = __float2half_rn(v.z);
    __half h3 = __float2half_rn(v.w);
    __half l0 = __float2half_rn(v.x - __half2float(h0));
    __half l1 = __float2half_rn(v.y - __half2float(h1));
    __half l2 = __float2half_rn(v.z - __half2float(h2));
    __half l3 = __float2half_rn(v.w - __half2float(h3));
    uint2 H, L;
    H.x = ((uint32_t)__half_as_ushort(h1) << 16) | __half_as_ushort(h0);
    H.y = ((uint32_t)__half_as_ushort(h3) << 16) | __half_as_ushort(h2);
    L.x = ((uint32_t)__half_as_ushort(l1) << 16) | __half_as_ushort(l0);
    L.y = ((uint32_t)__half_as_ushort(l3) << 16) | __half_as_ushort(l2);
    ((uint2*)hi)[i] = H;
    ((uint2*)lo)[i] = L;
}

// hi-only variant (for wo weights — WO GEMM runs fp16 x1)
__global__ void split_hi_kernel(const float* __restrict__ in,
                                __half* __restrict__ hi, int n4)
{
    int i = blockIdx.x * blockDim.x + threadIdx.x;
    if (i >= n4) return;
    float4 v = ((const float4*)in)[i];
    uint2 H;
    H.x = pack_f16(v.x, v.y);
    H.y = pack_f16(v.z, v.w);
    ((uint2*)hi)[i] = H;
}

// ---------------------------------------------------------------------------
// Fused RoPE + fp16 hi/lo split of the roped qkv tensor.
// ---------------------------------------------------------------------------
__global__ void rope_split_kernel(const float* __restrict__ fc)
{
    const int n4 = (S * NQKV) / 4;
    int i = blockIdx.x * blockDim.x + threadIdx.x;
    if (i >= n4) return;
    int col4 = i % (NQKV / 4);
    int s    = i / (NQKV / 4);
    int c    = col4 << 2;
    int hh   = c >> 7;             // head index 0..47
    float4 v = *(float4*)&g_qkv[(size_t)s * NQKV + c];
    if (hh < 40) {                 // q (0..31) and k (32..39) get rope
        float4 f = *(const float4*)&fc[s * HD + (c & 127)];
        float x0 = v.x, x1 = v.y, x2 = v.z, x3 = v.w;
        v.x = x0 * f.x - x1 * f.y;
        v.y = x1 * f.x + x0 * f.y;
        v.z = x2 * f.z - x3 * f.w;
        v.w = x3 * f.z + x2 * f.w;
        *(float4*)&g_qkv[(size_t)s * NQKV + c] = v;
    }
    __half h0 = __float2half_rn(v.x);
    __half h1 = __float2half_rn(v.y);
    __half h2 = __float2half_rn(v.z);
    __half h3 = __float2half_rn(v.w);
    __half l0 = __float2half_rn(v.x - __half2float(h0));
    __half l1 = __float2half_rn(v.y - __half2float(h1));
    __half l2 = __float2half_rn(v.z - __half2float(h2));
    __half l3 = __float2half_rn(v.w - __half2float(h3));
    uint2 H, L;
    H.x = ((uint32_t)__half_as_ushort(h1) << 16) | __half_as_ushort(h0);
    H.y = ((uint32_t)__half_as_ushort(h3) << 16) | __half_as_ushort(h2);
    L.x = ((uint32_t)__half_as_ushort(l1) << 16) | __half_as_ushort(l0);
    L.y = ((uint32_t)__half_as_ushort(l3) << 16) | __half_as_ushort(l2);
    size_t base = (size_t)s * NQKV + c;
    *(uint2*)&g_qh[base] = H;
    *(uint2*)&g_ql[base] = L;
}

// ---------------------------------------------------------------------------
// Tensor-core GEMM:  C = A @ B^T, fp16 operands, fp32 acc.
// FULL=true : x3 products (Ah·Bh + Ah·Bl + Al·Bh), error ~2^-22
// FULL=false: plain fp16 x1 (Ah·Bh), error ~4e-4 — used ONLY for the final WO
// 128x128 tile, BK=32, 256 threads, swizzled smem, 3-stage pipeline, 2 CTAs/SM.
// ---------------------------------------------------------------------------
#define GTILE 8192                      // 128 rows x 64 bytes per variant

template<bool FULL>
__global__ __launch_bounds__(256, 2)
void gemm_f16(const __half* __restrict__ Ah, const __half* __restrict__ Al,
              const __half* __restrict__ Bh, const __half* __restrict__ Bl,
              float* __restrict__ C, int N, int K)
{
    constexpr uint32_t AHI = 0;
    constexpr uint32_t ALO = GTILE;                      // FULL only
    constexpr uint32_t BHI = FULL ? 2 * GTILE : GTILE;
    constexpr uint32_t BLO = 3 * GTILE;                  // FULL only
    constexpr uint32_t GB  = (FULL ? 4 : 2) * GTILE;

    extern __shared__ char smc[];
    const uint32_t sbase = smem_to_u32(smc);
    const int tid  = threadIdx.x;
    const int lane = tid & 31;
    const int wid  = tid >> 5;
    const int wm0  = (wid >> 2) << 6;
    const int wn0  = (wid & 3) << 5;
    const int bm   = blockIdx.y << 7;
    const int bn   = blockIdx.x << 7;

    float acc[4][4][4];
#pragma unroll
    for (int i = 0; i < 4; ++i)
#pragma unroll
        for (int j = 0; j < 4; ++j)
#pragma unroll
            for (int q = 0; q < 4; ++q) acc[i][j][q] = 0.f;

    const int nch = K >> 5;

    auto issue = [&](int cc, uint32_t boff) {
        const int kb = cc << 5;
#pragma unroll
        for (int i2 = 0; i2 < 2; ++i2) {
            int u   = tid + (i2 << 8);
            int row = u >> 2;
            int k   = u & 3;
            int sw  = k ^ ((row >> 1) & 3);
            uint32_t d = sbase + boff + (uint32_t)(row * 64 + sw * 16);
            const int ge = kb + (k << 3);
            CP16(d + AHI, Ah + (size_t)(bm + row) * K + ge);
            CP16(d + BHI, Bh + (size_t)(bn + row) * K + ge);
            if (FULL) {
                CP16(d + ALO, Al + (size_t)(bm + row) * K + ge);
                CP16(d + BLO, Bl + (size_t)(bn + row) * K + ge);
            }
        }
    };

    // fragment address components (swizzled layout)
    const int ar = lane & 15;
    const int ac = lane >> 4;
    const int br = (lane & 7) + (((lane >> 4) & 1) << 3);
    const int bc = (lane >> 3) & 1;

    issue(0, 0u);   CP_COMMIT();
    issue(1, GB);   CP_COMMIT();

    for (int c = 0; c < nch; ++c) {
        CP_WAIT(1);
        __syncthreads();

        if (c + 2 < nch) issue(c + 2, (uint32_t)((c + 2) % 3) * GB);
        CP_COMMIT();

        const uint32_t boff = (uint32_t)(c % 3) * GB;
#pragma unroll
        for (int ks = 0; ks < 2; ++ks) {
            uint32_t ahi[4][4], bhi[2][4];
            uint32_t alo[4][4], blo[2][4];
            const int kc2 = ks << 1;
#pragma unroll
            for (int mt = 0; mt < 4; ++mt) {
                int r_ = wm0 + (mt << 4) + ar;
                int sw = (kc2 + ac) ^ ((r_ >> 1) & 3);
                uint32_t off = (uint32_t)(r_ * 64 + sw * 16);
                ldsm4(ahi[mt], sbase + boff + AHI + off);
                if (FULL) ldsm4(alo[mt], sbase + boff + ALO + off);
            }
#pragma unroll
            for (int np = 0; np < 2; ++np) {
                int r_ = wn0 + (np << 4) + br;
                int sw = (kc2 + bc) ^ ((r_ >> 1) & 3);
                uint32_t off = (uint32_t)(r_ * 64 + sw * 16);
                ldsm4(bhi[np], sbase + boff + BHI + off);
                if (FULL) ldsm4(blo[np], sbase + boff + BLO + off);
            }
            // pass 1: hi*hi
#pragma unroll
            for (int mt = 0; mt < 4; ++mt)
#pragma unroll
                for (int nt = 0; nt < 4; ++nt)
                    mma_f16(acc[mt][nt], ahi[mt], &bhi[nt >> 1][(nt & 1) << 1]);
            if (FULL) {
                // pass 2: hi*lo
#pragma unroll
                for (int mt = 0; mt < 4; ++mt)
#pragma unroll
                    for (int nt = 0; nt < 4; ++nt)
                        mma_f16(acc[mt][nt], ahi[mt], &blo[nt >> 1][(nt & 1) << 1]);
                // pass 3: lo*hi
#pragma unroll
                for (int mt = 0; mt < 4; ++mt)
#pragma unroll
                    for (int nt = 0; nt < 4; ++nt)
                        mma_f16(acc[mt][nt], alo[mt], &bhi[nt >> 1][(nt & 1) << 1]);
            }
        }
    }

    const int er = lane >> 2;
    const int ec = (lane & 3) << 1;
#pragma unroll
    for (int mt = 0; mt < 4; ++mt) {
#pragma unroll
        for (int nt = 0; nt < 4; ++nt) {
            int r0 = bm + wm0 + (mt << 4) + er;
            int c0 = bn + wn0 + (nt << 3) + ec;
            *(float2*)(C + (size_t)r0 * N + c0)       = make_float2(acc[mt][nt][0], acc[mt][nt][1]);
            *(float2*)(C + (size_t)(r0 + 8) * N + c0) = make_float2(acc[mt][nt][2], acc[mt][nt][3]);
        }
    }
}

// ---------------------------------------------------------------------------
// Per-block key means (8 tokens per block)
// ---------------------------------------------------------------------------
__global__ void kmean_kernel()
{
    int idx = blockIdx.x * blockDim.x + threadIdx.x;
    int d  = idx & 127;
    int hl = (idx >> 7) & 7;
    int t  = idx >> 10;
    const float* p = &g_qkv[(size_t)(t * 8) * NQKV + HQ * HD + hl * HD + d];
    float s = 0.f;
#pragma unroll
    for (int i = 0; i < 8; ++i) s += p[(size_t)i * NQKV];
    g_krep[idx] = s * 0.125f;
}

// ---------------------------------------------------------------------------
// Mean query per head — deterministic 2-stage
// ---------------------------------------------------------------------------
__global__ void qmean_part_kernel()
{
    int h = blockIdx.x, chunk = blockIdx.y, d = threadIdx.x;
    const float* p = &g_qkv[(size_t)(chunk * 256) * NQKV + h * HD + d];
    float s = 0.f;
#pragma unroll 4
    for (int i = 0; i < 256; ++i) s += p[(size_t)i * NQKV];
    g_qpart[chunk][h * HD + d] = s;
}

__global__ void qmean_final_kernel()
{
    int idx = blockIdx.x * blockDim.x + threadIdx.x;
    float s = 0.f;
#pragma unroll
    for (int i = 0; i < 16; ++i) s += g_qpart[i][idx];
    g_qmean[idx] = s * (1.f / 4096.f);
}

// ---------------------------------------------------------------------------
// Scores + top-k block selection. One block per head, 512 threads.
// ---------------------------------------------------------------------------
__global__ void scores_topk_kernel()
{
    __shared__ float qm[HD];
    __shared__ float sc[TB];
    __shared__ float rv[TB];
    __shared__ int   ri[TB];

    const int h  = blockIdx.x;
    const int t  = threadIdx.x;
    const int hl = h >> 2;

    if (t < HD) qm[t] = g_qmean[h * HD + t];
    __syncthreads();

    float s = 0.f;
    const float* kr = &g_krep[(t * HKV + hl) * HD];
#pragma unroll 8
    for (int d = 0; d < HD; ++d) s += qm[d] * kr[d];
    s *= SCALE;

    bool masked = (t < SINKB) || (t >= WINST);
    sc[t] = masked ? NEGF : s;

    if (t < 4) {
        g_blk[h * KLBLK + t]     = t;
        g_blk[h * KLBLK + 4 + t] = WINST + t;
    }
    __syncthreads();

    for (int pick = 0; pick < MBTOP; ++pick) {
        rv[t] = sc[t];
        ri[t] = t;
        __syncthreads();
        for (int off = 256; off > 0; off >>= 1) {
            if (t < off) {
                float v2 = rv[t + off];
                int   i2 = ri[t + off];
                if (v2 > rv[t] || (v2 == rv[t] && i2 < ri[t])) { rv[t] = v2; ri[t] = i2; }
            }
            __syncthreads();
        }
        if (t == 0) {
            g_blk[h * KLBLK + 8 + pick] = ri[0];
            sc[ri[0]] = -2e30f;
        }
        __syncthreads();
    }
}

// ---------------------------------------------------------------------------
// Tensor-core flash attention (fp16 x3), DOUBLE-BUFFERED K/V gather.
// grid = (S/64, HQ), 128 threads (4 warps, each owns 16 q-rows).
// 2-stage ring over precomputed active tiles; CP_WAIT(1) overlaps each tile's
// gather with the previous tile's compute. 104.8 KB smem -> still 2 CTAs/SM.
// ---------------------------------------------------------------------------
#define ASTRIDE  272                // smem row stride in bytes (136 fp16)
#define QH_OFF   0
#define QL_OFF   17408
#define KV_OFF   34816
#define KVSTG    34816              // per stage: KH | KL | VH | VL (4 x 8704)
#define TOKS_OFF (KV_OFF + 2 * KVSTG)        // 104448, 2 x 32 ints
#define ACT_OFF  (TOKS_OFF + 2 * 128)        // 104704, 27 ints
#define NACT_OFF (ACT_OFF + 108)             // 104812
#define SMEM_ATTN 104832
#define NTILE (KSEL / 32)           // 27

// gather K/V rows of tile kt into stage buffer b (also records token ids)
#define ATTN_FETCH(kt, b) do {                                                 \
    const size_t kcol_ = (size_t)HQ * HD + (size_t)hl * HD;                    \
    int* tb_ = (int*)(smb + TOKS_OFF + (b) * 128);                             \
    for (int t_ = tid; t_ < 512; t_ += 128) {                                  \
        int r_ = t_ >> 4, ch_ = t_ & 15;                                       \
        int j_ = (kt) * 32 + r_;                                               \
        int blk_ = g_blk[h * KLBLK + (j_ >> 3)];                               \
        int tok_ = (blk_ << 3) + (j_ & 7);                                     \
        if (ch_ == 0) tb_[r_] = tok_;                                          \
        size_t src_ = (size_t)tok_ * NQKV + kcol_ + ch_ * 8;                   \
        uint32_t d_ = sb + KV_OFF + (b) * KVSTG +                              \
                      (uint32_t)(r_ * ASTRIDE + ch_ * 16);                     \
        CP16(d_ + 0,     g_qh + src_);                                         \
        CP16(d_ + 8704,  g_ql + src_);                                         \
        CP16(d_ + 17408, g_qh + src_ + HKV * HD);                              \
        CP16(d_ + 26112, g_ql + src_ + HKV * HD);                              \
    }                                                                          \
} while (0)

__global__ __launch_bounds__(128)
void attn_mma_kernel()
{
    extern __shared__ char smb[];
    const uint32_t sb = smem_to_u32(smb);

    const int tid  = threadIdx.x;
    const int lane = tid & 31;
    const int wid  = tid >> 5;
    const int h    = blockIdx.y;
    const int q0   = blockIdx.x << 6;
    const int hl   = h >> 2;
    const int m0   = wid << 4;

    const int er = lane >> 2;
    const int ec = (lane & 3) << 1;

    // Q tile load (group 0)
    {
        const size_t qcol = (size_t)h * HD;
        for (int t = tid; t < 1024; t += 128) {
            int r = t >> 4, ch = t & 15;
            uint32_t d = sb + (uint32_t)(r * ASTRIDE + ch * 16);
            const size_t src = (size_t)(q0 + r) * NQKV + qcol + ch * 8;
            CP16(d + QH_OFF, g_qh + src);
            CP16(d + QL_OFF, g_ql + src);
        }
    }
    CP_COMMIT();

    // build active tile list (causal tile skip)
    if (tid == 0) {
        int n = 0;
        int* act_ = (int*)(smb + ACT_OFF);
        for (int kt = 0; kt < NTILE; ++kt) {
            int mn = 0x7fffffff;
#pragma unroll
            for (int s2 = 0; s2 < 4; ++s2)
                mn = min(mn, g_blk[h * KLBLK + kt * 4 + s2]);
            if ((mn << 3) <= q0 + 63) act_[n++] = kt;
        }
        *(int*)(smb + NACT_OFF) = n;
    }
    __syncthreads();
    const int nact = *(const int*)(smb + NACT_OFF);
    const int* act = (const int*)(smb + ACT_OFF);

    // K/V pipeline prologue (groups 1, 2)
    ATTN_FETCH(act[0], 0);
    CP_COMMIT();
    if (nact > 1) ATTN_FETCH(act[1], 1);
    CP_COMMIT();

    float oacc[16][4];
#pragma unroll
    for (int i = 0; i < 16; ++i)
#pragma unroll
        for (int j = 0; j < 4; ++j) oacc[i][j] = 0.f;
    float mrow0 = NEGF, mrow1 = NEGF, lrow0 = 0.f, lrow1 = 0.f;

    for (int it = 0; it < nact; ++it) {
        CP_WAIT(1);          // Q + stage(it) complete; stage(it+1) may be in flight
        __syncthreads();

        const int b = it & 1;
        const uint32_t kvb = sb + KV_OFF + b * KVSTG;
        const int* tb = (const int*)(smb + TOKS_OFF + b * 128);

        // ---- scores: S = Q @ K^T (64x32), fp16 x3 ----
        float sc[4][4];
#pragma unroll
        for (int i = 0; i < 4; ++i)
#pragma unroll
            for (int j = 0; j < 4; ++j) sc[i][j] = 0.f;

#pragma unroll
        for (int ks = 0; ks < 8; ++ks) {
            const int kc = ks << 4;
            uint32_t ah[4], al[4], kh0[4], kl0[4], kh1[4], kl1[4];
            uint32_t aoff = (uint32_t)((m0 + (lane & 15)) * ASTRIDE)
                          + (uint32_t)((kc + ((lane >> 4) << 3)) * 2);
            ldsm4(ah, sb + QH_OFF + aoff);
            ldsm4(al, sb + QL_OFF + aoff);
            uint32_t boff = (uint32_t)((((lane & 7) + (((lane >> 4) & 1) << 3)) * ASTRIDE))
                          + (uint32_t)((kc + (((lane >> 3) & 1) << 3)) * 2);
            ldsm4(kh0, kvb + boff);
            ldsm4(kl0, kvb + 8704 + boff);
            ldsm4(kh1, kvb + boff + 16 * ASTRIDE);
            ldsm4(kl1, kvb + 8704 + boff + 16 * ASTRIDE);
#pragma unroll
            for (int nt = 0; nt < 4; ++nt)
                mma_f16(sc[nt], ah, (nt < 2) ? &kh0[(nt & 1) << 1] : &kh1[(nt & 1) << 1]);
#pragma unroll
            for (int nt = 0; nt < 4; ++nt)
                mma_f16(sc[nt], ah, (nt < 2) ? &kl0[(nt & 1) << 1] : &kl1[(nt & 1) << 1]);
#pragma unroll
            for (int nt = 0; nt < 4; ++nt)
                mma_f16(sc[nt], al, (nt < 2) ? &kh0[(nt & 1) << 1] : &kh1[(nt & 1) << 1]);
        }

        // ---- scale + causal mask ----
        const int qr0 = q0 + m0 + er;
        const int qr1 = qr0 + 8;
#pragma unroll
        for (int nt = 0; nt < 4; ++nt) {
            int2 tt = *(int2*)&tb[(nt << 3) + ec];
            sc[nt][0] = (tt.x <= qr0) ? sc[nt][0] * SCALE : NEGF;
            sc[nt][1] = (tt.y <= qr0) ? sc[nt][1] * SCALE : NEGF;
            sc[nt][2] = (tt.x <= qr1) ? sc[nt][2] * SCALE : NEGF;
            sc[nt][3] = (tt.y <= qr1) ? sc[nt][3] * SCALE : NEGF;
        }

        // ---- online softmax on fragments (quad reductions) ----
        float mt0 = fmaxf(fmaxf(fmaxf(sc[0][0], sc[0][1]), fmaxf(sc[1][0], sc[1][1])),
                          fmaxf(fmaxf(sc[2][0], sc[2][1]), fmaxf(sc[3][0], sc[3][1])));
        float mt1 = fmaxf(fmaxf(fmaxf(sc[0][2], sc[0][3]), fmaxf(sc[1][2], sc[1][3])),
                          fmaxf(fmaxf(sc[2][2], sc[2][3]), fmaxf(sc[3][2], sc[3][3])));
        mt0 = fmaxf(mt0, __shfl_xor_sync(0xffffffffu, mt0, 1));
        mt0 = fmaxf(mt0, __shfl_xor_sync(0xffffffffu, mt0, 2));
        mt1 = fmaxf(mt1, __shfl_xor_sync(0xffffffffu, mt1, 1));
        mt1 = fmaxf(mt1, __shfl_xor_sync(0xffffffffu, mt1, 2));
        float mn0 = fmaxf(mrow0, mt0);
        float mn1 = fmaxf(mrow1, mt1);
        float cc0 = __expf(mrow0 - mn0);
        float cc1 = __expf(mrow1 - mn1);
        float ls0 = 0.f, ls1 = 0.f;
#pragma unroll
        for (int nt = 0; nt < 4; ++nt) {
            float p0 = (sc[nt][0] > -1e29f) ? __expf(sc[nt][0] - mn0) : 0.f;
            float p1 = (sc[nt][1] > -1e29f) ? __expf(sc[nt][1] - mn0) : 0.f;
            float p2 = (sc[nt][2] > -1e29f) ? __expf(sc[nt][2] - mn1) : 0.f;
            float p3 = (sc[nt][3] > -1e29f) ? __expf(sc[nt][3] - mn1) : 0.f;
            sc[nt][0] = p0; sc[nt][1] = p1; sc[nt][2] = p2; sc[nt][3] = p3;
            ls0 += p0 + p1; ls1 += p2 + p3;
        }
        ls0 += __shfl_xor_sync(0xffffffffu, ls0, 1);
        ls0 += __shfl_xor_sync(0xffffffffu, ls0, 2);
        ls1 += __shfl_xor_sync(0xffffffffu, ls1, 1);
        ls1 += __shfl_xor_sync(0xffffffffu, ls1, 2);
        lrow0 = lrow0 * cc0 + ls0;  mrow0 = mn0;
        lrow1 = lrow1 * cc1 + ls1;  mrow1 = mn1;

#pragma unroll
        for (int nt = 0; nt < 16; ++nt) {
            oacc[nt][0] *= cc0; oacc[nt][1] *= cc0;
            oacc[nt][2] *= cc1; oacc[nt][3] *= cc1;
        }

        // ---- pack P into A fragments (hi/lo, fp16) ----
        uint32_t ph[2][4], pl[2][4];
#pragma unroll
        for (int ks = 0; ks < 2; ++ks) {
#pragma unroll
            for (int hh = 0; hh < 2; ++hh) {
                int nt = (ks << 1) + hh;
                float p0 = sc[nt][0], p1 = sc[nt][1], p2 = sc[nt][2], p3 = sc[nt][3];
                uint32_t h01 = pack_f16(p0, p1);
                uint32_t h23 = pack_f16(p2, p3);
                ph[ks][(hh << 1) + 0] = h01;
                ph[ks][(hh << 1) + 1] = h23;
                __half2 b01 = *(__half2*)&h01;
                __half2 b23 = *(__half2*)&h23;
                pl[ks][(hh << 1) + 0] = pack_f16(p0 - __half2float(b01.x),
                                                 p1 - __half2float(b01.y));
                pl[ks][(hh << 1) + 1] = pack_f16(p2 - __half2float(b23.x),
                                                 p3 - __half2float(b23.y));
            }
        }

        // ---- O += P @ V (64x128), fp16 x3 ----
#pragma unroll
        for (int ks = 0; ks < 2; ++ks) {
#pragma unroll
            for (int ng = 0; ng < 8; ++ng) {
                uint32_t vh[4], vl[4];
                uint32_t voff = (uint32_t)(((ks << 4) + (lane & 15)) * ASTRIDE)
                              + (uint32_t)(((ng << 4) + ((lane >> 4) << 3)) * 2);
                ldsm4t(vh, kvb + 17408 + voff);
                ldsm4t(vl, kvb + 26112 + voff);
                mma_f16(oacc[2 * ng],     ph[ks], &vh[0]);
                mma_f16(oacc[2 * ng + 1], ph[ks], &vh[2]);
                mma_f16(oacc[2 * ng],     ph[ks], &vl[0]);
                mma_f16(oacc[2 * ng + 1], ph[ks], &vl[2]);
                mma_f16(oacc[2 * ng],     pl[ks], &vh[0]);
                mma_f16(oacc[2 * ng + 1], pl[ks], &vh[2]);
            }
        }

        // reads of stage b done; refill it with tile it+2
        __syncthreads();
        if (it + 2 < nact) ATTN_FETCH(act[it + 2], b);
        CP_COMMIT();
    }

    // ---- epilogue: normalize, store fp16 (hi only — WO GEMM is fp16 x1) ----
    const float inv0 = 1.f / lrow0;
    const float inv1 = 1.f / lrow1;
    const int row0 = q0 + m0 + er;
    const int row1 = row0 + 8;
#pragma unroll
    for (int nt = 0; nt < 16; ++nt) {
        int col = h * HD + (nt << 3) + ec;
        *(uint32_t*)&g_ath[(size_t)row0 * DIMM + col] =
            pack_f16(oacc[nt][0] * inv0, oacc[nt][1] * inv0);
        *(uint32_t*)&g_ath[(size_t)row1 * DIMM + col] =
            pack_f16(oacc[nt][2] * inv1, oacc[nt][3] * inv1);
    }
}

// ---------------------------------------------------------------------------
// Host launcher
// ---------------------------------------------------------------------------
extern "C" void kernel_launch(void* const* d_in, const int* in_sizes, int n_in,
                              void* d_out, int out_size)
{
    (void)in_sizes; (void)n_in; (void)out_size;
    const float* x    = (const float*)d_in[0];
    const float* fc   = (const float*)d_in[1];
    const float* wqkv = (const float*)d_in[2];
    const float* wo   = (const float*)d_in[3];
    float* y = (float*)d_out;

    float* qkv_p = nullptr;
    __half *xh, *xl, *wqh, *wql, *woh, *ath;
    cudaGetSymbolAddress((void**)&qkv_p, g_qkv);
    cudaGetSymbolAddress((void**)&xh,  g_xh);  cudaGetSymbolAddress((void**)&xl,  g_xl);
    cudaGetSymbolAddress((void**)&wqh, g_wqh); cudaGetSymbolAddress((void**)&wql, g_wql);
    cudaGetSymbolAddress((void**)&woh, g_woh);
    cudaGetSymbolAddress((void**)&ath, g_ath);

    cudaFuncSetAttribute(attn_mma_kernel, cudaFuncAttributeMaxDynamicSharedMemorySize, SMEM_ATTN);
    cudaFuncSetAttribute(gemm_f16<true>,  cudaFuncAttributeMaxDynamicSharedMemorySize, 3 * 4 * GTILE);
    cudaFuncSetAttribute(gemm_f16<false>, cudaFuncAttributeMaxDynamicSharedMemorySize, 3 * 2 * GTILE);

    // 0. split GEMM inputs to fp16 (x, wqkv: hi+lo; wo: hi only)
    {
        int n4x = (S * DIMM) / 4;
        split_kernel<<<(n4x + 255) / 256, 256>>>(x, xh, xl, n4x);
        int n4q = (NQKV * DIMM) / 4;
        split_kernel<<<(n4q + 255) / 256, 256>>>(wqkv, wqh, wql, n4q);
        int n4o = (DIMM * DIMM) / 4;
        split_hi_kernel<<<(n4o + 255) / 256, 256>>>(wo, woh, n4o);
    }

    // 1. QKV projection (fp16 x3 — error ~2^-22)
    gemm_f16<true><<<dim3(NQKV / 128, S / 128), 256, 3 * 4 * GTILE>>>(
        xh, xl, wqh, wql, qkv_p, NQKV, DIMM);

    // 2. fused RoPE + fp16 hi/lo split of roped qkv
    {
        int n4 = (S * NQKV) / 4;
        rope_split_kernel<<<(n4 + 255) / 256, 256>>>(fc);
    }

    // 3. per-block key means + query mean
    kmean_kernel<<<(TB * HKV * HD) / 256, 256>>>();
    qmean_part_kernel<<<dim3(HQ, 16), 128>>>();
    qmean_final_kernel<<<(HQ * HD) / 128, 128>>>();

    // 4. scores + top-k block selection
    scores_topk_kernel<<<HQ, TB>>>();

    // 5. tensor-core sparse causal attention (fp16 x3, double-buffered gather)
    attn_mma_kernel<<<dim3(S / 64, HQ), 128, SMEM_ATTN>>>();

    // 6. output projection (fp16 x1 — final op, error unamplified ~4e-4)
    gemm_f16<false><<<dim3(DIMM / 128, S / 128), 256, 3 * 2 * GTILE>>>(
        ath, nullptr, woh, nullptr, y, DIMM, DIMM);
}

// round 12
// speedup vs baseline: 1.0652x; 1.0088x over previous
#include <cuda_runtime.h>
#include <cuda_fp16.h>
#include <cstdint>

// ---------------------------------------------------------------------------
// Problem constants (fixed shapes)
// ---------------------------------------------------------------------------
#define S      4096
#define DIMM   4096
#define HQ     32
#define HKV    8
#define HD     128
#define NQKV   6144          // (HQ + 2*HKV) * HD
#define TB     512           // S / 8 blocks
#define SINKB  4             // ceil(30/8)
#define WINST  508           // window start block
#define MBTOP  100           // heavy blocks
#define KLBLK  108           // 4 sink + 4 window + 100 heavy
#define KSEL   (KLBLK * 8)   // 864 selected tokens per head
#define NEGF   (-1e30f)
#define SCALE  0.08838834764831845f   // 1/sqrt(128)

// ---------------------------------------------------------------------------
// Scratch (static device globals — no runtime allocation allowed)
// ---------------------------------------------------------------------------
__device__ float g_qkv[(size_t)S * NQKV];     // qkv projections (q/k roped in-place)
__device__ float g_krep[TB * HKV * HD];       // per-block mean keys
__device__ float g_qmean[HQ * HD];            // mean query per head
__device__ float g_qpart[16][HQ * HD];        // partial q sums (deterministic 2-stage)
__device__ int   g_blk[HQ * KLBLK];           // selected block ids per head

// fp16 hi/lo split operands
__device__ __align__(16) __half g_xh[(size_t)S * DIMM];
__device__ __align__(16) __half g_xl[(size_t)S * DIMM];
__device__ __align__(16) __half g_wqh[(size_t)NQKV * DIMM];
__device__ __align__(16) __half g_wql[(size_t)NQKV * DIMM];
__device__ __align__(16) __half g_woh[(size_t)DIMM * DIMM];   // hi only (WO is fp16 x1)
__device__ __align__(16) __half g_ath[(size_t)S * DIMM];      // attention out (hi only)
__device__ __align__(16) __half g_qh[(size_t)S * NQKV];       // roped qkv hi
__device__ __align__(16) __half g_ql[(size_t)S * NQKV];       // roped qkv lo

// ---------------------------------------------------------------------------
// asm helpers (base-ISA only; no tcgen05 on this toolchain)
// ---------------------------------------------------------------------------
__device__ __forceinline__ uint32_t smem_to_u32(const void* smem_ptr) {
    uint32_t addr;
    asm("{ .reg .u64 tmp; cvta.to.shared.u64 tmp, %1; cvt.u32.u64 %0, tmp; }"
        : "=r"(addr) : "l"(smem_ptr));
    return addr;
}

__device__ __forceinline__ void ldsm4(uint32_t* r, uint32_t addr) {
    asm volatile("ldmatrix.sync.aligned.m8n8.x4.shared.b16 {%0,%1,%2,%3}, [%4];"
        : "=r"(r[0]), "=r"(r[1]), "=r"(r[2]), "=r"(r[3]) : "r"(addr));
}

__device__ __forceinline__ void ldsm4t(uint32_t* r, uint32_t addr) {
    asm volatile("ldmatrix.sync.aligned.m8n8.x4.trans.shared.b16 {%0,%1,%2,%3}, [%4];"
        : "=r"(r[0]), "=r"(r[1]), "=r"(r[2]), "=r"(r[3]) : "r"(addr));
}

__device__ __forceinline__ void mma_f16(float* d, const uint32_t* a, const uint32_t* b) {
    asm volatile("mma.sync.aligned.m16n8k16.row.col.f32.f16.f16.f32 "
        "{%0,%1,%2,%3}, {%4,%5,%6,%7}, {%8,%9}, {%0,%1,%2,%3};"
        : "+f"(d[0]), "+f"(d[1]), "+f"(d[2]), "+f"(d[3])
        : "r"(a[0]), "r"(a[1]), "r"(a[2]), "r"(a[3]), "r"(b[0]), "r"(b[1]));
}

#define CP16(dst, src) \
    asm volatile("cp.async.cg.shared.global [%0], [%1], 16;" :: "r"(dst), "l"(src))
#define CP_COMMIT() asm volatile("cp.async.commit_group;" ::: "memory")
#define CP_WAIT(n)  asm volatile("cp.async.wait_group %0;" :: "n"(n) : "memory")

__device__ __forceinline__ uint32_t pack_f16(float a, float b) {
    __half2 h = __floats2half2_rn(a, b);
    return *(uint32_t*)&h;
}

// ---------------------------------------------------------------------------
// fp32 -> fp16 hi/lo split (pre-pass), float4 per thread
// ---------------------------------------------------------------------------
__global__ void split_kernel(const float* __restrict__ in,
                             __half* __restrict__ hi,
                             __half* __restrict__ lo, int n4)
{
    int i = blockIdx.x * blockDim.x + threadIdx.x;
    if (i >= n4) return;
    float4 v = ((const float4*)in)[i];
    __half h0 = __float2half_rn(v.x);
    __half h1 = __float2half_rn(v.y);
    __half h2 = __float2half_rn(v.z);
    __half h3 = __float2half_rn(v.w);
    __half l0 = __float2half_rn(v.x - __half2float(h0));
    __half l1 = __float2half_rn(v.y - __half2float(h1));
    __half l2 = __float2half_rn(v.z - __half2float(h2));
    __half l3 = __float2half_rn(v.w - __half2float(h3));
    uint2 H, L;
    H.x = ((uint32_t)__half_as_ushort(h1) << 16) | __half_as_ushort(h0);
    H.y = ((uint32_t)__half_as_ushort(h3) << 16) | __half_as_ushort(h2);
    L.x = ((uint32_t)__half_as_ushort(l1) << 16) | __half_as_ushort(l0);
    L.y = ((uint32_t)__half_as_ushort(l3) << 16) | __half_as_ushort(l2);
    ((uint2*)hi)[i] = H;
    ((uint2*)lo)[i] = L;
}

// hi-only variant (for wo weights — WO GEMM runs fp16 x1)
__global__ void split_hi_kernel(const float* __restrict__ in,
                                __half* __restrict__ hi, int n4)
{
    int i = blockIdx.x * blockDim.x + threadIdx.x;
    if (i >= n4) return;
    float4 v = ((const float4*)in)[i];
    uint2 H;
    H.x = pack_f16(v.x, v.y);
    H.y = pack_f16(v.z, v.w);
    ((uint2*)hi)[i] = H;
}

// ---------------------------------------------------------------------------
// Fused RoPE + fp16 hi/lo split of the roped qkv tensor.
// ---------------------------------------------------------------------------
__global__ void rope_split_kernel(const float* __restrict__ fc)
{
    const int n4 = (S * NQKV) / 4;
    int i = blockIdx.x * blockDim.x + threadIdx.x;
    if (i >= n4) return;
    int col4 = i % (NQKV / 4);
    int s    = i / (NQKV / 4);
    int c    = col4 << 2;
    int hh   = c >> 7;             // head index 0..47
    float4 v = *(float4*)&g_qkv[(size_t)s * NQKV + c];
    if (hh < 40) {                 // q (0..31) and k (32..39) get rope
        float4 f = *(const float4*)&fc[s * HD + (c & 127)];
        float x0 = v.x, x1 = v.y, x2 = v.z, x3 = v.w;
        v.x = x0 * f.x - x1 * f.y;
        v.y = x1 * f.x + x0 * f.y;
        v.z = x2 * f.z - x3 * f.w;
        v.w = x3 * f.z + x2 * f.w;
        *(float4*)&g_qkv[(size_t)s * NQKV + c] = v;
    }
    __half h0 = __float2half_rn(v.x);
    __half h1 = __float2half_rn(v.y);
    __half h2 = __float2half_rn(v.z);
    __half h3 = __float2half_rn(v.w);
    __half l0 = __float2half_rn(v.x - __half2float(h0));
    __half l1 = __float2half_rn(v.y - __half2float(h1));
    __half l2 = __float2half_rn(v.z - __half2float(h2));
    __half l3 = __float2half_rn(v.w - __half2float(h3));
    uint2 H, L;
    H.x = ((uint32_t)__half_as_ushort(h1) << 16) | __half_as_ushort(h0);
    H.y = ((uint32_t)__half_as_ushort(h3) << 16) | __half_as_ushort(h2);
    L.x = ((uint32_t)__half_as_ushort(l1) << 16) | __half_as_ushort(l0);
    L.y = ((uint32_t)__half_as_ushort(l3) << 16) | __half_as_ushort(l2);
    size_t base = (size_t)s * NQKV + c;
    *(uint2*)&g_qh[base] = H;
    *(uint2*)&g_ql[base] = L;
}

// ---------------------------------------------------------------------------
// QKV tensor-core GEMM: C = A @ B^T, fp16 x3 (Ah·Bh + Ah·Bl + Al·Bh), fp32 acc.
// 128x128 tile, BK=32, 256 threads, swizzled smem, 3-stage pipeline, 2 CTAs/SM.
// ---------------------------------------------------------------------------
#define GTILE 8192                      // 128 rows x 64 bytes per variant

__global__ __launch_bounds__(256, 2)
void gemm_qkv(const __half* __restrict__ Ah, const __half* __restrict__ Al,
              const __half* __restrict__ Bh, const __half* __restrict__ Bl,
              float* __restrict__ C, int N, int K)
{
    constexpr uint32_t AHI = 0;
    constexpr uint32_t ALO = GTILE;
    constexpr uint32_t BHI = 2 * GTILE;
    constexpr uint32_t BLO = 3 * GTILE;
    constexpr uint32_t GB  = 4 * GTILE;

    extern __shared__ char smc[];
    const uint32_t sbase = smem_to_u32(smc);
    const int tid  = threadIdx.x;
    const int lane = tid & 31;
    const int wid  = tid >> 5;
    const int wm0  = (wid >> 2) << 6;
    const int wn0  = (wid & 3) << 5;
    const int bm   = blockIdx.y << 7;
    const int bn   = blockIdx.x << 7;

    float acc[4][4][4];
#pragma unroll
    for (int i = 0; i < 4; ++i)
#pragma unroll
        for (int j = 0; j < 4; ++j)
#pragma unroll
            for (int q = 0; q < 4; ++q) acc[i][j][q] = 0.f;

    const int nch = K >> 5;

    auto issue = [&](int cc, uint32_t boff) {
        const int kb = cc << 5;
#pragma unroll
        for (int i2 = 0; i2 < 2; ++i2) {
            int u   = tid + (i2 << 8);
            int row = u >> 2;
            int k   = u & 3;
            int sw  = k ^ ((row >> 1) & 3);
            uint32_t d = sbase + boff + (uint32_t)(row * 64 + sw * 16);
            const int ge = kb + (k << 3);
            CP16(d + AHI, Ah + (size_t)(bm + row) * K + ge);
            CP16(d + BHI, Bh + (size_t)(bn + row) * K + ge);
            CP16(d + ALO, Al + (size_t)(bm + row) * K + ge);
            CP16(d + BLO, Bl + (size_t)(bn + row) * K + ge);
        }
    };

    const int ar = lane & 15;
    const int ac = lane >> 4;
    const int br = (lane & 7) + (((lane >> 4) & 1) << 3);
    const int bc = (lane >> 3) & 1;

    issue(0, 0u);   CP_COMMIT();
    issue(1, GB);   CP_COMMIT();

    for (int c = 0; c < nch; ++c) {
        CP_WAIT(1);
        __syncthreads();

        if (c + 2 < nch) issue(c + 2, (uint32_t)((c + 2) % 3) * GB);
        CP_COMMIT();

        const uint32_t boff = (uint32_t)(c % 3) * GB;
#pragma unroll
        for (int ks = 0; ks < 2; ++ks) {
            uint32_t ahi[4][4], bhi[2][4];
            uint32_t alo[4][4], blo[2][4];
            const int kc2 = ks << 1;
#pragma unroll
            for (int mt = 0; mt < 4; ++mt) {
                int r_ = wm0 + (mt << 4) + ar;
                int sw = (kc2 + ac) ^ ((r_ >> 1) & 3);
                uint32_t off = (uint32_t)(r_ * 64 + sw * 16);
                ldsm4(ahi[mt], sbase + boff + AHI + off);
                ldsm4(alo[mt], sbase + boff + ALO + off);
            }
#pragma unroll
            for (int np = 0; np < 2; ++np) {
                int r_ = wn0 + (np << 4) + br;
                int sw = (kc2 + bc) ^ ((r_ >> 1) & 3);
                uint32_t off = (uint32_t)(r_ * 64 + sw * 16);
                ldsm4(bhi[np], sbase + boff + BHI + off);
                ldsm4(blo[np], sbase + boff + BLO + off);
            }
            // pass 1: hi*hi
#pragma unroll
            for (int mt = 0; mt < 4; ++mt)
#pragma unroll
                for (int nt = 0; nt < 4; ++nt)
                    mma_f16(acc[mt][nt], ahi[mt], &bhi[nt >> 1][(nt & 1) << 1]);
            // pass 2: hi*lo
#pragma unroll
            for (int mt = 0; mt < 4; ++mt)
#pragma unroll
                for (int nt = 0; nt < 4; ++nt)
                    mma_f16(acc[mt][nt], ahi[mt], &blo[nt >> 1][(nt & 1) << 1]);
            // pass 3: lo*hi
#pragma unroll
            for (int mt = 0; mt < 4; ++mt)
#pragma unroll
                for (int nt = 0; nt < 4; ++nt)
                    mma_f16(acc[mt][nt], alo[mt], &bhi[nt >> 1][(nt & 1) << 1]);
        }
    }

    const int er = lane >> 2;
    const int ec = (lane & 3) << 1;
#pragma unroll
    for (int mt = 0; mt < 4; ++mt) {
#pragma unroll
        for (int nt = 0; nt < 4; ++nt) {
            int r0 = bm + wm0 + (mt << 4) + er;
            int c0 = bn + wn0 + (nt << 3) + ec;
            *(float2*)(C + (size_t)r0 * N + c0)       = make_float2(acc[mt][nt][0], acc[mt][nt][1]);
            *(float2*)(C + (size_t)(r0 + 8) * N + c0) = make_float2(acc[mt][nt][2], acc[mt][nt][3]);
        }
    }
}

// ---------------------------------------------------------------------------
// WO tensor-core GEMM: C = Ah @ Bh^T, fp16 x1, fp32 acc, BK=64.
// Per stage: A = two 8KB sub-tiles (k 0..31 / 32..63), B likewise -> 32KB.
// 3-stage pipeline, ONE sync per 64-K chunk (64 syncs total), 2 CTAs/SM.
// Same k16-MMA sequence as BK=32 version -> bit-identical output.
// ---------------------------------------------------------------------------
#define WO_A 0
#define WO_B 16384
#define WO_GB 32768
#define SMEM_WO (3 * WO_GB)            // 98304

__global__ __launch_bounds__(256, 2)
void gemm_wo64(const __half* __restrict__ Ah, const __half* __restrict__ Bh,
               float* __restrict__ C, int N, int K)
{
    extern __shared__ char smc[];
    const uint32_t sbase = smem_to_u32(smc);
    const int tid  = threadIdx.x;
    const int lane = tid & 31;
    const int wid  = tid >> 5;
    const int wm0  = (wid >> 2) << 6;
    const int wn0  = (wid & 3) << 5;
    const int bm   = blockIdx.y << 7;
    const int bn   = blockIdx.x << 7;

    float acc[4][4][4];
#pragma unroll
    for (int i = 0; i < 4; ++i)
#pragma unroll
        for (int j = 0; j < 4; ++j)
#pragma unroll
            for (int q = 0; q < 4; ++q) acc[i][j][q] = 0.f;

    const int nch = K >> 6;            // 64-wide chunks

    auto issue = [&](int cc, uint32_t boff) {
        const int kb = cc << 6;
#pragma unroll
        for (int i2 = 0; i2 < 4; ++i2) {
            int u   = tid + (i2 << 8);      // 0..1023
            int row = u >> 3;
            int k   = u & 7;                // 16B chunk within 128B of K
            int sub = k >> 2;               // sub-tile (k-half)
            int sw  = (k & 3) ^ ((row >> 1) & 3);
            uint32_t d = sbase + boff + (uint32_t)(sub * 8192 + row * 64 + sw * 16);
            const int ge = kb + (k << 3);
            CP16(d + WO_A, Ah + (size_t)(bm + row) * K + ge);
            CP16(d + WO_B, Bh + (size_t)(bn + row) * K + ge);
        }
    };

    const int ar = lane & 15;
    const int ac = lane >> 4;
    const int br = (lane & 7) + (((lane >> 4) & 1) << 3);
    const int bc = (lane >> 3) & 1;

    issue(0, 0u);       CP_COMMIT();
    issue(1, WO_GB);    CP_COMMIT();

    for (int c = 0; c < nch; ++c) {
        CP_WAIT(1);
        __syncthreads();

        if (c + 2 < nch) issue(c + 2, (uint32_t)((c + 2) % 3) * WO_GB);
        CP_COMMIT();

        const uint32_t boff = (uint32_t)(c % 3) * WO_GB;
#pragma unroll
        for (int ks = 0; ks < 4; ++ks) {
            const uint32_t suboff = (uint32_t)((ks >> 1) * 8192);
            const int kc2 = (ks & 1) << 1;
            uint32_t ahi[4][4], bhi[2][4];
#pragma unroll
            for (int mt = 0; mt < 4; ++mt) {
                int r_ = wm0 + (mt << 4) + ar;
                int sw = (kc2 + ac) ^ ((r_ >> 1) & 3);
                ldsm4(ahi[mt], sbase + boff + WO_A + suboff + (uint32_t)(r_ * 64 + sw * 16));
            }
#pragma unroll
            for (int np = 0; np < 2; ++np) {
                int r_ = wn0 + (np << 4) + br;
                int sw = (kc2 + bc) ^ ((r_ >> 1) & 3);
                ldsm4(bhi[np], sbase + boff + WO_B + suboff + (uint32_t)(r_ * 64 + sw * 16));
            }
#pragma unroll
            for (int mt = 0; mt < 4; ++mt)
#pragma unroll
                for (int nt = 0; nt < 4; ++nt)
                    mma_f16(acc[mt][nt], ahi[mt], &bhi[nt >> 1][(nt & 1) << 1]);
        }
    }

    const int er = lane >> 2;
    const int ec = (lane & 3) << 1;
#pragma unroll
    for (int mt = 0; mt < 4; ++mt) {
#pragma unroll
        for (int nt = 0; nt < 4; ++nt) {
            int r0 = bm + wm0 + (mt << 4) + er;
            int c0 = bn + wn0 + (nt << 3) + ec;
            *(float2*)(C + (size_t)r0 * N + c0)       = make_float2(acc[mt][nt][0], acc[mt][nt][1]);
            *(float2*)(C + (size_t)(r0 + 8) * N + c0) = make_float2(acc[mt][nt][2], acc[mt][nt][3]);
        }
    }
}

// ---------------------------------------------------------------------------
// Per-block key means (8 tokens per block)
// ---------------------------------------------------------------------------
__global__ void kmean_kernel()
{
    int idx = blockIdx.x * blockDim.x + threadIdx.x;
    int d  = idx & 127;
    int hl = (idx >> 7) & 7;
    int t  = idx >> 10;
    const float* p = &g_qkv[(size_t)(t * 8) * NQKV + HQ * HD + hl * HD + d];
    float s = 0.f;
#pragma unroll
    for (int i = 0; i < 8; ++i) s += p[(size_t)i * NQKV];
    g_krep[idx] = s * 0.125f;
}

// ---------------------------------------------------------------------------
// Mean query per head — deterministic 2-stage
// ---------------------------------------------------------------------------
__global__ void qmean_part_kernel()
{
    int h = blockIdx.x, chunk = blockIdx.y, d = threadIdx.x;
    const float* p = &g_qkv[(size_t)(chunk * 256) * NQKV + h * HD + d];
    float s = 0.f;
#pragma unroll 4
    for (int i = 0; i < 256; ++i) s += p[(size_t)i * NQKV];
    g_qpart[chunk][h * HD + d] = s;
}

__global__ void qmean_final_kernel()
{
    int idx = blockIdx.x * blockDim.x + threadIdx.x;
    float s = 0.f;
#pragma unroll
    for (int i = 0; i < 16; ++i) s += g_qpart[i][idx];
    g_qmean[idx] = s * (1.f / 4096.f);
}

// ---------------------------------------------------------------------------
// Scores + top-k block selection. One block per head, 512 threads.
// ---------------------------------------------------------------------------
__global__ void scores_topk_kernel()
{
    __shared__ float qm[HD];
    __shared__ float sc[TB];
    __shared__ float rv[TB];
    __shared__ int   ri[TB];

    const int h  = blockIdx.x;
    const int t  = threadIdx.x;
    const int hl = h >> 2;

    if (t < HD) qm[t] = g_qmean[h * HD + t];
    __syncthreads();

    float s = 0.f;
    const float* kr = &g_krep[(t * HKV + hl) * HD];
#pragma unroll 8
    for (int d = 0; d < HD; ++d) s += qm[d] * kr[d];
    s *= SCALE;

    bool masked = (t < SINKB) || (t >= WINST);
    sc[t] = masked ? NEGF : s;

    if (t < 4) {
        g_blk[h * KLBLK + t]     = t;
        g_blk[h * KLBLK + 4 + t] = WINST + t;
    }
    __syncthreads();

    for (int pick = 0; pick < MBTOP; ++pick) {
        rv[t] = sc[t];
        ri[t] = t;
        __syncthreads();
        for (int off = 256; off > 0; off >>= 1) {
            if (t < off) {
                float v2 = rv[t + off];
                int   i2 = ri[t + off];
                if (v2 > rv[t] || (v2 == rv[t] && i2 < ri[t])) { rv[t] = v2; ri[t] = i2; }
            }
            __syncthreads();
        }
        if (t == 0) {
            g_blk[h * KLBLK + 8 + pick] = ri[0];
            sc[ri[0]] = -2e30f;
        }
        __syncthreads();
    }
}

// ---------------------------------------------------------------------------
// Tensor-core flash attention over 864 selected tokens per head (fp16 x3).
// grid = (S/64, HQ), 128 threads (4 warps, each owns 16 q-rows). Round-9 form.
// ---------------------------------------------------------------------------
#define ASTRIDE 272                 // smem row stride in bytes (136 fp16)
#define QH_OFF  0
#define QL_OFF  17408
#define KH_OFF  34816
#define KL_OFF  43520
#define VH_OFF  52224
#define VL_OFF  60928
#define TOK_OFF 69632
#define FLG_OFF 69760
#define SMEM_ATTN 69824

__global__ __launch_bounds__(128)
void attn_mma_kernel()
{
    extern __shared__ char smb[];
    const uint32_t sb = smem_to_u32(smb);
    int* toks = (int*)(smb + TOK_OFF);
    int* sflg = (int*)(smb + FLG_OFF);

    const int tid  = threadIdx.x;
    const int lane = tid & 31;
    const int wid  = tid >> 5;
    const int h    = blockIdx.y;
    const int q0   = blockIdx.x << 6;
    const int hl   = h >> 2;
    const int m0   = wid << 4;

    const int er = lane >> 2;
    const int ec = (lane & 3) << 1;

    // load Q tile rows q0..q0+63, head slice (hi+lo)
    {
        const size_t qcol = (size_t)h * HD;
        for (int t = tid; t < 1024; t += 128) {
            int r = t >> 4, ch = t & 15;
            uint32_t d = sb + (uint32_t)(r * ASTRIDE + ch * 16);
            const size_t src = (size_t)(q0 + r) * NQKV + qcol + ch * 8;
            CP16(d + QH_OFF, g_qh + src);
            CP16(d + QL_OFF, g_ql + src);
        }
    }
    CP_COMMIT();

    float oacc[16][4];
#pragma unroll
    for (int i = 0; i < 16; ++i)
#pragma unroll
        for (int j = 0; j < 4; ++j) oacc[i][j] = 0.f;
    float mrow0 = NEGF, mrow1 = NEGF, lrow0 = 0.f, lrow1 = 0.f;

    CP_WAIT(0);
    __syncthreads();

    for (int kt = 0; kt < KSEL / 32; ++kt) {
        if (tid < 32) {
            int j = kt * 32 + tid;
            int b = g_blk[h * KLBLK + (j >> 3)];
            toks[tid] = (b << 3) + (j & 7);
        }
        __syncthreads();
        if (tid == 0) {
            int mn = toks[0];
#pragma unroll
            for (int i = 1; i < 32; ++i) mn = min(mn, toks[i]);
            sflg[0] = (mn > q0 + 63);
        }
        __syncthreads();
        if (sflg[0]) continue;

        // gather K/V rows (hi+lo) via cp.async
        {
            const size_t kcol = (size_t)HQ * HD + (size_t)hl * HD;
            for (int t = tid; t < 512; t += 128) {
                int r = t >> 4, ch = t & 15;
                size_t src = (size_t)toks[r] * NQKV + kcol + ch * 8;
                uint32_t d = sb + (uint32_t)(r * ASTRIDE + ch * 16);
                CP16(d + KH_OFF, g_qh + src);
                CP16(d + KL_OFF, g_ql + src);
                CP16(d + VH_OFF, g_qh + src + HKV * HD);
                CP16(d + VL_OFF, g_ql + src + HKV * HD);
            }
        }
        CP_COMMIT(); CP_WAIT(0);
        __syncthreads();

        // ---- scores: S = Q @ K^T (64x32), fp16 x3 ----
        float sc[4][4];
#pragma unroll
        for (int i = 0; i < 4; ++i)
#pragma unroll
            for (int j = 0; j < 4; ++j) sc[i][j] = 0.f;

#pragma unroll
        for (int ks = 0; ks < 8; ++ks) {
            const int kc = ks << 4;
            uint32_t ah[4], al[4], kh0[4], kl0[4], kh1[4], kl1[4];
            uint32_t aoff = (uint32_t)((m0 + (lane & 15)) * ASTRIDE)
                          + (uint32_t)((kc + ((lane >> 4) << 3)) * 2);
            ldsm4(ah, sb + QH_OFF + aoff);
            ldsm4(al, sb + QL_OFF + aoff);
            uint32_t boff = (uint32_t)((((lane & 7) + (((lane >> 4) & 1) << 3)) * ASTRIDE))
                          + (uint32_t)((kc + (((lane >> 3) & 1) << 3)) * 2);
            ldsm4(kh0, sb + KH_OFF + boff);
            ldsm4(kl0, sb + KL_OFF + boff);
            ldsm4(kh1, sb + KH_OFF + boff + 16 * ASTRIDE);
            ldsm4(kl1, sb + KL_OFF + boff + 16 * ASTRIDE);
#pragma unroll
            for (int nt = 0; nt < 4; ++nt)
                mma_f16(sc[nt], ah, (nt < 2) ? &kh0[(nt & 1) << 1] : &kh1[(nt & 1) << 1]);
#pragma unroll
            for (int nt = 0; nt < 4; ++nt)
                mma_f16(sc[nt], ah, (nt < 2) ? &kl0[(nt & 1) << 1] : &kl1[(nt & 1) << 1]);
#pragma unroll
            for (int nt = 0; nt < 4; ++nt)
                mma_f16(sc[nt], al, (nt < 2) ? &kh0[(nt & 1) << 1] : &kh1[(nt & 1) << 1]);
        }

        // ---- scale + causal mask ----
        const int qr0 = q0 + m0 + er;
        const int qr1 = qr0 + 8;
#pragma unroll
        for (int nt = 0; nt < 4; ++nt) {
            int2 tt = *(int2*)&toks[(nt << 3) + ec];
            sc[nt][0] = (tt.x <= qr0) ? sc[nt][0] * SCALE : NEGF;
            sc[nt][1] = (tt.y <= qr0) ? sc[nt][1] * SCALE : NEGF;
            sc[nt][2] = (tt.x <= qr1) ? sc[nt][2] * SCALE : NEGF;
            sc[nt][3] = (tt.y <= qr1) ? sc[nt][3] * SCALE : NEGF;
        }

        // ---- online softmax on fragments (quad reductions) ----
        float mt0 = fmaxf(fmaxf(fmaxf(sc[0][0], sc[0][1]), fmaxf(sc[1][0], sc[1][1])),
                          fmaxf(fmaxf(sc[2][0], sc[2][1]), fmaxf(sc[3][0], sc[3][1])));
        float mt1 = fmaxf(fmaxf(fmaxf(sc[0][2], sc[0][3]), fmaxf(sc[1][2], sc[1][3])),
                          fmaxf(fmaxf(sc[2][2], sc[2][3]), fmaxf(sc[3][2], sc[3][3])));
        mt0 = fmaxf(mt0, __shfl_xor_sync(0xffffffffu, mt0, 1));
        mt0 = fmaxf(mt0, __shfl_xor_sync(0xffffffffu, mt0, 2));
        mt1 = fmaxf(mt1, __shfl_xor_sync(0xffffffffu, mt1, 1));
        mt1 = fmaxf(mt1, __shfl_xor_sync(0xffffffffu, mt1, 2));
        float mn0 = fmaxf(mrow0, mt0);
        float mn1 = fmaxf(mrow1, mt1);
        float cc0 = __expf(mrow0 - mn0);
        float cc1 = __expf(mrow1 - mn1);
        float ls0 = 0.f, ls1 = 0.f;
#pragma unroll
        for (int nt = 0; nt < 4; ++nt) {
            float p0 = (sc[nt][0] > -1e29f) ? __expf(sc[nt][0] - mn0) : 0.f;
            float p1 = (sc[nt][1] > -1e29f) ? __expf(sc[nt][1] - mn0) : 0.f;
            float p2 = (sc[nt][2] > -1e29f) ? __expf(sc[nt][2] - mn1) : 0.f;
            float p3 = (sc[nt][3] > -1e29f) ? __expf(sc[nt][3] - mn1) : 0.f;
            sc[nt][0] = p0; sc[nt][1] = p1; sc[nt][2] = p2; sc[nt][3] = p3;
            ls0 += p0 + p1; ls1 += p2 + p3;
        }
        ls0 += __shfl_xor_sync(0xffffffffu, ls0, 1);
        ls0 += __shfl_xor_sync(0xffffffffu, ls0, 2);
        ls1 += __shfl_xor_sync(0xffffffffu, ls1, 1);
        ls1 += __shfl_xor_sync(0xffffffffu, ls1, 2);
        lrow0 = lrow0 * cc0 + ls0;  mrow0 = mn0;
        lrow1 = lrow1 * cc1 + ls1;  mrow1 = mn1;

#pragma unroll
        for (int nt = 0; nt < 16; ++nt) {
            oacc[nt][0] *= cc0; oacc[nt][1] *= cc0;
            oacc[nt][2] *= cc1; oacc[nt][3] *= cc1;
        }

        // ---- pack P into A fragments (hi/lo, fp16) ----
        uint32_t ph[2][4], pl[2][4];
#pragma unroll
        for (int ks = 0; ks < 2; ++ks) {
#pragma unroll
            for (int hh = 0; hh < 2; ++hh) {
                int nt = (ks << 1) + hh;
                float p0 = sc[nt][0], p1 = sc[nt][1], p2 = sc[nt][2], p3 = sc[nt][3];
                uint32_t h01 = pack_f16(p0, p1);
                uint32_t h23 = pack_f16(p2, p3);
                ph[ks][(hh << 1) + 0] = h01;
                ph[ks][(hh << 1) + 1] = h23;
                __half2 b01 = *(__half2*)&h01;
                __half2 b23 = *(__half2*)&h23;
                pl[ks][(hh << 1) + 0] = pack_f16(p0 - __half2float(b01.x),
                                                 p1 - __half2float(b01.y));
                pl[ks][(hh << 1) + 1] = pack_f16(p2 - __half2float(b23.x),
                                                 p3 - __half2float(b23.y));
            }
        }

        // ---- O += P @ V (64x128), fp16 x3 ----
#pragma unroll
        for (int ks = 0; ks < 2; ++ks) {
#pragma unroll
            for (int ng = 0; ng < 8; ++ng) {
                uint32_t vh[4], vl[4];
                uint32_t voff = (uint32_t)(((ks << 4) + (lane & 15)) * ASTRIDE)
                              + (uint32_t)(((ng << 4) + ((lane >> 4) << 3)) * 2);
                ldsm4t(vh, sb + VH_OFF + voff);
                ldsm4t(vl, sb + VL_OFF + voff);
                mma_f16(oacc[2 * ng],     ph[ks], &vh[0]);
                mma_f16(oacc[2 * ng + 1], ph[ks], &vh[2]);
                mma_f16(oacc[2 * ng],     ph[ks], &vl[0]);
                mma_f16(oacc[2 * ng + 1], ph[ks], &vl[2]);
                mma_f16(oacc[2 * ng],     pl[ks], &vh[0]);
                mma_f16(oacc[2 * ng + 1], pl[ks], &vh[2]);
            }
        }
        __syncthreads();   // protect K/V smem before next tile's cp.async
    }

    // ---- epilogue: normalize, store fp16 (hi only — WO GEMM is fp16 x1) ----
    const float inv0 = 1.f / lrow0;
    const float inv1 = 1.f / lrow1;
    const int row0 = q0 + m0 + er;
    const int row1 = row0 + 8;
#pragma unroll
    for (int nt = 0; nt < 16; ++nt) {
        int col = h * HD + (nt << 3) + ec;
        *(uint32_t*)&g_ath[(size_t)row0 * DIMM + col] =
            pack_f16(oacc[nt][0] * inv0, oacc[nt][1] * inv0);
        *(uint32_t*)&g_ath[(size_t)row1 * DIMM + col] =
            pack_f16(oacc[nt][2] * inv1, oacc[nt][3] * inv1);
    }
}

// ---------------------------------------------------------------------------
// Host launcher
// ---------------------------------------------------------------------------
extern "C" void kernel_launch(void* const* d_in, const int* in_sizes, int n_in,
                              void* d_out, int out_size)
{
    (void)in_sizes; (void)n_in; (void)out_size;
    const float* x    = (const float*)d_in[0];
    const float* fc   = (const float*)d_in[1];
    const float* wqkv = (const float*)d_in[2];
    const float* wo   = (const float*)d_in[3];
    float* y = (float*)d_out;

    float* qkv_p = nullptr;
    __half *xh, *xl, *wqh, *wql, *woh, *ath;
    cudaGetSymbolAddress((void**)&qkv_p, g_qkv);
    cudaGetSymbolAddress((void**)&xh,  g_xh);  cudaGetSymbolAddress((void**)&xl,  g_xl);
    cudaGetSymbolAddress((void**)&wqh, g_wqh); cudaGetSymbolAddress((void**)&wql, g_wql);
    cudaGetSymbolAddress((void**)&woh, g_woh);
    cudaGetSymbolAddress((void**)&ath, g_ath);

    cudaFuncSetAttribute(attn_mma_kernel, cudaFuncAttributeMaxDynamicSharedMemorySize, SMEM_ATTN);
    cudaFuncSetAttribute(gemm_qkv,  cudaFuncAttributeMaxDynamicSharedMemorySize, 3 * 4 * GTILE);
    cudaFuncSetAttribute(gemm_wo64, cudaFuncAttributeMaxDynamicSharedMemorySize, SMEM_WO);

    // 0. split GEMM inputs to fp16 (x, wqkv: hi+lo; wo: hi only)
    {
        int n4x = (S * DIMM) / 4;
        split_kernel<<<(n4x + 255) / 256, 256>>>(x, xh, xl, n4x);
        int n4q = (NQKV * DIMM) / 4;
        split_kernel<<<(n4q + 255) / 256, 256>>>(wqkv, wqh, wql, n4q);
        int n4o = (DIMM * DIMM) / 4;
        split_hi_kernel<<<(n4o + 255) / 256, 256>>>(wo, woh, n4o);
    }

    // 1. QKV projection (fp16 x3 — error ~2^-22)
    gemm_qkv<<<dim3(NQKV / 128, S / 128), 256, 3 * 4 * GTILE>>>(
        xh, xl, wqh, wql, qkv_p, NQKV, DIMM);

    // 2. fused RoPE + fp16 hi/lo split of roped qkv
    {
        int n4 = (S * NQKV) / 4;
        rope_split_kernel<<<(n4 + 255) / 256, 256>>>(fc);
    }

    // 3. per-block key means + query mean
    kmean_kernel<<<(TB * HKV * HD) / 256, 256>>>();
    qmean_part_kernel<<<dim3(HQ, 16), 128>>>();
    qmean_final_kernel<<<(HQ * HD) / 128, 128>>>();

    // 4. scores + top-k block selection
    scores_topk_kernel<<<HQ, TB>>>();

    // 5. tensor-core sparse causal attention (fp16 x3)
    attn_mma_kernel<<<dim3(S / 64, HQ), 128, SMEM_ATTN>>>();

    // 6. output projection (fp16 x1, BK=64 — final op, error unamplified ~4e-4)
    gemm_wo64<<<dim3(DIMM / 128, S / 128), 256, SMEM_WO>>>(
        ath, woh, y, DIMM, DIMM);
}

// round 13
// speedup vs baseline: 1.1283x; 1.0592x over previous
#include <cuda_runtime.h>
#include <cuda_fp16.h>
#include <cstdint>

// ---------------------------------------------------------------------------
// Problem constants (fixed shapes)
// ---------------------------------------------------------------------------
#define S      4096
#define DIMM   4096
#define HQ     32
#define HKV    8
#define HD     128
#define NQKV   6144          // (HQ + 2*HKV) * HD
#define TB     512           // S / 8 blocks
#define SINKB  4             // ceil(30/8)
#define WINST  508           // window start block
#define MBTOP  100           // heavy blocks
#define KLBLK  108           // 4 sink + 4 window + 100 heavy
#define KSEL   (KLBLK * 8)   // 864 selected tokens per head
#define NEGF   (-1e30f)
#define SCALE  0.08838834764831845f   // 1/sqrt(128)

// ---------------------------------------------------------------------------
// Scratch (static device globals — no runtime allocation allowed)
// ---------------------------------------------------------------------------
__device__ float g_qkv[(size_t)S * NQKV];     // qkv projections (q/k roped in-place)
__device__ float g_krep[TB * HKV * HD];       // per-block mean keys
__device__ float g_qmean[HQ * HD];            // mean query per head
__device__ float g_qpart[16][HQ * HD];        // partial q sums (deterministic 2-stage)
__device__ int   g_blk[HQ * KLBLK];           // selected block ids per head

// fp16 hi/lo split operands
__device__ __align__(16) __half g_xh[(size_t)S * DIMM];
__device__ __align__(16) __half g_xl[(size_t)S * DIMM];
__device__ __align__(16) __half g_wqh[(size_t)NQKV * DIMM];
__device__ __align__(16) __half g_wql[(size_t)NQKV * DIMM];
__device__ __align__(16) __half g_woh[(size_t)DIMM * DIMM];   // hi only (WO is fp16 x1)
__device__ __align__(16) __half g_ath[(size_t)S * DIMM];      // attention out (hi only)
__device__ __align__(16) __half g_qh[(size_t)S * NQKV];       // roped qkv hi
__device__ __align__(16) __half g_ql[(size_t)S * NQKV];       // roped qkv lo

// ---------------------------------------------------------------------------
// asm helpers (base-ISA only; no tcgen05 on this toolchain)
// ---------------------------------------------------------------------------
__device__ __forceinline__ uint32_t smem_to_u32(const void* smem_ptr) {
    uint32_t addr;
    asm("{ .reg .u64 tmp; cvta.to.shared.u64 tmp, %1; cvt.u32.u64 %0, tmp; }"
        : "=r"(addr) : "l"(smem_ptr));
    return addr;
}

__device__ __forceinline__ void ldsm4(uint32_t* r, uint32_t addr) {
    asm volatile("ldmatrix.sync.aligned.m8n8.x4.shared.b16 {%0,%1,%2,%3}, [%4];"
        : "=r"(r[0]), "=r"(r[1]), "=r"(r[2]), "=r"(r[3]) : "r"(addr));
}

__device__ __forceinline__ void ldsm4t(uint32_t* r, uint32_t addr) {
    asm volatile("ldmatrix.sync.aligned.m8n8.x4.trans.shared.b16 {%0,%1,%2,%3}, [%4];"
        : "=r"(r[0]), "=r"(r[1]), "=r"(r[2]), "=r"(r[3]) : "r"(addr));
}

__device__ __forceinline__ void mma_f16(float* d, const uint32_t* a, const uint32_t* b) {
    asm volatile("mma.sync.aligned.m16n8k16.row.col.f32.f16.f16.f32 "
        "{%0,%1,%2,%3}, {%4,%5,%6,%7}, {%8,%9}, {%0,%1,%2,%3};"
        : "+f"(d[0]), "+f"(d[1]), "+f"(d[2]), "+f"(d[3])
        : "r"(a[0]), "r"(a[1]), "r"(a[2]), "r"(a[3]), "r"(b[0]), "r"(b[1]));
}

#define CP16(dst, src) \
    asm volatile("cp.async.cg.shared.global [%0], [%1], 16;" :: "r"(dst), "l"(src))
#define CP_COMMIT() asm volatile("cp.async.commit_group;" ::: "memory")
#define CP_WAIT(n)  asm volatile("cp.async.wait_group %0;" :: "n"(n) : "memory")

__device__ __forceinline__ uint32_t pack_f16(float a, float b) {
    __half2 h = __floats2half2_rn(a, b);
    return *(uint32_t*)&h;
}

// ---------------------------------------------------------------------------
// fp32 -> fp16 hi/lo split (pre-pass), float4 per thread
// ---------------------------------------------------------------------------
__global__ void split_kernel(const float* __restrict__ in,
                             __half* __restrict__ hi,
                             __half* __restrict__ lo, int n4)
{
    int i = blockIdx.x * blockDim.x + threadIdx.x;
    if (i >= n4) return;
    float4 v = ((const float4*)in)[i];
    __half h0 = __float2half_rn(v.x);
    __half h1 = __float2half_rn(v.y);
    __half h2 = __float2half_rn(v.z);
    __half h3 = __float2half_rn(v.w);
    __half l0 = __float2half_rn(v.x - __half2float(h0));
    __half l1 = __float2half_rn(v.y - __half2float(h1));
    __half l2 = __float2half_rn(v.z - __half2float(h2));
    __half l3 = __float2half_rn(v.w - __half2float(h3));
    uint2 H, L;
    H.x = ((uint32_t)__half_as_ushort(h1) << 16) | __half_as_ushort(h0);
    H.y = ((uint32_t)__half_as_ushort(h3) << 16) | __half_as_ushort(h2);
    L.x = ((uint32_t)__half_as_ushort(l1) << 16) | __half_as_ushort(l0);
    L.y = ((uint32_t)__half_as_ushort(l3) << 16) | __half_as_ushort(l2);
    ((uint2*)hi)[i] = H;
    ((uint2*)lo)[i] = L;
}

// hi-only variant (for wo weights — WO GEMM runs fp16 x1)
__global__ void split_hi_kernel(const float* __restrict__ in,
                                __half* __restrict__ hi, int n4)
{
    int i = blockIdx.x * blockDim.x + threadIdx.x;
    if (i >= n4) return;
    float4 v = ((const float4*)in)[i];
    uint2 H;
    H.x = pack_f16(v.x, v.y);
    H.y = pack_f16(v.z, v.w);
    ((uint2*)hi)[i] = H;
}

// ---------------------------------------------------------------------------
// Fused RoPE + fp16 hi/lo split of the roped qkv tensor.
// ---------------------------------------------------------------------------
__global__ void rope_split_kernel(const float* __restrict__ fc)
{
    const int n4 = (S * NQKV) / 4;
    int i = blockIdx.x * blockDim.x + threadIdx.x;
    if (i >= n4) return;
    int col4 = i % (NQKV / 4);
    int s    = i / (NQKV / 4);
    int c    = col4 << 2;
    int hh   = c >> 7;             // head index 0..47
    float4 v = *(float4*)&g_qkv[(size_t)s * NQKV + c];
    if (hh < 40) {                 // q (0..31) and k (32..39) get rope
        float4 f = *(const float4*)&fc[s * HD + (c & 127)];
        float x0 = v.x, x1 = v.y, x2 = v.z, x3 = v.w;
        v.x = x0 * f.x - x1 * f.y;
        v.y = x1 * f.x + x0 * f.y;
        v.z = x2 * f.z - x3 * f.w;
        v.w = x3 * f.z + x2 * f.w;
        *(float4*)&g_qkv[(size_t)s * NQKV + c] = v;
    }
    __half h0 = __float2half_rn(v.x);
    __half h1 = __float2half_rn(v.y);
    __half h2 = __float2half_rn(v.z);
    __half h3 = __float2half_rn(v.w);
    __half l0 = __float2half_rn(v.x - __half2float(h0));
    __half l1 = __float2half_rn(v.y - __half2float(h1));
    __half l2 = __float2half_rn(v.z - __half2float(h2));
    __half l3 = __float2half_rn(v.w - __half2float(h3));
    uint2 H, L;
    H.x = ((uint32_t)__half_as_ushort(h1) << 16) | __half_as_ushort(h0);
    H.y = ((uint32_t)__half_as_ushort(h3) << 16) | __half_as_ushort(h2);
    L.x = ((uint32_t)__half_as_ushort(l1) << 16) | __half_as_ushort(l0);
    L.y = ((uint32_t)__half_as_ushort(l3) << 16) | __half_as_ushort(l2);
    size_t base = (size_t)s * NQKV + c;
    *(uint2*)&g_qh[base] = H;
    *(uint2*)&g_ql[base] = L;
}

// ---------------------------------------------------------------------------
// QKV tensor-core GEMM: C = A @ B^T, fp16 x3 (Ah·Bh + Ah·Bl + Al·Bh), fp32 acc.
// 128x128 tile, BK=32, 256 threads, swizzled smem, 3-stage pipeline, 2 CTAs/SM.
// ---------------------------------------------------------------------------
#define GTILE 8192                      // 128 rows x 64 bytes per variant

__global__ __launch_bounds__(256, 2)
void gemm_qkv(const __half* __restrict__ Ah, const __half* __restrict__ Al,
              const __half* __restrict__ Bh, const __half* __restrict__ Bl,
              float* __restrict__ C, int N, int K)
{
    constexpr uint32_t AHI = 0;
    constexpr uint32_t ALO = GTILE;
    constexpr uint32_t BHI = 2 * GTILE;
    constexpr uint32_t BLO = 3 * GTILE;
    constexpr uint32_t GB  = 4 * GTILE;

    extern __shared__ char smc[];
    const uint32_t sbase = smem_to_u32(smc);
    const int tid  = threadIdx.x;
    const int lane = tid & 31;
    const int wid  = tid >> 5;
    const int wm0  = (wid >> 2) << 6;
    const int wn0  = (wid & 3) << 5;
    const int bm   = blockIdx.y << 7;
    const int bn   = blockIdx.x << 7;

    float acc[4][4][4];
#pragma unroll
    for (int i = 0; i < 4; ++i)
#pragma unroll
        for (int j = 0; j < 4; ++j)
#pragma unroll
            for (int q = 0; q < 4; ++q) acc[i][j][q] = 0.f;

    const int nch = K >> 5;

    auto issue = [&](int cc, uint32_t boff) {
        const int kb = cc << 5;
#pragma unroll
        for (int i2 = 0; i2 < 2; ++i2) {
            int u   = tid + (i2 << 8);
            int row = u >> 2;
            int k   = u & 3;
            int sw  = k ^ ((row >> 1) & 3);
            uint32_t d = sbase + boff + (uint32_t)(row * 64 + sw * 16);
            const int ge = kb + (k << 3);
            CP16(d + AHI, Ah + (size_t)(bm + row) * K + ge);
            CP16(d + BHI, Bh + (size_t)(bn + row) * K + ge);
            CP16(d + ALO, Al + (size_t)(bm + row) * K + ge);
            CP16(d + BLO, Bl + (size_t)(bn + row) * K + ge);
        }
    };

    const int ar = lane & 15;
    const int ac = lane >> 4;
    const int br = (lane & 7) + (((lane >> 4) & 1) << 3);
    const int bc = (lane >> 3) & 1;

    issue(0, 0u);   CP_COMMIT();
    issue(1, GB);   CP_COMMIT();

    for (int c = 0; c < nch; ++c) {
        CP_WAIT(1);
        __syncthreads();

        if (c + 2 < nch) issue(c + 2, (uint32_t)((c + 2) % 3) * GB);
        CP_COMMIT();

        const uint32_t boff = (uint32_t)(c % 3) * GB;
#pragma unroll
        for (int ks = 0; ks < 2; ++ks) {
            uint32_t ahi[4][4], bhi[2][4];
            uint32_t alo[4][4], blo[2][4];
            const int kc2 = ks << 1;
#pragma unroll
            for (int mt = 0; mt < 4; ++mt) {
                int r_ = wm0 + (mt << 4) + ar;
                int sw = (kc2 + ac) ^ ((r_ >> 1) & 3);
                uint32_t off = (uint32_t)(r_ * 64 + sw * 16);
                ldsm4(ahi[mt], sbase + boff + AHI + off);
                ldsm4(alo[mt], sbase + boff + ALO + off);
            }
#pragma unroll
            for (int np = 0; np < 2; ++np) {
                int r_ = wn0 + (np << 4) + br;
                int sw = (kc2 + bc) ^ ((r_ >> 1) & 3);
                uint32_t off = (uint32_t)(r_ * 64 + sw * 16);
                ldsm4(bhi[np], sbase + boff + BHI + off);
                ldsm4(blo[np], sbase + boff + BLO + off);
            }
            // pass 1: hi*hi
#pragma unroll
            for (int mt = 0; mt < 4; ++mt)
#pragma unroll
                for (int nt = 0; nt < 4; ++nt)
                    mma_f16(acc[mt][nt], ahi[mt], &bhi[nt >> 1][(nt & 1) << 1]);
            // pass 2: hi*lo
#pragma unroll
            for (int mt = 0; mt < 4; ++mt)
#pragma unroll
                for (int nt = 0; nt < 4; ++nt)
                    mma_f16(acc[mt][nt], ahi[mt], &blo[nt >> 1][(nt & 1) << 1]);
            // pass 3: lo*hi
#pragma unroll
            for (int mt = 0; mt < 4; ++mt)
#pragma unroll
                for (int nt = 0; nt < 4; ++nt)
                    mma_f16(acc[mt][nt], alo[mt], &bhi[nt >> 1][(nt & 1) << 1]);
        }
    }

    const int er = lane >> 2;
    const int ec = (lane & 3) << 1;
#pragma unroll
    for (int mt = 0; mt < 4; ++mt) {
#pragma unroll
        for (int nt = 0; nt < 4; ++nt) {
            int r0 = bm + wm0 + (mt << 4) + er;
            int c0 = bn + wn0 + (nt << 3) + ec;
            *(float2*)(C + (size_t)r0 * N + c0)       = make_float2(acc[mt][nt][0], acc[mt][nt][1]);
            *(float2*)(C + (size_t)(r0 + 8) * N + c0) = make_float2(acc[mt][nt][2], acc[mt][nt][3]);
        }
    }
}

// ---------------------------------------------------------------------------
// WO tensor-core GEMM: C = Ah @ Bh^T, fp16 x1, fp32 acc, BK=64.
// ---------------------------------------------------------------------------
#define WO_A 0
#define WO_B 16384
#define WO_GB 32768
#define SMEM_WO (3 * WO_GB)            // 98304

__global__ __launch_bounds__(256, 2)
void gemm_wo64(const __half* __restrict__ Ah, const __half* __restrict__ Bh,
               float* __restrict__ C, int N, int K)
{
    extern __shared__ char smc[];
    const uint32_t sbase = smem_to_u32(smc);
    const int tid  = threadIdx.x;
    const int lane = tid & 31;
    const int wid  = tid >> 5;
    const int wm0  = (wid >> 2) << 6;
    const int wn0  = (wid & 3) << 5;
    const int bm   = blockIdx.y << 7;
    const int bn   = blockIdx.x << 7;

    float acc[4][4][4];
#pragma unroll
    for (int i = 0; i < 4; ++i)
#pragma unroll
        for (int j = 0; j < 4; ++j)
#pragma unroll
            for (int q = 0; q < 4; ++q) acc[i][j][q] = 0.f;

    const int nch = K >> 6;            // 64-wide chunks

    auto issue = [&](int cc, uint32_t boff) {
        const int kb = cc << 6;
#pragma unroll
        for (int i2 = 0; i2 < 4; ++i2) {
            int u   = tid + (i2 << 8);      // 0..1023
            int row = u >> 3;
            int k   = u & 7;
            int sub = k >> 2;
            int sw  = (k & 3) ^ ((row >> 1) & 3);
            uint32_t d = sbase + boff + (uint32_t)(sub * 8192 + row * 64 + sw * 16);
            const int ge = kb + (k << 3);
            CP16(d + WO_A, Ah + (size_t)(bm + row) * K + ge);
            CP16(d + WO_B, Bh + (size_t)(bn + row) * K + ge);
        }
    };

    const int ar = lane & 15;
    const int ac = lane >> 4;
    const int br = (lane & 7) + (((lane >> 4) & 1) << 3);
    const int bc = (lane >> 3) & 1;

    issue(0, 0u);       CP_COMMIT();
    issue(1, WO_GB);    CP_COMMIT();

    for (int c = 0; c < nch; ++c) {
        CP_WAIT(1);
        __syncthreads();

        if (c + 2 < nch) issue(c + 2, (uint32_t)((c + 2) % 3) * WO_GB);
        CP_COMMIT();

        const uint32_t boff = (uint32_t)(c % 3) * WO_GB;
#pragma unroll
        for (int ks = 0; ks < 4; ++ks) {
            const uint32_t suboff = (uint32_t)((ks >> 1) * 8192);
            const int kc2 = (ks & 1) << 1;
            uint32_t ahi[4][4], bhi[2][4];
#pragma unroll
            for (int mt = 0; mt < 4; ++mt) {
                int r_ = wm0 + (mt << 4) + ar;
                int sw = (kc2 + ac) ^ ((r_ >> 1) & 3);
                ldsm4(ahi[mt], sbase + boff + WO_A + suboff + (uint32_t)(r_ * 64 + sw * 16));
            }
#pragma unroll
            for (int np = 0; np < 2; ++np) {
                int r_ = wn0 + (np << 4) + br;
                int sw = (kc2 + bc) ^ ((r_ >> 1) & 3);
                ldsm4(bhi[np], sbase + boff + WO_B + suboff + (uint32_t)(r_ * 64 + sw * 16));
            }
#pragma unroll
            for (int mt = 0; mt < 4; ++mt)
#pragma unroll
                for (int nt = 0; nt < 4; ++nt)
                    mma_f16(acc[mt][nt], ahi[mt], &bhi[nt >> 1][(nt & 1) << 1]);
        }
    }

    const int er = lane >> 2;
    const int ec = (lane & 3) << 1;
#pragma unroll
    for (int mt = 0; mt < 4; ++mt) {
#pragma unroll
        for (int nt = 0; nt < 4; ++nt) {
            int r0 = bm + wm0 + (mt << 4) + er;
            int c0 = bn + wn0 + (nt << 3) + ec;
            *(float2*)(C + (size_t)r0 * N + c0)       = make_float2(acc[mt][nt][0], acc[mt][nt][1]);
            *(float2*)(C + (size_t)(r0 + 8) * N + c0) = make_float2(acc[mt][nt][2], acc[mt][nt][3]);
        }
    }
}

// ---------------------------------------------------------------------------
// Per-block key means (8 tokens per block)
// ---------------------------------------------------------------------------
__global__ void kmean_kernel()
{
    int idx = blockIdx.x * blockDim.x + threadIdx.x;
    int d  = idx & 127;
    int hl = (idx >> 7) & 7;
    int t  = idx >> 10;
    const float* p = &g_qkv[(size_t)(t * 8) * NQKV + HQ * HD + hl * HD + d];
    float s = 0.f;
#pragma unroll
    for (int i = 0; i < 8; ++i) s += p[(size_t)i * NQKV];
    g_krep[idx] = s * 0.125f;
}

// ---------------------------------------------------------------------------
// Mean query per head — deterministic 2-stage
// ---------------------------------------------------------------------------
__global__ void qmean_part_kernel()
{
    int h = blockIdx.x, chunk = blockIdx.y, d = threadIdx.x;
    const float* p = &g_qkv[(size_t)(chunk * 256) * NQKV + h * HD + d];
    float s = 0.f;
#pragma unroll 4
    for (int i = 0; i < 256; ++i) s += p[(size_t)i * NQKV];
    g_qpart[chunk][h * HD + d] = s;
}

__global__ void qmean_final_kernel()
{
    int idx = blockIdx.x * blockDim.x + threadIdx.x;
    float s = 0.f;
#pragma unroll
    for (int i = 0; i < 16; ++i) s += g_qpart[i][idx];
    g_qmean[idx] = s * (1.f / 4096.f);
}

// ---------------------------------------------------------------------------
// Scores + top-k block selection. One block per head, 512 threads.
// Shuffle-based argmax (2 barriers per pick instead of 9). Tie-break = lower
// index, matching jax.lax.top_k. Selection identical to previous version.
// ---------------------------------------------------------------------------
__global__ void scores_topk_kernel()
{
    __shared__ float qm[HD];
    __shared__ float sc[TB];
    __shared__ float wv[16];
    __shared__ int   wi[16];

    const int h    = blockIdx.x;
    const int t    = threadIdx.x;
    const int lane = t & 31;
    const int wrp  = t >> 5;
    const int hl   = h >> 2;

    if (t < HD) qm[t] = g_qmean[h * HD + t];
    __syncthreads();

    float s = 0.f;
    const float* kr = &g_krep[(t * HKV + hl) * HD];
#pragma unroll 8
    for (int d = 0; d < HD; ++d) s += qm[d] * kr[d];
    s *= SCALE;

    bool masked = (t < SINKB) || (t >= WINST);
    sc[t] = masked ? NEGF : s;

    if (t < 4) {
        g_blk[h * KLBLK + t]     = t;
        g_blk[h * KLBLK + 4 + t] = WINST + t;
    }
    __syncthreads();

    for (int pick = 0; pick < MBTOP; ++pick) {
        float v = sc[t];
        int   i = t;
#pragma unroll
        for (int off = 16; off > 0; off >>= 1) {
            float v2 = __shfl_down_sync(0xffffffffu, v, off);
            int   i2 = __shfl_down_sync(0xffffffffu, i, off);
            if (v2 > v || (v2 == v && i2 < i)) { v = v2; i = i2; }
        }
        if (lane == 0) { wv[wrp] = v; wi[wrp] = i; }
        __syncthreads();
        if (t < 32) {
            float fv = (t < 16) ? wv[t] : -3e30f;
            int   fi = (t < 16) ? wi[t] : 0x7fffffff;
#pragma unroll
            for (int off = 8; off > 0; off >>= 1) {
                float v2 = __shfl_down_sync(0xffffffffu, fv, off);
                int   i2 = __shfl_down_sync(0xffffffffu, fi, off);
                if (v2 > fv || (v2 == fv && i2 < fi)) { fv = v2; fi = i2; }
            }
            if (t == 0) {
                g_blk[h * KLBLK + 8 + pick] = fi;
                sc[fi] = -2e30f;
            }
        }
        __syncthreads();
    }
}

// ---------------------------------------------------------------------------
// Tensor-core flash attention over 864 selected tokens per head.
// fp16: QK^T x3; P·V x2 (P_hi·V_hi + P_lo·V_hi — V_lo dropped, err ~2.8e-4
// unamplified). grid = (S/64, HQ), 128 threads (4 warps x 16 q-rows).
// ---------------------------------------------------------------------------
#define ASTRIDE 272                 // smem row stride in bytes (136 fp16)
#define QH_OFF  0
#define QL_OFF  17408
#define KH_OFF  34816
#define KL_OFF  43520
#define VH_OFF  52224
#define TOK_OFF 60928
#define FLG_OFF 61056
#define SMEM_ATTN 61120

__global__ __launch_bounds__(128)
void attn_mma_kernel()
{
    extern __shared__ char smb[];
    const uint32_t sb = smem_to_u32(smb);
    int* toks = (int*)(smb + TOK_OFF);
    int* sflg = (int*)(smb + FLG_OFF);

    const int tid  = threadIdx.x;
    const int lane = tid & 31;
    const int wid  = tid >> 5;
    const int h    = blockIdx.y;
    const int q0   = blockIdx.x << 6;
    const int hl   = h >> 2;
    const int m0   = wid << 4;

    const int er = lane >> 2;
    const int ec = (lane & 3) << 1;

    // load Q tile rows q0..q0+63, head slice (hi+lo)
    {
        const size_t qcol = (size_t)h * HD;
        for (int t = tid; t < 1024; t += 128) {
            int r = t >> 4, ch = t & 15;
            uint32_t d = sb + (uint32_t)(r * ASTRIDE + ch * 16);
            const size_t src = (size_t)(q0 + r) * NQKV + qcol + ch * 8;
            CP16(d + QH_OFF, g_qh + src);
            CP16(d + QL_OFF, g_ql + src);
        }
    }
    CP_COMMIT();

    float oacc[16][4];
#pragma unroll
    for (int i = 0; i < 16; ++i)
#pragma unroll
        for (int j = 0; j < 4; ++j) oacc[i][j] = 0.f;
    float mrow0 = NEGF, mrow1 = NEGF, lrow0 = 0.f, lrow1 = 0.f;

    CP_WAIT(0);
    __syncthreads();

    for (int kt = 0; kt < KSEL / 32; ++kt) {
        if (tid < 32) {
            int j = kt * 32 + tid;
            int b = g_blk[h * KLBLK + (j >> 3)];
            toks[tid] = (b << 3) + (j & 7);
        }
        __syncthreads();
        if (tid == 0) {
            int mn = toks[0];
#pragma unroll
            for (int i = 1; i < 32; ++i) mn = min(mn, toks[i]);
            sflg[0] = (mn > q0 + 63);
        }
        __syncthreads();
        if (sflg[0]) continue;

        // gather K (hi+lo) and V (hi only) rows via cp.async
        {
            const size_t kcol = (size_t)HQ * HD + (size_t)hl * HD;
            for (int t = tid; t < 512; t += 128) {
                int r = t >> 4, ch = t & 15;
                size_t src = (size_t)toks[r] * NQKV + kcol + ch * 8;
                uint32_t d = sb + (uint32_t)(r * ASTRIDE + ch * 16);
                CP16(d + KH_OFF, g_qh + src);
                CP16(d + KL_OFF, g_ql + src);
                CP16(d + VH_OFF, g_qh + src + HKV * HD);
            }
        }
        CP_COMMIT(); CP_WAIT(0);
        __syncthreads();

        // ---- scores: S = Q @ K^T (64x32), fp16 x3 ----
        float sc[4][4];
#pragma unroll
        for (int i = 0; i < 4; ++i)
#pragma unroll
            for (int j = 0; j < 4; ++j) sc[i][j] = 0.f;

#pragma unroll
        for (int ks = 0; ks < 8; ++ks) {
            const int kc = ks << 4;
            uint32_t ah[4], al[4], kh0[4], kl0[4], kh1[4], kl1[4];
            uint32_t aoff = (uint32_t)((m0 + (lane & 15)) * ASTRIDE)
                          + (uint32_t)((kc + ((lane >> 4) << 3)) * 2);
            ldsm4(ah, sb + QH_OFF + aoff);
            ldsm4(al, sb + QL_OFF + aoff);
            uint32_t boff = (uint32_t)((((lane & 7) + (((lane >> 4) & 1) << 3)) * ASTRIDE))
                          + (uint32_t)((kc + (((lane >> 3) & 1) << 3)) * 2);
            ldsm4(kh0, sb + KH_OFF + boff);
            ldsm4(kl0, sb + KL_OFF + boff);
            ldsm4(kh1, sb + KH_OFF + boff + 16 * ASTRIDE);
            ldsm4(kl1, sb + KL_OFF + boff + 16 * ASTRIDE);
#pragma unroll
            for (int nt = 0; nt < 4; ++nt)
                mma_f16(sc[nt], ah, (nt < 2) ? &kh0[(nt & 1) << 1] : &kh1[(nt & 1) << 1]);
#pragma unroll
            for (int nt = 0; nt < 4; ++nt)
                mma_f16(sc[nt], ah, (nt < 2) ? &kl0[(nt & 1) << 1] : &kl1[(nt & 1) << 1]);
#pragma unroll
            for (int nt = 0; nt < 4; ++nt)
                mma_f16(sc[nt], al, (nt < 2) ? &kh0[(nt & 1) << 1] : &kh1[(nt & 1) << 1]);
        }

        // ---- scale + causal mask ----
        const int qr0 = q0 + m0 + er;
        const int qr1 = qr0 + 8;
#pragma unroll
        for (int nt = 0; nt < 4; ++nt) {
            int2 tt = *(int2*)&toks[(nt << 3) + ec];
            sc[nt][0] = (tt.x <= qr0) ? sc[nt][0] * SCALE : NEGF;
            sc[nt][1] = (tt.y <= qr0) ? sc[nt][1] * SCALE : NEGF;
            sc[nt][2] = (tt.x <= qr1) ? sc[nt][2] * SCALE : NEGF;
            sc[nt][3] = (tt.y <= qr1) ? sc[nt][3] * SCALE : NEGF;
        }

        // ---- online softmax on fragments (quad reductions) ----
        float mt0 = fmaxf(fmaxf(fmaxf(sc[0][0], sc[0][1]), fmaxf(sc[1][0], sc[1][1])),
                          fmaxf(fmaxf(sc[2][0], sc[2][1]), fmaxf(sc[3][0], sc[3][1])));
        float mt1 = fmaxf(fmaxf(fmaxf(sc[0][2], sc[0][3]), fmaxf(sc[1][2], sc[1][3])),
                          fmaxf(fmaxf(sc[2][2], sc[2][3]), fmaxf(sc[3][2], sc[3][3])));
        mt0 = fmaxf(mt0, __shfl_xor_sync(0xffffffffu, mt0, 1));
        mt0 = fmaxf(mt0, __shfl_xor_sync(0xffffffffu, mt0, 2));
        mt1 = fmaxf(mt1, __shfl_xor_sync(0xffffffffu, mt1, 1));
        mt1 = fmaxf(mt1, __shfl_xor_sync(0xffffffffu, mt1, 2));
        float mn0 = fmaxf(mrow0, mt0);
        float mn1 = fmaxf(mrow1, mt1);
        float cc0 = __expf(mrow0 - mn0);
        float cc1 = __expf(mrow1 - mn1);
        float ls0 = 0.f, ls1 = 0.f;
#pragma unroll
        for (int nt = 0; nt < 4; ++nt) {
            float p0 = (sc[nt][0] > -1e29f) ? __expf(sc[nt][0] - mn0) : 0.f;
            float p1 = (sc[nt][1] > -1e29f) ? __expf(sc[nt][1] - mn0) : 0.f;
            float p2 = (sc[nt][2] > -1e29f) ? __expf(sc[nt][2] - mn1) : 0.f;
            float p3 = (sc[nt][3] > -1e29f) ? __expf(sc[nt][3] - mn1) : 0.f;
            sc[nt][0] = p0; sc[nt][1] = p1; sc[nt][2] = p2; sc[nt][3] = p3;
            ls0 += p0 + p1; ls1 += p2 + p3;
        }
        ls0 += __shfl_xor_sync(0xffffffffu, ls0, 1);
        ls0 += __shfl_xor_sync(0xffffffffu, ls0, 2);
        ls1 += __shfl_xor_sync(0xffffffffu, ls1, 1);
        ls1 += __shfl_xor_sync(0xffffffffu, ls1, 2);
        lrow0 = lrow0 * cc0 + ls0;  mrow0 = mn0;
        lrow1 = lrow1 * cc1 + ls1;  mrow1 = mn1;

#pragma unroll
        for (int nt = 0; nt < 16; ++nt) {
            oacc[nt][0] *= cc0; oacc[nt][1] *= cc0;
            oacc[nt][2] *= cc1; oacc[nt][3] *= cc1;
        }

        // ---- pack P into A fragments (hi/lo, fp16) ----
        uint32_t ph[2][4], pl[2][4];
#pragma unroll
        for (int ks = 0; ks < 2; ++ks) {
#pragma unroll
            for (int hh = 0; hh < 2; ++hh) {
                int nt = (ks << 1) + hh;
                float p0 = sc[nt][0], p1 = sc[nt][1], p2 = sc[nt][2], p3 = sc[nt][3];
                uint32_t h01 = pack_f16(p0, p1);
                uint32_t h23 = pack_f16(p2, p3);
                ph[ks][(hh << 1) + 0] = h01;
                ph[ks][(hh << 1) + 1] = h23;
                __half2 b01 = *(__half2*)&h01;
                __half2 b23 = *(__half2*)&h23;
                pl[ks][(hh << 1) + 0] = pack_f16(p0 - __half2float(b01.x),
                                                 p1 - __half2float(b01.y));
                pl[ks][(hh << 1) + 1] = pack_f16(p2 - __half2float(b23.x),
                                                 p3 - __half2float(b23.y));
            }
        }

        // ---- O += P @ V (64x128), fp16 x2 (V-lo dropped) ----
#pragma unroll
        for (int ks = 0; ks < 2; ++ks) {
#pragma unroll
            for (int ng = 0; ng < 8; ++ng) {
                uint32_t vh[4];
                uint32_t voff = (uint32_t)(((ks << 4) + (lane & 15)) * ASTRIDE)
                              + (uint32_t)(((ng << 4) + ((lane >> 4) << 3)) * 2);
                ldsm4t(vh, sb + VH_OFF + voff);
                mma_f16(oacc[2 * ng],     ph[ks], &vh[0]);
                mma_f16(oacc[2 * ng + 1], ph[ks], &vh[2]);
                mma_f16(oacc[2 * ng],     pl[ks], &vh[0]);
                mma_f16(oacc[2 * ng + 1], pl[ks], &vh[2]);
            }
        }
        __syncthreads();   // protect K/V smem before next tile's cp.async
    }

    // ---- epilogue: normalize, store fp16 (hi only — WO GEMM is fp16 x1) ----
    const float inv0 = 1.f / lrow0;
    const float inv1 = 1.f / lrow1;
    const int row0 = q0 + m0 + er;
    const int row1 = row0 + 8;
#pragma unroll
    for (int nt = 0; nt < 16; ++nt) {
        int col = h * HD + (nt << 3) + ec;
        *(uint32_t*)&g_ath[(size_t)row0 * DIMM + col] =
            pack_f16(oacc[nt][0] * inv0, oacc[nt][1] * inv0);
        *(uint32_t*)&g_ath[(size_t)row1 * DIMM + col] =
            pack_f16(oacc[nt][2] * inv1, oacc[nt][3] * inv1);
    }
}

// ---------------------------------------------------------------------------
// Host launcher
// ---------------------------------------------------------------------------
extern "C" void kernel_launch(void* const* d_in, const int* in_sizes, int n_in,
                              void* d_out, int out_size)
{
    (void)in_sizes; (void)n_in; (void)out_size;
    const float* x    = (const float*)d_in[0];
    const float* fc   = (const float*)d_in[1];
    const float* wqkv = (const float*)d_in[2];
    const float* wo   = (const float*)d_in[3];
    float* y = (float*)d_out;

    float* qkv_p = nullptr;
    __half *xh, *xl, *wqh, *wql, *woh, *ath;
    cudaGetSymbolAddress((void**)&qkv_p, g_qkv);
    cudaGetSymbolAddress((void**)&xh,  g_xh);  cudaGetSymbolAddress((void**)&xl,  g_xl);
    cudaGetSymbolAddress((void**)&wqh, g_wqh); cudaGetSymbolAddress((void**)&wql, g_wql);
    cudaGetSymbolAddress((void**)&woh, g_woh);
    cudaGetSymbolAddress((void**)&ath, g_ath);

    cudaFuncSetAttribute(attn_mma_kernel, cudaFuncAttributeMaxDynamicSharedMemorySize, SMEM_ATTN);
    cudaFuncSetAttribute(gemm_qkv,  cudaFuncAttributeMaxDynamicSharedMemorySize, 3 * 4 * GTILE);
    cudaFuncSetAttribute(gemm_wo64, cudaFuncAttributeMaxDynamicSharedMemorySize, SMEM_WO);

    // 0. split GEMM inputs to fp16 (x, wqkv: hi+lo; wo: hi only)
    {
        int n4x = (S * DIMM) / 4;
        split_kernel<<<(n4x + 255) / 256, 256>>>(x, xh, xl, n4x);
        int n4q = (NQKV * DIMM) / 4;
        split_kernel<<<(n4q + 255) / 256, 256>>>(wqkv, wqh, wql, n4q);
        int n4o = (DIMM * DIMM) / 4;
        split_hi_kernel<<<(n4o + 255) / 256, 256>>>(wo, woh, n4o);
    }

    // 1. QKV projection (fp16 x3 — error ~2^-22)
    gemm_qkv<<<dim3(NQKV / 128, S / 128), 256, 3 * 4 * GTILE>>>(
        xh, xl, wqh, wql, qkv_p, NQKV, DIMM);

    // 2. fused RoPE + fp16 hi/lo split of roped qkv
    {
        int n4 = (S * NQKV) / 4;
        rope_split_kernel<<<(n4 + 255) / 256, 256>>>(fc);
    }

    // 3. per-block key means + query mean
    kmean_kernel<<<(TB * HKV * HD) / 256, 256>>>();
    qmean_part_kernel<<<dim3(HQ, 16), 128>>>();
    qmean_final_kernel<<<(HQ * HD) / 128, 128>>>();

    // 4. scores + top-k block selection (shuffle-based argmax)
    scores_topk_kernel<<<HQ, TB>>>();

    // 5. tensor-core sparse causal attention (QK x3, PV x2)
    attn_mma_kernel<<<dim3(S / 64, HQ), 128, SMEM_ATTN>>>();

    // 6. output projection (fp16 x1, BK=64 — final op, error unamplified ~4e-4)
    gemm_wo64<<<dim3(DIMM / 128, S / 128), 256, SMEM_WO>>>(
        ath, woh, y, DIMM, DIMM);
}

// round 15
// speedup vs baseline: 1.1737x; 1.0403x over previous
#include <cuda_runtime.h>
#include <cuda_fp16.h>
#include <cstdint>

// ---------------------------------------------------------------------------
// Problem constants (fixed shapes)
// ---------------------------------------------------------------------------
#define S      4096
#define DIMM   4096
#define HQ     32
#define HKV    8
#define HD     128
#define NQKV   6144          // (HQ + 2*HKV) * HD
#define TB     512           // S / 8 blocks
#define SINKB  4             // ceil(30/8)
#define WINST  508           // window start block
#define MBTOP  100           // heavy blocks
#define KLBLK  108           // 4 sink + 4 window + 100 heavy
#define KSEL   (KLBLK * 8)   // 864 selected tokens per head
#define NEGF   (-1e30f)
#define SCALE  0.08838834764831845f   // 1/sqrt(128)
#define VCOL0  ((HQ + HKV) * HD)      // 5120 — first v column

// ---------------------------------------------------------------------------
// Scratch (static device globals — no runtime allocation allowed)
// ---------------------------------------------------------------------------
__device__ float g_qkv[(size_t)S * NQKV];     // qkv projections (fp32, roped in place)
__device__ float g_krep[TB * HKV * HD];       // per-block mean keys
__device__ float g_qmean[HQ * HD];            // mean query per head
__device__ float g_qpart[16][HQ * HD];        // partial q sums (deterministic 2-stage)
__device__ int   g_blk[HQ * KLBLK];           // selected block ids per head

// fp16 hi/lo split operands
__device__ __align__(16) __half g_xh[(size_t)S * DIMM];
__device__ __align__(16) __half g_xl[(size_t)S * DIMM];
__device__ __align__(16) __half g_wqh[(size_t)NQKV * DIMM];
__device__ __align__(16) __half g_wql[(size_t)NQKV * DIMM];
__device__ __align__(16) __half g_woh[(size_t)DIMM * DIMM];   // hi only (WO is fp16 x1)
__device__ __align__(16) __half g_ath[(size_t)S * DIMM];      // attention out (hi only)
__device__ __align__(16) __half g_qh[(size_t)S * NQKV];       // roped qkv hi
__device__ __align__(16) __half g_ql[(size_t)S * NQKV];       // roped qkv lo

// ---------------------------------------------------------------------------
// asm helpers (base-ISA only; no tcgen05 on this toolchain)
// ---------------------------------------------------------------------------
__device__ __forceinline__ uint32_t smem_to_u32(const void* smem_ptr) {
    uint32_t addr;
    asm("{ .reg .u64 tmp; cvta.to.shared.u64 tmp, %1; cvt.u32.u64 %0, tmp; }"
        : "=r"(addr) : "l"(smem_ptr));
    return addr;
}

__device__ __forceinline__ void ldsm4(uint32_t* r, uint32_t addr) {
    asm volatile("ldmatrix.sync.aligned.m8n8.x4.shared.b16 {%0,%1,%2,%3}, [%4];"
        : "=r"(r[0]), "=r"(r[1]), "=r"(r[2]), "=r"(r[3]) : "r"(addr));
}

__device__ __forceinline__ void ldsm4t(uint32_t* r, uint32_t addr) {
    asm volatile("ldmatrix.sync.aligned.m8n8.x4.trans.shared.b16 {%0,%1,%2,%3}, [%4];"
        : "=r"(r[0]), "=r"(r[1]), "=r"(r[2]), "=r"(r[3]) : "r"(addr));
}

__device__ __forceinline__ void mma_f16(float* d, const uint32_t* a, const uint32_t* b) {
    asm volatile("mma.sync.aligned.m16n8k16.row.col.f32.f16.f16.f32 "
        "{%0,%1,%2,%3}, {%4,%5,%6,%7}, {%8,%9}, {%0,%1,%2,%3};"
        : "+f"(d[0]), "+f"(d[1]), "+f"(d[2]), "+f"(d[3])
        : "r"(a[0]), "r"(a[1]), "r"(a[2]), "r"(a[3]), "r"(b[0]), "r"(b[1]));
}

#define CP16(dst, src) \
    asm volatile("cp.async.cg.shared.global [%0], [%1], 16;" :: "r"(dst), "l"(src))
#define CP_COMMIT() asm volatile("cp.async.commit_group;" ::: "memory")
#define CP_WAIT(n)  asm volatile("cp.async.wait_group %0;" :: "n"(n) : "memory")

__device__ __forceinline__ uint32_t pack_f16(float a, float b) {
    __half2 h = __floats2half2_rn(a, b);
    return *(uint32_t*)&h;
}

// ---------------------------------------------------------------------------
// fp32 -> fp16 hi/lo split (pre-pass), float4 per thread
// ---------------------------------------------------------------------------
__global__ void split_kernel(const float* __restrict__ in,
                             __half* __restrict__ hi,
                             __half* __restrict__ lo, int n4)
{
    int i = blockIdx.x * blockDim.x + threadIdx.x;
    if (i >= n4) return;
    float4 v = ((const float4*)in)[i];
    __half h0 = __float2half_rn(v.x);
    __half h1 = __float2half_rn(v.y);
    __half h2 = __float2half_rn(v.z);
    __half h3 = __float2half_rn(v.w);
    __half l0 = __float2half_rn(v.x - __half2float(h0));
    __half l1 = __float2half_rn(v.y - __half2float(h1));
    __half l2 = __float2half_rn(v.z - __half2float(h2));
    __half l3 = __float2half_rn(v.w - __half2float(h3));
    uint2 H, L;
    H.x = ((uint32_t)__half_as_ushort(h1) << 16) | __half_as_ushort(h0);
    H.y = ((uint32_t)__half_as_ushort(h3) << 16) | __half_as_ushort(h2);
    L.x = ((uint32_t)__half_as_ushort(l1) << 16) | __half_as_ushort(l0);
    L.y = ((uint32_t)__half_as_ushort(l3) << 16) | __half_as_ushort(l2);
    ((uint2*)hi)[i] = H;
    ((uint2*)lo)[i] = L;
}

// hi-only variant (for wo weights — WO GEMM runs fp16 x1)
__global__ void split_hi_kernel(const float* __restrict__ in,
                                __half* __restrict__ hi, int n4)
{
    int i = blockIdx.x * blockDim.x + threadIdx.x;
    if (i >= n4) return;
    float4 v = ((const float4*)in)[i];
    uint2 H;
    H.x = pack_f16(v.x, v.y);
    H.y = pack_f16(v.z, v.w);
    ((uint2*)hi)[i] = H;
}

// ---------------------------------------------------------------------------
// Fused RoPE + fp16 hi/lo split of the roped qkv tensor.
// ---------------------------------------------------------------------------
__global__ void rope_split_kernel(const float* __restrict__ fc)
{
    const int n4 = (S * NQKV) / 4;
    int i = blockIdx.x * blockDim.x + threadIdx.x;
    if (i >= n4) return;
    int col4 = i % (NQKV / 4);
    int s    = i / (NQKV / 4);
    int c    = col4 << 2;
    int hh   = c >> 7;             // head index 0..47
    float4 v = *(float4*)&g_qkv[(size_t)s * NQKV + c];
    if (hh < 40) {                 // q (0..31) and k (32..39) get rope
        float4 f = *(const float4*)&fc[s * HD + (c & 127)];
        float x0 = v.x, x1 = v.y, x2 = v.z, x3 = v.w;
        v.x = x0 * f.x - x1 * f.y;
        v.y = x1 * f.x + x0 * f.y;
        v.z = x2 * f.z - x3 * f.w;
        v.w = x3 * f.z + x2 * f.w;
        *(float4*)&g_qkv[(size_t)s * NQKV + c] = v;
    }
    __half h0 = __float2half_rn(v.x);
    __half h1 = __float2half_rn(v.y);
    __half h2 = __float2half_rn(v.z);
    __half h3 = __float2half_rn(v.w);
    __half l0 = __float2half_rn(v.x - __half2float(h0));
    __half l1 = __float2half_rn(v.y - __half2float(h1));
    __half l2 = __float2half_rn(v.z - __half2float(h2));
    __half l3 = __float2half_rn(v.w - __half2float(h3));
    uint2 H, L;
    H.x = ((uint32_t)__half_as_ushort(h1) << 16) | __half_as_ushort(h0);
    H.y = ((uint32_t)__half_as_ushort(h3) << 16) | __half_as_ushort(h2);
    L.x = ((uint32_t)__half_as_ushort(l1) << 16) | __half_as_ushort(l0);
    L.y = ((uint32_t)__half_as_ushort(l3) << 16) | __half_as_ushort(l2);
    size_t base = (size_t)s * NQKV + c;
    *(uint2*)&g_qh[base] = H;
    *(uint2*)&g_ql[base] = L;
}

// ---------------------------------------------------------------------------
// QKV tensor-core GEMM: C = A @ B^T, fp16, fp32 acc.
// q/k column tiles (bn < 5120): x3 products (Ah·Bh + Ah·Bl + Al·Bh) —
//   bit-identical to round 13; selection unaffected.
// v column tiles (bn >= 5120): x2 (Ah·Bh + Al·Bh) — w_lo dropped; v error
//   ~1.4e-4, linear through attention/WO, never touches top-k.
// 128x128 tile, BK=32, 256 threads, swizzled smem, 3-stage pipeline, 2 CTAs/SM.
// ---------------------------------------------------------------------------
#define GTILE 8192                      // 128 rows x 64 bytes per variant

__global__ __launch_bounds__(256, 2)
void gemm_qkv(const __half* __restrict__ Ah, const __half* __restrict__ Al,
              const __half* __restrict__ Bh, const __half* __restrict__ Bl,
              float* __restrict__ C, int N, int K)
{
    constexpr uint32_t AHI = 0;
    constexpr uint32_t ALO = GTILE;
    constexpr uint32_t BHI = 2 * GTILE;
    constexpr uint32_t BLO = 3 * GTILE;
    constexpr uint32_t GB  = 4 * GTILE;

    extern __shared__ char smc[];
    const uint32_t sbase = smem_to_u32(smc);
    const int tid  = threadIdx.x;
    const int lane = tid & 31;
    const int wid  = tid >> 5;
    const int wm0  = (wid >> 2) << 6;
    const int wn0  = (wid & 3) << 5;
    const int bm   = blockIdx.y << 7;
    const int bn   = blockIdx.x << 7;
    const bool vblk = (bn >= VCOL0);    // v-head tile: skip B_lo entirely

    float acc[4][4][4];
#pragma unroll
    for (int i = 0; i < 4; ++i)
#pragma unroll
        for (int j = 0; j < 4; ++j)
#pragma unroll
            for (int q = 0; q < 4; ++q) acc[i][j][q] = 0.f;

    const int nch = K >> 5;

    auto issue = [&](int cc, uint32_t boff) {
        const int kb = cc << 5;
#pragma unroll
        for (int i2 = 0; i2 < 2; ++i2) {
            int u   = tid + (i2 << 8);
            int row = u >> 2;
            int k   = u & 3;
            int sw  = k ^ ((row >> 1) & 3);
            uint32_t d = sbase + boff + (uint32_t)(row * 64 + sw * 16);
            const int ge = kb + (k << 3);
            CP16(d + AHI, Ah + (size_t)(bm + row) * K + ge);
            CP16(d + BHI, Bh + (size_t)(bn + row) * K + ge);
            CP16(d + ALO, Al + (size_t)(bm + row) * K + ge);
            if (!vblk) CP16(d + BLO, Bl + (size_t)(bn + row) * K + ge);
        }
    };

    const int ar = lane & 15;
    const int ac = lane >> 4;
    const int br = (lane & 7) + (((lane >> 4) & 1) << 3);
    const int bc = (lane >> 3) & 1;

    issue(0, 0u);   CP_COMMIT();
    issue(1, GB);   CP_COMMIT();

    for (int c = 0; c < nch; ++c) {
        CP_WAIT(1);
        __syncthreads();

        if (c + 2 < nch) issue(c + 2, (uint32_t)((c + 2) % 3) * GB);
        CP_COMMIT();

        const uint32_t boff = (uint32_t)(c % 3) * GB;
#pragma unroll
        for (int ks = 0; ks < 2; ++ks) {
            uint32_t ahi[4][4], alo[4][4], bhi[2][4], blo[2][4];
            const int kc2 = ks << 1;
#pragma unroll
            for (int mt = 0; mt < 4; ++mt) {
                int r_ = wm0 + (mt << 4) + ar;
                int sw = (kc2 + ac) ^ ((r_ >> 1) & 3);
                uint32_t off = (uint32_t)(r_ * 64 + sw * 16);
                ldsm4(ahi[mt], sbase + boff + AHI + off);
                ldsm4(alo[mt], sbase + boff + ALO + off);
            }
#pragma unroll
            for (int np = 0; np < 2; ++np) {
                int r_ = wn0 + (np << 4) + br;
                int sw = (kc2 + bc) ^ ((r_ >> 1) & 3);
                uint32_t off = (uint32_t)(r_ * 64 + sw * 16);
                ldsm4(bhi[np], sbase + boff + BHI + off);
                if (!vblk) ldsm4(blo[np], sbase + boff + BLO + off);
            }
            // pass 1: hi*hi
#pragma unroll
            for (int mt = 0; mt < 4; ++mt)
#pragma unroll
                for (int nt = 0; nt < 4; ++nt)
                    mma_f16(acc[mt][nt], ahi[mt], &bhi[nt >> 1][(nt & 1) << 1]);
            // pass 2: hi*lo (skipped on v tiles)
            if (!vblk) {
#pragma unroll
                for (int mt = 0; mt < 4; ++mt)
#pragma unroll
                    for (int nt = 0; nt < 4; ++nt)
                        mma_f16(acc[mt][nt], ahi[mt], &blo[nt >> 1][(nt & 1) << 1]);
            }
            // pass 3: lo*hi
#pragma unroll
            for (int mt = 0; mt < 4; ++mt)
#pragma unroll
                for (int nt = 0; nt < 4; ++nt)
                    mma_f16(acc[mt][nt], alo[mt], &bhi[nt >> 1][(nt & 1) << 1]);
        }
    }

    const int er = lane >> 2;
    const int ec = (lane & 3) << 1;
#pragma unroll
    for (int mt = 0; mt < 4; ++mt) {
#pragma unroll
        for (int nt = 0; nt < 4; ++nt) {
            int r0 = bm + wm0 + (mt << 4) + er;
            int c0 = bn + wn0 + (nt << 3) + ec;
            *(float2*)(C + (size_t)r0 * N + c0)       = make_float2(acc[mt][nt][0], acc[mt][nt][1]);
            *(float2*)(C + (size_t)(r0 + 8) * N + c0) = make_float2(acc[mt][nt][2], acc[mt][nt][3]);
        }
    }
}

// ---------------------------------------------------------------------------
// WO tensor-core GEMM: C = Ah @ Bh^T, fp16 x1, fp32 acc, BK=64.
// ---------------------------------------------------------------------------
#define WO_A 0
#define WO_B 16384
#define WO_GB 32768
#define SMEM_WO (3 * WO_GB)            // 98304

__global__ __launch_bounds__(256, 2)
void gemm_wo64(const __half* __restrict__ Ah, const __half* __restrict__ Bh,
               float* __restrict__ C, int N, int K)
{
    extern __shared__ char smc[];
    const uint32_t sbase = smem_to_u32(smc);
    const int tid  = threadIdx.x;
    const int lane = tid & 31;
    const int wid  = tid >> 5;
    const int wm0  = (wid >> 2) << 6;
    const int wn0  = (wid & 3) << 5;
    const int bm   = blockIdx.y << 7;
    const int bn   = blockIdx.x << 7;

    float acc[4][4][4];
#pragma unroll
    for (int i = 0; i < 4; ++i)
#pragma unroll
        for (int j = 0; j < 4; ++j)
#pragma unroll
            for (int q = 0; q < 4; ++q) acc[i][j][q] = 0.f;

    const int nch = K >> 6;            // 64-wide chunks

    auto issue = [&](int cc, uint32_t boff) {
        const int kb = cc << 6;
#pragma unroll
        for (int i2 = 0; i2 < 4; ++i2) {
            int u   = tid + (i2 << 8);      // 0..1023
            int row = u >> 3;
            int k   = u & 7;
            int sub = k >> 2;
            int sw  = (k & 3) ^ ((row >> 1) & 3);
            uint32_t d = sbase + boff + (uint32_t)(sub * 8192 + row * 64 + sw * 16);
            const int ge = kb + (k << 3);
            CP16(d + WO_A, Ah + (size_t)(bm + row) * K + ge);
            CP16(d + WO_B, Bh + (size_t)(bn + row) * K + ge);
        }
    };

    const int ar = lane & 15;
    const int ac = lane >> 4;
    const int br = (lane & 7) + (((lane >> 4) & 1) << 3);
    const int bc = (lane >> 3) & 1;

    issue(0, 0u);       CP_COMMIT();
    issue(1, WO_GB);    CP_COMMIT();

    for (int c = 0; c < nch; ++c) {
        CP_WAIT(1);
        __syncthreads();

        if (c + 2 < nch) issue(c + 2, (uint32_t)((c + 2) % 3) * WO_GB);
        CP_COMMIT();

        const uint32_t boff = (uint32_t)(c % 3) * WO_GB;
#pragma unroll
        for (int ks = 0; ks < 4; ++ks) {
            const uint32_t suboff = (uint32_t)((ks >> 1) * 8192);
            const int kc2 = (ks & 1) << 1;
            uint32_t ahi[4][4], bhi[2][4];
#pragma unroll
            for (int mt = 0; mt < 4; ++mt) {
                int r_ = wm0 + (mt << 4) + ar;
                int sw = (kc2 + ac) ^ ((r_ >> 1) & 3);
                ldsm4(ahi[mt], sbase + boff + WO_A + suboff + (uint32_t)(r_ * 64 + sw * 16));
            }
#pragma unroll
            for (int np = 0; np < 2; ++np) {
                int r_ = wn0 + (np << 4) + br;
                int sw = (kc2 + bc) ^ ((r_ >> 1) & 3);
                ldsm4(bhi[np], sbase + boff + WO_B + suboff + (uint32_t)(r_ * 64 + sw * 16));
            }
#pragma unroll
            for (int mt = 0; mt < 4; ++mt)
#pragma unroll
                for (int nt = 0; nt < 4; ++nt)
                    mma_f16(acc[mt][nt], ahi[mt], &bhi[nt >> 1][(nt & 1) << 1]);
        }
    }

    const int er = lane >> 2;
    const int ec = (lane & 3) << 1;
#pragma unroll
    for (int mt = 0; mt < 4; ++mt) {
#pragma unroll
        for (int nt = 0; nt < 4; ++nt) {
            int r0 = bm + wm0 + (mt << 4) + er;
            int c0 = bn + wn0 + (nt << 3) + ec;
            *(float2*)(C + (size_t)r0 * N + c0)       = make_float2(acc[mt][nt][0], acc[mt][nt][1]);
            *(float2*)(C + (size_t)(r0 + 8) * N + c0) = make_float2(acc[mt][nt][2], acc[mt][nt][3]);
        }
    }
}

// ---------------------------------------------------------------------------
// Per-block key means (8 tokens per block)
// ---------------------------------------------------------------------------
__global__ void kmean_kernel()
{
    int idx = blockIdx.x * blockDim.x + threadIdx.x;
    int d  = idx & 127;
    int hl = (idx >> 7) & 7;
    int t  = idx >> 10;
    const float* p = &g_qkv[(size_t)(t * 8) * NQKV + HQ * HD + hl * HD + d];
    float s = 0.f;
#pragma unroll
    for (int i = 0; i < 8; ++i) s += p[(size_t)i * NQKV];
    g_krep[idx] = s * 0.125f;
}

// ---------------------------------------------------------------------------
// Mean query per head — deterministic 2-stage
// ---------------------------------------------------------------------------
__global__ void qmean_part_kernel()
{
    int h = blockIdx.x, chunk = blockIdx.y, d = threadIdx.x;
    const float* p = &g_qkv[(size_t)(chunk * 256) * NQKV + h * HD + d];
    float s = 0.f;
#pragma unroll 4
    for (int i = 0; i < 256; ++i) s += p[(size_t)i * NQKV];
    g_qpart[chunk][h * HD + d] = s;
}

__global__ void qmean_final_kernel()
{
    int idx = blockIdx.x * blockDim.x + threadIdx.x;
    float s = 0.f;
#pragma unroll
    for (int i = 0; i < 16; ++i) s += g_qpart[i][idx];
    g_qmean[idx] = s * (1.f / 4096.f);
}

// ---------------------------------------------------------------------------
// Scores + top-k block selection. One block per head, 512 threads.
// Shuffle-based argmax. Tie-break = lower index (matches jax.lax.top_k).
// ---------------------------------------------------------------------------
__global__ void scores_topk_kernel()
{
    __shared__ float qm[HD];
    __shared__ float sc[TB];
    __shared__ float wv[16];
    __shared__ int   wi[16];

    const int h    = blockIdx.x;
    const int t    = threadIdx.x;
    const int lane = t & 31;
    const int wrp  = t >> 5;
    const int hl   = h >> 2;

    if (t < HD) qm[t] = g_qmean[h * HD + t];
    __syncthreads();

    float s = 0.f;
    const float* kr = &g_krep[(t * HKV + hl) * HD];
#pragma unroll 8
    for (int d = 0; d < HD; ++d) s += qm[d] * kr[d];
    s *= SCALE;

    bool masked = (t < SINKB) || (t >= WINST);
    sc[t] = masked ? NEGF : s;

    if (t < 4) {
        g_blk[h * KLBLK + t]     = t;
        g_blk[h * KLBLK + 4 + t] = WINST + t;
    }
    __syncthreads();

    for (int pick = 0; pick < MBTOP; ++pick) {
        float v = sc[t];
        int   i = t;
#pragma unroll
        for (int off = 16; off > 0; off >>= 1) {
            float v2 = __shfl_down_sync(0xffffffffu, v, off);
            int   i2 = __shfl_down_sync(0xffffffffu, i, off);
            if (v2 > v || (v2 == v && i2 < i)) { v = v2; i = i2; }
        }
        if (lane == 0) { wv[wrp] = v; wi[wrp] = i; }
        __syncthreads();
        if (t < 32) {
            float fv = (t < 16) ? wv[t] : -3e30f;
            int   fi = (t < 16) ? wi[t] : 0x7fffffff;
#pragma unroll
            for (int off = 8; off > 0; off >>= 1) {
                float v2 = __shfl_down_sync(0xffffffffu, fv, off);
                int   i2 = __shfl_down_sync(0xffffffffu, fi, off);
                if (v2 > fv || (v2 == fv && i2 < fi)) { fv = v2; fi = i2; }
            }
            if (t == 0) {
                g_blk[h * KLBLK + 8 + pick] = fi;
                sc[fi] = -2e30f;
            }
        }
        __syncthreads();
    }
}

// ---------------------------------------------------------------------------
// Tensor-core flash attention over 864 selected tokens per head.
// fp16: QK^T x3; P·V x2 (V_lo dropped). grid = (S/64, HQ), 128 threads.
// ---------------------------------------------------------------------------
#define ASTRIDE 272                 // smem row stride in bytes (136 fp16)
#define QH_OFF  0
#define QL_OFF  17408
#define KH_OFF  34816
#define KL_OFF  43520
#define VH_OFF  52224
#define TOK_OFF 60928
#define FLG_OFF 61056
#define SMEM_ATTN 61120

__global__ __launch_bounds__(128)
void attn_mma_kernel()
{
    extern __shared__ char smb[];
    const uint32_t sb = smem_to_u32(smb);
    int* toks = (int*)(smb + TOK_OFF);
    int* sflg = (int*)(smb + FLG_OFF);

    const int tid  = threadIdx.x;
    const int lane = tid & 31;
    const int wid  = tid >> 5;
    const int h    = blockIdx.y;
    const int q0   = blockIdx.x << 6;
    const int hl   = h >> 2;
    const int m0   = wid << 4;

    const int er = lane >> 2;
    const int ec = (lane & 3) << 1;

    // load Q tile rows q0..q0+63, head slice (hi+lo)
    {
        const size_t qcol = (size_t)h * HD;
        for (int t = tid; t < 1024; t += 128) {
            int r = t >> 4, ch = t & 15;
            uint32_t d = sb + (uint32_t)(r * ASTRIDE + ch * 16);
            const size_t src = (size_t)(q0 + r) * NQKV + qcol + ch * 8;
            CP16(d + QH_OFF, g_qh + src);
            CP16(d + QL_OFF, g_ql + src);
        }
    }
    CP_COMMIT();

    float oacc[16][4];
#pragma unroll
    for (int i = 0; i < 16; ++i)
#pragma unroll
        for (int j = 0; j < 4; ++j) oacc[i][j] = 0.f;
    float mrow0 = NEGF, mrow1 = NEGF, lrow0 = 0.f, lrow1 = 0.f;

    CP_WAIT(0);
    __syncthreads();

    for (int kt = 0; kt < KSEL / 32; ++kt) {
        if (tid < 32) {
            int j = kt * 32 + tid;
            int b = g_blk[h * KLBLK + (j >> 3)];
            toks[tid] = (b << 3) + (j & 7);
        }
        __syncthreads();
        if (tid == 0) {
            int mn = toks[0];
#pragma unroll
            for (int i = 1; i < 32; ++i) mn = min(mn, toks[i]);
            sflg[0] = (mn > q0 + 63);
        }
        __syncthreads();
        if (sflg[0]) continue;

        // gather K (hi+lo) and V (hi only) rows via cp.async
        {
            const size_t kcol = (size_t)HQ * HD + (size_t)hl * HD;
            for (int t = tid; t < 512; t += 128) {
                int r = t >> 4, ch = t & 15;
                size_t src = (size_t)toks[r] * NQKV + kcol + ch * 8;
                uint32_t d = sb + (uint32_t)(r * ASTRIDE + ch * 16);
                CP16(d + KH_OFF, g_qh + src);
                CP16(d + KL_OFF, g_ql + src);
                CP16(d + VH_OFF, g_qh + src + HKV * HD);
            }
        }
        CP_COMMIT(); CP_WAIT(0);
        __syncthreads();

        // ---- scores: S = Q @ K^T (64x32), fp16 x3 ----
        float sc[4][4];
#pragma unroll
        for (int i = 0; i < 4; ++i)
#pragma unroll
            for (int j = 0; j < 4; ++j) sc[i][j] = 0.f;

#pragma unroll
        for (int ks = 0; ks < 8; ++ks) {
            const int kc = ks << 4;
            uint32_t ah[4], al[4], kh0[4], kl0[4], kh1[4], kl1[4];
            uint32_t aoff = (uint32_t)((m0 + (lane & 15)) * ASTRIDE)
                          + (uint32_t)((kc + ((lane >> 4) << 3)) * 2);
            ldsm4(ah, sb + QH_OFF + aoff);
            ldsm4(al, sb + QL_OFF + aoff);
            uint32_t boff = (uint32_t)((((lane & 7) + (((lane >> 4) & 1) << 3)) * ASTRIDE))
                          + (uint32_t)((kc + (((lane >> 3) & 1) << 3)) * 2);
            ldsm4(kh0, sb + KH_OFF + boff);
            ldsm4(kl0, sb + KL_OFF + boff);
            ldsm4(kh1, sb + KH_OFF + boff + 16 * ASTRIDE);
            ldsm4(kl1, sb + KL_OFF + boff + 16 * ASTRIDE);
#pragma unroll
            for (int nt = 0; nt < 4; ++nt)
                mma_f16(sc[nt], ah, (nt < 2) ? &kh0[(nt & 1) << 1] : &kh1[(nt & 1) << 1]);
#pragma unroll
            for (int nt = 0; nt < 4; ++nt)
                mma_f16(sc[nt], ah, (nt < 2) ? &kl0[(nt & 1) << 1] : &kl1[(nt & 1) << 1]);
#pragma unroll
            for (int nt = 0; nt < 4; ++nt)
                mma_f16(sc[nt], al, (nt < 2) ? &kh0[(nt & 1) << 1] : &kh1[(nt & 1) << 1]);
        }

        // ---- scale + causal mask ----
        const int qr0 = q0 + m0 + er;
        const int qr1 = qr0 + 8;
#pragma unroll
        for (int nt = 0; nt < 4; ++nt) {
            int2 tt = *(int2*)&toks[(nt << 3) + ec];
            sc[nt][0] = (tt.x <= qr0) ? sc[nt][0] * SCALE : NEGF;
            sc[nt][1] = (tt.y <= qr0) ? sc[nt][1] * SCALE : NEGF;
            sc[nt][2] = (tt.x <= qr1) ? sc[nt][2] * SCALE : NEGF;
            sc[nt][3] = (tt.y <= qr1) ? sc[nt][3] * SCALE : NEGF;
        }

        // ---- online softmax on fragments (quad reductions) ----
        float mt0 = fmaxf(fmaxf(fmaxf(sc[0][0], sc[0][1]), fmaxf(sc[1][0], sc[1][1])),
                          fmaxf(fmaxf(sc[2][0], sc[2][1]), fmaxf(sc[3][0], sc[3][1])));
        float mt1 = fmaxf(fmaxf(fmaxf(sc[0][2], sc[0][3]), fmaxf(sc[1][2], sc[1][3])),
                          fmaxf(fmaxf(sc[2][2], sc[2][3]), fmaxf(sc[3][2], sc[3][3])));
        mt0 = fmaxf(mt0, __shfl_xor_sync(0xffffffffu, mt0, 1));
        mt0 = fmaxf(mt0, __shfl_xor_sync(0xffffffffu, mt0, 2));
        mt1 = fmaxf(mt1, __shfl_xor_sync(0xffffffffu, mt1, 1));
        mt1 = fmaxf(mt1, __shfl_xor_sync(0xffffffffu, mt1, 2));
        float mn0 = fmaxf(mrow0, mt0);
        float mn1 = fmaxf(mrow1, mt1);
        float cc0 = __expf(mrow0 - mn0);
        float cc1 = __expf(mrow1 - mn1);
        float ls0 = 0.f, ls1 = 0.f;
#pragma unroll
        for (int nt = 0; nt < 4; ++nt) {
            float p0 = (sc[nt][0] > -1e29f) ? __expf(sc[nt][0] - mn0) : 0.f;
            float p1 = (sc[nt][1] > -1e29f) ? __expf(sc[nt][1] - mn0) : 0.f;
            float p2 = (sc[nt][2] > -1e29f) ? __expf(sc[nt][2] - mn1) : 0.f;
            float p3 = (sc[nt][3] > -1e29f) ? __expf(sc[nt][3] - mn1) : 0.f;
            sc[nt][0] = p0; sc[nt][1] = p1; sc[nt][2] = p2; sc[nt][3] = p3;
            ls0 += p0 + p1; ls1 += p2 + p3;
        }
        ls0 += __shfl_xor_sync(0xffffffffu, ls0, 1);
        ls0 += __shfl_xor_sync(0xffffffffu, ls0, 2);
        ls1 += __shfl_xor_sync(0xffffffffu, ls1, 1);
        ls1 += __shfl_xor_sync(0xffffffffu, ls1, 2);
        lrow0 = lrow0 * cc0 + ls0;  mrow0 = mn0;
        lrow1 = lrow1 * cc1 + ls1;  mrow1 = mn1;

#pragma unroll
        for (int nt = 0; nt < 16; ++nt) {
            oacc[nt][0] *= cc0; oacc[nt][1] *= cc0;
            oacc[nt][2] *= cc1; oacc[nt][3] *= cc1;
        }

        // ---- pack P into A fragments (hi/lo, fp16) ----
        uint32_t ph[2][4], pl[2][4];
#pragma unroll
        for (int ks = 0; ks < 2; ++ks) {
#pragma unroll
            for (int hh = 0; hh < 2; ++hh) {
                int nt = (ks << 1) + hh;
                float p0 = sc[nt][0], p1 = sc[nt][1], p2 = sc[nt][2], p3 = sc[nt][3];
                uint32_t h01 = pack_f16(p0, p1);
                uint32_t h23 = pack_f16(p2, p3);
                ph[ks][(hh << 1) + 0] = h01;
                ph[ks][(hh << 1) + 1] = h23;
                __half2 b01 = *(__half2*)&h01;
                __half2 b23 = *(__half2*)&h23;
                pl[ks][(hh << 1) + 0] = pack_f16(p0 - __half2float(b01.x),
                                                 p1 - __half2float(b01.y));
                pl[ks][(hh << 1) + 1] = pack_f16(p2 - __half2float(b23.x),
                                                 p3 - __half2float(b23.y));
            }
        }

        // ---- O += P @ V (64x128), fp16 x2 (V-lo dropped) ----
#pragma unroll
        for (int ks = 0; ks < 2; ++ks) {
#pragma unroll
            for (int ng = 0; ng < 8; ++ng) {
                uint32_t vh[4];
                uint32_t voff = (uint32_t)(((ks << 4) + (lane & 15)) * ASTRIDE)
                              + (uint32_t)(((ng << 4) + ((lane >> 4) << 3)) * 2);
                ldsm4t(vh, sb + VH_OFF + voff);
                mma_f16(oacc[2 * ng],     ph[ks], &vh[0]);
                mma_f16(oacc[2 * ng + 1], ph[ks], &vh[2]);
                mma_f16(oacc[2 * ng],     pl[ks], &vh[0]);
                mma_f16(oacc[2 * ng + 1], pl[ks], &vh[2]);
            }
        }
        __syncthreads();   // protect K/V smem before next tile's cp.async
    }

    // ---- epilogue: normalize, store fp16 (hi only — WO GEMM is fp16 x1) ----
    const float inv0 = 1.f / lrow0;
    const float inv1 = 1.f / lrow1;
    const int row0 = q0 + m0 + er;
    const int row1 = row0 + 8;
#pragma unroll
    for (int nt = 0; nt < 16; ++nt) {
        int col = h * HD + (nt << 3) + ec;
        *(uint32_t*)&g_ath[(size_t)row0 * DIMM + col] =
            pack_f16(oacc[nt][0] * inv0, oacc[nt][1] * inv0);
        *(uint32_t*)&g_ath[(size_t)row1 * DIMM + col] =
            pack_f16(oacc[nt][2] * inv1, oacc[nt][3] * inv1);
    }
}

// ---------------------------------------------------------------------------
// Host launcher
// ---------------------------------------------------------------------------
extern "C" void kernel_launch(void* const* d_in, const int* in_sizes, int n_in,
                              void* d_out, int out_size)
{
    (void)in_sizes; (void)n_in; (void)out_size;
    const float* x    = (const float*)d_in[0];
    const float* fc   = (const float*)d_in[1];
    const float* wqkv = (const float*)d_in[2];
    const float* wo   = (const float*)d_in[3];
    float* y = (float*)d_out;

    float* qkv_p = nullptr;
    __half *xh, *xl, *wqh, *wql, *woh, *ath;
    cudaGetSymbolAddress((void**)&qkv_p, g_qkv);
    cudaGetSymbolAddress((void**)&xh,  g_xh);  cudaGetSymbolAddress((void**)&xl,  g_xl);
    cudaGetSymbolAddress((void**)&wqh, g_wqh); cudaGetSymbolAddress((void**)&wql, g_wql);
    cudaGetSymbolAddress((void**)&woh, g_woh);
    cudaGetSymbolAddress((void**)&ath, g_ath);

    cudaFuncSetAttribute(attn_mma_kernel, cudaFuncAttributeMaxDynamicSharedMemorySize, SMEM_ATTN);
    cudaFuncSetAttribute(gemm_qkv,  cudaFuncAttributeMaxDynamicSharedMemorySize, 3 * 4 * GTILE);
    cudaFuncSetAttribute(gemm_wo64, cudaFuncAttributeMaxDynamicSharedMemorySize, SMEM_WO);

    // 0. split GEMM inputs to fp16 (x, wqkv: hi+lo; wo: hi only)
    {
        int n4x = (S * DIMM) / 4;
        split_kernel<<<(n4x + 255) / 256, 256>>>(x, xh, xl, n4x);
        int n4q = (NQKV * DIMM) / 4;
        split_kernel<<<(n4q + 255) / 256, 256>>>(wqkv, wqh, wql, n4q);
        int n4o = (DIMM * DIMM) / 4;
        split_hi_kernel<<<(n4o + 255) / 256, 256>>>(wo, woh, n4o);
    }

    // 1. QKV projection (q/k: fp16 x3 — selection-exact; v: x2)
    gemm_qkv<<<dim3(NQKV / 128, S / 128), 256, 3 * 4 * GTILE>>>(
        xh, xl, wqh, wql, qkv_p, NQKV, DIMM);

    // 2. fused RoPE + fp16 hi/lo split of roped qkv
    {
        int n4 = (S * NQKV) / 4;
        rope_split_kernel<<<(n4 + 255) / 256, 256>>>(fc);
    }

    // 3. per-block key means + query mean
    kmean_kernel<<<(TB * HKV * HD) / 256, 256>>>();
    qmean_part_kernel<<<dim3(HQ, 16), 128>>>();
    qmean_final_kernel<<<(HQ * HD) / 128, 128>>>();

    // 4. scores + top-k block selection (shuffle-based argmax)
    scores_topk_kernel<<<HQ, TB>>>();

    // 5. tensor-core sparse causal attention (QK x3, PV x2)
    attn_mma_kernel<<<dim3(S / 64, HQ), 128, SMEM_ATTN>>>();

    // 6. output projection (fp16 x1, BK=64 — final op, error unamplified ~4e-4)
    gemm_wo64<<<dim3(DIMM / 128, S / 128), 256, SMEM_WO>>>(
        ath, woh, y, DIMM, DIMM);
}

// round 16
// speedup vs baseline: 1.2108x; 1.0316x over previous
#include <cuda_runtime.h>
#include <cuda_fp16.h>
#include <cstdint>

// ---------------------------------------------------------------------------
// Problem constants (fixed shapes)
// ---------------------------------------------------------------------------
#define S      4096
#define DIMM   4096
#define HQ     32
#define HKV    8
#define HD     128
#define NQKV   6144          // (HQ + 2*HKV) * HD
#define TB     512           // S / 8 blocks
#define SINKB  4             // ceil(30/8)
#define WINST  508           // window start block
#define MBTOP  100           // heavy blocks
#define KLBLK  108           // 4 sink + 4 window + 100 heavy
#define KSEL   (KLBLK * 8)   // 864 selected tokens per head
#define NEGF   (-1e30f)
#define SCALE  0.08838834764831845f   // 1/sqrt(128)
#define VCOL0  ((HQ + HKV) * HD)      // 5120 — first v column

// ---------------------------------------------------------------------------
// Scratch (static device globals — no runtime allocation allowed)
// ---------------------------------------------------------------------------
__device__ float g_qkv[(size_t)S * NQKV];     // qkv projections (fp32, roped in place)
__device__ float g_krep[TB * HKV * HD];       // per-block mean keys
__device__ float g_qmean[HQ * HD];            // mean query per head
__device__ float g_qpart[16][HQ * HD];        // partial q sums (deterministic 2-stage)
__device__ int   g_blk[HQ * KLBLK];           // selected block ids per head

// fp16 hi/lo split operands
__device__ __align__(16) __half g_xh[(size_t)S * DIMM];
__device__ __align__(16) __half g_xl[(size_t)S * DIMM];
__device__ __align__(16) __half g_wqh[(size_t)NQKV * DIMM];
__device__ __align__(16) __half g_wql[(size_t)NQKV * DIMM];
__device__ __align__(16) __half g_woh[(size_t)DIMM * DIMM];   // hi only (WO is fp16 x1)
__device__ __align__(16) __half g_ath[(size_t)S * DIMM];      // attention out (hi only)
__device__ __align__(16) __half g_qh[(size_t)S * NQKV];       // roped qkv hi
__device__ __align__(16) __half g_ql[(size_t)S * NQKV];       // roped qkv lo

// ---------------------------------------------------------------------------
// asm helpers (base-ISA only; no tcgen05 on this toolchain)
// ---------------------------------------------------------------------------
__device__ __forceinline__ uint32_t smem_to_u32(const void* smem_ptr) {
    uint32_t addr;
    asm("{ .reg .u64 tmp; cvta.to.shared.u64 tmp, %1; cvt.u32.u64 %0, tmp; }"
        : "=r"(addr) : "l"(smem_ptr));
    return addr;
}

__device__ __forceinline__ void ldsm4(uint32_t* r, uint32_t addr) {
    asm volatile("ldmatrix.sync.aligned.m8n8.x4.shared.b16 {%0,%1,%2,%3}, [%4];"
        : "=r"(r[0]), "=r"(r[1]), "=r"(r[2]), "=r"(r[3]) : "r"(addr));
}

__device__ __forceinline__ void ldsm4t(uint32_t* r, uint32_t addr) {
    asm volatile("ldmatrix.sync.aligned.m8n8.x4.trans.shared.b16 {%0,%1,%2,%3}, [%4];"
        : "=r"(r[0]), "=r"(r[1]), "=r"(r[2]), "=r"(r[3]) : "r"(addr));
}

__device__ __forceinline__ void mma_f16(float* d, const uint32_t* a, const uint32_t* b) {
    asm volatile("mma.sync.aligned.m16n8k16.row.col.f32.f16.f16.f32 "
        "{%0,%1,%2,%3}, {%4,%5,%6,%7}, {%8,%9}, {%0,%1,%2,%3};"
        : "+f"(d[0]), "+f"(d[1]), "+f"(d[2]), "+f"(d[3])
        : "r"(a[0]), "r"(a[1]), "r"(a[2]), "r"(a[3]), "r"(b[0]), "r"(b[1]));
}

#define CP16(dst, src) \
    asm volatile("cp.async.cg.shared.global [%0], [%1], 16;" :: "r"(dst), "l"(src))
#define CP_COMMIT() asm volatile("cp.async.commit_group;" ::: "memory")
#define CP_WAIT(n)  asm volatile("cp.async.wait_group %0;" :: "n"(n) : "memory")

__device__ __forceinline__ uint32_t pack_f16(float a, float b) {
    __half2 h = __floats2half2_rn(a, b);
    return *(uint32_t*)&h;
}

// ---------------------------------------------------------------------------
// fp32 -> fp16 hi/lo split (pre-pass), float4 per thread
// ---------------------------------------------------------------------------
__global__ void split_kernel(const float* __restrict__ in,
                             __half* __restrict__ hi,
                             __half* __restrict__ lo, int n4)
{
    int i = blockIdx.x * blockDim.x + threadIdx.x;
    if (i >= n4) return;
    float4 v = ((const float4*)in)[i];
    __half h0 = __float2half_rn(v.x);
    __half h1 = __float2half_rn(v.y);
    __half h2 = __float2half_rn(v.z);
    __half h3 = __float2half_rn(v.w);
    __half l0 = __float2half_rn(v.x - __half2float(h0));
    __half l1 = __float2half_rn(v.y - __half2float(h1));
    __half l2 = __float2half_rn(v.z - __half2float(h2));
    __half l3 = __float2half_rn(v.w - __half2float(h3));
    uint2 H, L;
    H.x = ((uint32_t)__half_as_ushort(h1) << 16) | __half_as_ushort(h0);
    H.y = ((uint32_t)__half_as_ushort(h3) << 16) | __half_as_ushort(h2);
    L.x = ((uint32_t)__half_as_ushort(l1) << 16) | __half_as_ushort(l0);
    L.y = ((uint32_t)__half_as_ushort(l3) << 16) | __half_as_ushort(l2);
    ((uint2*)hi)[i] = H;
    ((uint2*)lo)[i] = L;
}

// hi-only variant (for wo weights — WO GEMM runs fp16 x1)
__global__ void split_hi_kernel(const float* __restrict__ in,
                                __half* __restrict__ hi, int n4)
{
    int i = blockIdx.x * blockDim.x + threadIdx.x;
    if (i >= n4) return;
    float4 v = ((const float4*)in)[i];
    uint2 H;
    H.x = pack_f16(v.x, v.y);
    H.y = pack_f16(v.z, v.w);
    ((uint2*)hi)[i] = H;
}

// ---------------------------------------------------------------------------
// Fused RoPE + fp16 hi/lo split of the roped qkv tensor.
// ---------------------------------------------------------------------------
__global__ void rope_split_kernel(const float* __restrict__ fc)
{
    const int n4 = (S * NQKV) / 4;
    int i = blockIdx.x * blockDim.x + threadIdx.x;
    if (i >= n4) return;
    int col4 = i % (NQKV / 4);
    int s    = i / (NQKV / 4);
    int c    = col4 << 2;
    int hh   = c >> 7;             // head index 0..47
    float4 v = *(float4*)&g_qkv[(size_t)s * NQKV + c];
    if (hh < 40) {                 // q (0..31) and k (32..39) get rope
        float4 f = *(const float4*)&fc[s * HD + (c & 127)];
        float x0 = v.x, x1 = v.y, x2 = v.z, x3 = v.w;
        v.x = x0 * f.x - x1 * f.y;
        v.y = x1 * f.x + x0 * f.y;
        v.z = x2 * f.z - x3 * f.w;
        v.w = x3 * f.z + x2 * f.w;
        *(float4*)&g_qkv[(size_t)s * NQKV + c] = v;
    }
    __half h0 = __float2half_rn(v.x);
    __half h1 = __float2half_rn(v.y);
    __half h2 = __float2half_rn(v.z);
    __half h3 = __float2half_rn(v.w);
    __half l0 = __float2half_rn(v.x - __half2float(h0));
    __half l1 = __float2half_rn(v.y - __half2float(h1));
    __half l2 = __float2half_rn(v.z - __half2float(h2));
    __half l3 = __float2half_rn(v.w - __half2float(h3));
    uint2 H, L;
    H.x = ((uint32_t)__half_as_ushort(h1) << 16) | __half_as_ushort(h0);
    H.y = ((uint32_t)__half_as_ushort(h3) << 16) | __half_as_ushort(h2);
    L.x = ((uint32_t)__half_as_ushort(l1) << 16) | __half_as_ushort(l0);
    L.y = ((uint32_t)__half_as_ushort(l3) << 16) | __half_as_ushort(l2);
    size_t base = (size_t)s * NQKV + c;
    *(uint2*)&g_qh[base] = H;
    *(uint2*)&g_ql[base] = L;
}

// ---------------------------------------------------------------------------
// QKV tensor-core GEMM: C = A @ B^T, fp16, fp32 acc.
// q/k column tiles (bn < 5120): x3 (selection-exact). v tiles: x2.
// 128x128 tile, BK=32, 256 threads, swizzled smem, 3-stage pipeline, 2 CTAs/SM.
// ---------------------------------------------------------------------------
#define GTILE 8192                      // 128 rows x 64 bytes per variant

__global__ __launch_bounds__(256, 2)
void gemm_qkv(const __half* __restrict__ Ah, const __half* __restrict__ Al,
              const __half* __restrict__ Bh, const __half* __restrict__ Bl,
              float* __restrict__ C, int N, int K)
{
    constexpr uint32_t AHI = 0;
    constexpr uint32_t ALO = GTILE;
    constexpr uint32_t BHI = 2 * GTILE;
    constexpr uint32_t BLO = 3 * GTILE;
    constexpr uint32_t GB  = 4 * GTILE;

    extern __shared__ char smc[];
    const uint32_t sbase = smem_to_u32(smc);
    const int tid  = threadIdx.x;
    const int lane = tid & 31;
    const int wid  = tid >> 5;
    const int wm0  = (wid >> 2) << 6;
    const int wn0  = (wid & 3) << 5;
    const int bm   = blockIdx.y << 7;
    const int bn   = blockIdx.x << 7;
    const bool vblk = (bn >= VCOL0);    // v-head tile: skip B_lo entirely

    float acc[4][4][4];
#pragma unroll
    for (int i = 0; i < 4; ++i)
#pragma unroll
        for (int j = 0; j < 4; ++j)
#pragma unroll
            for (int q = 0; q < 4; ++q) acc[i][j][q] = 0.f;

    const int nch = K >> 5;

    auto issue = [&](int cc, uint32_t boff) {
        const int kb = cc << 5;
#pragma unroll
        for (int i2 = 0; i2 < 2; ++i2) {
            int u   = tid + (i2 << 8);
            int row = u >> 2;
            int k   = u & 3;
            int sw  = k ^ ((row >> 1) & 3);
            uint32_t d = sbase + boff + (uint32_t)(row * 64 + sw * 16);
            const int ge = kb + (k << 3);
            CP16(d + AHI, Ah + (size_t)(bm + row) * K + ge);
            CP16(d + BHI, Bh + (size_t)(bn + row) * K + ge);
            CP16(d + ALO, Al + (size_t)(bm + row) * K + ge);
            if (!vblk) CP16(d + BLO, Bl + (size_t)(bn + row) * K + ge);
        }
    };

    const int ar = lane & 15;
    const int ac = lane >> 4;
    const int br = (lane & 7) + (((lane >> 4) & 1) << 3);
    const int bc = (lane >> 3) & 1;

    issue(0, 0u);   CP_COMMIT();
    issue(1, GB);   CP_COMMIT();

    for (int c = 0; c < nch; ++c) {
        CP_WAIT(1);
        __syncthreads();

        if (c + 2 < nch) issue(c + 2, (uint32_t)((c + 2) % 3) * GB);
        CP_COMMIT();

        const uint32_t boff = (uint32_t)(c % 3) * GB;
#pragma unroll
        for (int ks = 0; ks < 2; ++ks) {
            uint32_t ahi[4][4], alo[4][4], bhi[2][4], blo[2][4];
            const int kc2 = ks << 1;
#pragma unroll
            for (int mt = 0; mt < 4; ++mt) {
                int r_ = wm0 + (mt << 4) + ar;
                int sw = (kc2 + ac) ^ ((r_ >> 1) & 3);
                uint32_t off = (uint32_t)(r_ * 64 + sw * 16);
                ldsm4(ahi[mt], sbase + boff + AHI + off);
                ldsm4(alo[mt], sbase + boff + ALO + off);
            }
#pragma unroll
            for (int np = 0; np < 2; ++np) {
                int r_ = wn0 + (np << 4) + br;
                int sw = (kc2 + bc) ^ ((r_ >> 1) & 3);
                uint32_t off = (uint32_t)(r_ * 64 + sw * 16);
                ldsm4(bhi[np], sbase + boff + BHI + off);
                if (!vblk) ldsm4(blo[np], sbase + boff + BLO + off);
            }
            // pass 1: hi*hi
#pragma unroll
            for (int mt = 0; mt < 4; ++mt)
#pragma unroll
                for (int nt = 0; nt < 4; ++nt)
                    mma_f16(acc[mt][nt], ahi[mt], &bhi[nt >> 1][(nt & 1) << 1]);
            // pass 2: hi*lo (skipped on v tiles)
            if (!vblk) {
#pragma unroll
                for (int mt = 0; mt < 4; ++mt)
#pragma unroll
                    for (int nt = 0; nt < 4; ++nt)
                        mma_f16(acc[mt][nt], ahi[mt], &blo[nt >> 1][(nt & 1) << 1]);
            }
            // pass 3: lo*hi
#pragma unroll
            for (int mt = 0; mt < 4; ++mt)
#pragma unroll
                for (int nt = 0; nt < 4; ++nt)
                    mma_f16(acc[mt][nt], alo[mt], &bhi[nt >> 1][(nt & 1) << 1]);
        }
    }

    const int er = lane >> 2;
    const int ec = (lane & 3) << 1;
#pragma unroll
    for (int mt = 0; mt < 4; ++mt) {
#pragma unroll
        for (int nt = 0; nt < 4; ++nt) {
            int r0 = bm + wm0 + (mt << 4) + er;
            int c0 = bn + wn0 + (nt << 3) + ec;
            *(float2*)(C + (size_t)r0 * N + c0)       = make_float2(acc[mt][nt][0], acc[mt][nt][1]);
            *(float2*)(C + (size_t)(r0 + 8) * N + c0) = make_float2(acc[mt][nt][2], acc[mt][nt][3]);
        }
    }
}

// ---------------------------------------------------------------------------
// WO tensor-core GEMM: C = Ah @ Bh^T, fp16 x1, fp32 acc, BK=64.
// ---------------------------------------------------------------------------
#define WO_A 0
#define WO_B 16384
#define WO_GB 32768
#define SMEM_WO (3 * WO_GB)            // 98304

__global__ __launch_bounds__(256, 2)
void gemm_wo64(const __half* __restrict__ Ah, const __half* __restrict__ Bh,
               float* __restrict__ C, int N, int K)
{
    extern __shared__ char smc[];
    const uint32_t sbase = smem_to_u32(smc);
    const int tid  = threadIdx.x;
    const int lane = tid & 31;
    const int wid  = tid >> 5;
    const int wm0  = (wid >> 2) << 6;
    const int wn0  = (wid & 3) << 5;
    const int bm   = blockIdx.y << 7;
    const int bn   = blockIdx.x << 7;

    float acc[4][4][4];
#pragma unroll
    for (int i = 0; i < 4; ++i)
#pragma unroll
        for (int j = 0; j < 4; ++j)
#pragma unroll
            for (int q = 0; q < 4; ++q) acc[i][j][q] = 0.f;

    const int nch = K >> 6;            // 64-wide chunks

    auto issue = [&](int cc, uint32_t boff) {
        const int kb = cc << 6;
#pragma unroll
        for (int i2 = 0; i2 < 4; ++i2) {
            int u   = tid + (i2 << 8);      // 0..1023
            int row = u >> 3;
            int k   = u & 7;
            int sub = k >> 2;
            int sw  = (k & 3) ^ ((row >> 1) & 3);
            uint32_t d = sbase + boff + (uint32_t)(sub * 8192 + row * 64 + sw * 16);
            const int ge = kb + (k << 3);
            CP16(d + WO_A, Ah + (size_t)(bm + row) * K + ge);
            CP16(d + WO_B, Bh + (size_t)(bn + row) * K + ge);
        }
    };

    const int ar = lane & 15;
    const int ac = lane >> 4;
    const int br = (lane & 7) + (((lane >> 4) & 1) << 3);
    const int bc = (lane >> 3) & 1;

    issue(0, 0u);       CP_COMMIT();
    issue(1, WO_GB);    CP_COMMIT();

    for (int c = 0; c < nch; ++c) {
        CP_WAIT(1);
        __syncthreads();

        if (c + 2 < nch) issue(c + 2, (uint32_t)((c + 2) % 3) * WO_GB);
        CP_COMMIT();

        const uint32_t boff = (uint32_t)(c % 3) * WO_GB;
#pragma unroll
        for (int ks = 0; ks < 4; ++ks) {
            const uint32_t suboff = (uint32_t)((ks >> 1) * 8192);
            const int kc2 = (ks & 1) << 1;
            uint32_t ahi[4][4], bhi[2][4];
#pragma unroll
            for (int mt = 0; mt < 4; ++mt) {
                int r_ = wm0 + (mt << 4) + ar;
                int sw = (kc2 + ac) ^ ((r_ >> 1) & 3);
                ldsm4(ahi[mt], sbase + boff + WO_A + suboff + (uint32_t)(r_ * 64 + sw * 16));
            }
#pragma unroll
            for (int np = 0; np < 2; ++np) {
                int r_ = wn0 + (np << 4) + br;
                int sw = (kc2 + bc) ^ ((r_ >> 1) & 3);
                ldsm4(bhi[np], sbase + boff + WO_B + suboff + (uint32_t)(r_ * 64 + sw * 16));
            }
#pragma unroll
            for (int mt = 0; mt < 4; ++mt)
#pragma unroll
                for (int nt = 0; nt < 4; ++nt)
                    mma_f16(acc[mt][nt], ahi[mt], &bhi[nt >> 1][(nt & 1) << 1]);
        }
    }

    const int er = lane >> 2;
    const int ec = (lane & 3) << 1;
#pragma unroll
    for (int mt = 0; mt < 4; ++mt) {
#pragma unroll
        for (int nt = 0; nt < 4; ++nt) {
            int r0 = bm + wm0 + (mt << 4) + er;
            int c0 = bn + wn0 + (nt << 3) + ec;
            *(float2*)(C + (size_t)r0 * N + c0)       = make_float2(acc[mt][nt][0], acc[mt][nt][1]);
            *(float2*)(C + (size_t)(r0 + 8) * N + c0) = make_float2(acc[mt][nt][2], acc[mt][nt][3]);
        }
    }
}

// ---------------------------------------------------------------------------
// Per-block key means (8 tokens per block)
// ---------------------------------------------------------------------------
__global__ void kmean_kernel()
{
    int idx = blockIdx.x * blockDim.x + threadIdx.x;
    int d  = idx & 127;
    int hl = (idx >> 7) & 7;
    int t  = idx >> 10;
    const float* p = &g_qkv[(size_t)(t * 8) * NQKV + HQ * HD + hl * HD + d];
    float s = 0.f;
#pragma unroll
    for (int i = 0; i < 8; ++i) s += p[(size_t)i * NQKV];
    g_krep[idx] = s * 0.125f;
}

// ---------------------------------------------------------------------------
// Mean query per head — deterministic 2-stage
// ---------------------------------------------------------------------------
__global__ void qmean_part_kernel()
{
    int h = blockIdx.x, chunk = blockIdx.y, d = threadIdx.x;
    const float* p = &g_qkv[(size_t)(chunk * 256) * NQKV + h * HD + d];
    float s = 0.f;
#pragma unroll 4
    for (int i = 0; i < 256; ++i) s += p[(size_t)i * NQKV];
    g_qpart[chunk][h * HD + d] = s;
}

__global__ void qmean_final_kernel()
{
    int idx = blockIdx.x * blockDim.x + threadIdx.x;
    float s = 0.f;
#pragma unroll
    for (int i = 0; i < 16; ++i) s += g_qpart[i][idx];
    g_qmean[idx] = s * (1.f / 4096.f);
}

// ---------------------------------------------------------------------------
// Scores + top-k block selection. One block per head, 512 threads.
// Shuffle-based argmax. Tie-break = lower index (matches jax.lax.top_k).
// ---------------------------------------------------------------------------
__global__ void scores_topk_kernel()
{
    __shared__ float qm[HD];
    __shared__ float sc[TB];
    __shared__ float wv[16];
    __shared__ int   wi[16];

    const int h    = blockIdx.x;
    const int t    = threadIdx.x;
    const int lane = t & 31;
    const int wrp  = t >> 5;
    const int hl   = h >> 2;

    if (t < HD) qm[t] = g_qmean[h * HD + t];
    __syncthreads();

    float s = 0.f;
    const float* kr = &g_krep[(t * HKV + hl) * HD];
#pragma unroll 8
    for (int d = 0; d < HD; ++d) s += qm[d] * kr[d];
    s *= SCALE;

    bool masked = (t < SINKB) || (t >= WINST);
    sc[t] = masked ? NEGF : s;

    if (t < 4) {
        g_blk[h * KLBLK + t]     = t;
        g_blk[h * KLBLK + 4 + t] = WINST + t;
    }
    __syncthreads();

    for (int pick = 0; pick < MBTOP; ++pick) {
        float v = sc[t];
        int   i = t;
#pragma unroll
        for (int off = 16; off > 0; off >>= 1) {
            float v2 = __shfl_down_sync(0xffffffffu, v, off);
            int   i2 = __shfl_down_sync(0xffffffffu, i, off);
            if (v2 > v || (v2 == v && i2 < i)) { v = v2; i = i2; }
        }
        if (lane == 0) { wv[wrp] = v; wi[wrp] = i; }
        __syncthreads();
        if (t < 32) {
            float fv = (t < 16) ? wv[t] : -3e30f;
            int   fi = (t < 16) ? wi[t] : 0x7fffffff;
#pragma unroll
            for (int off = 8; off > 0; off >>= 1) {
                float v2 = __shfl_down_sync(0xffffffffu, fv, off);
                int   i2 = __shfl_down_sync(0xffffffffu, fi, off);
                if (v2 > fv || (v2 == fv && i2 < fi)) { fv = v2; fi = i2; }
            }
            if (t == 0) {
                g_blk[h * KLBLK + 8 + pick] = fi;
                sc[fi] = -2e30f;
            }
        }
        __syncthreads();
    }
}

// ---------------------------------------------------------------------------
// Tensor-core flash attention over 864 selected tokens per head.
// fp16: QK^T x2 ((Qh+Ql)·Kh — K_lo dropped, smooth path, err ~2.3e-4 on s);
// P·V x2 (V_lo dropped). grid = (S/64, HQ), 128 threads (4 warps x 16 q-rows).
// ---------------------------------------------------------------------------
#define ASTRIDE 272                 // smem row stride in bytes (136 fp16)
#define QH_OFF  0
#define QL_OFF  17408
#define KH_OFF  34816
#define VH_OFF  43520
#define TOK_OFF 52224
#define FLG_OFF 52352
#define SMEM_ATTN 52416

__global__ __launch_bounds__(128)
void attn_mma_kernel()
{
    extern __shared__ char smb[];
    const uint32_t sb = smem_to_u32(smb);
    int* toks = (int*)(smb + TOK_OFF);
    int* sflg = (int*)(smb + FLG_OFF);

    const int tid  = threadIdx.x;
    const int lane = tid & 31;
    const int wid  = tid >> 5;
    const int h    = blockIdx.y;
    const int q0   = blockIdx.x << 6;
    const int hl   = h >> 2;
    const int m0   = wid << 4;

    const int er = lane >> 2;
    const int ec = (lane & 3) << 1;

    // load Q tile rows q0..q0+63, head slice (hi+lo)
    {
        const size_t qcol = (size_t)h * HD;
        for (int t = tid; t < 1024; t += 128) {
            int r = t >> 4, ch = t & 15;
            uint32_t d = sb + (uint32_t)(r * ASTRIDE + ch * 16);
            const size_t src = (size_t)(q0 + r) * NQKV + qcol + ch * 8;
            CP16(d + QH_OFF, g_qh + src);
            CP16(d + QL_OFF, g_ql + src);
        }
    }
    CP_COMMIT();

    float oacc[16][4];
#pragma unroll
    for (int i = 0; i < 16; ++i)
#pragma unroll
        for (int j = 0; j < 4; ++j) oacc[i][j] = 0.f;
    float mrow0 = NEGF, mrow1 = NEGF, lrow0 = 0.f, lrow1 = 0.f;

    CP_WAIT(0);
    __syncthreads();

    for (int kt = 0; kt < KSEL / 32; ++kt) {
        if (tid < 32) {
            int j = kt * 32 + tid;
            int b = g_blk[h * KLBLK + (j >> 3)];
            toks[tid] = (b << 3) + (j & 7);
        }
        __syncthreads();
        if (tid == 0) {
            int mn = toks[0];
#pragma unroll
            for (int i = 1; i < 32; ++i) mn = min(mn, toks[i]);
            sflg[0] = (mn > q0 + 63);
        }
        __syncthreads();
        if (sflg[0]) continue;

        // gather K (hi) and V (hi) rows via cp.async — K_lo/V_lo not needed
        {
            const size_t kcol = (size_t)HQ * HD + (size_t)hl * HD;
            for (int t = tid; t < 512; t += 128) {
                int r = t >> 4, ch = t & 15;
                size_t src = (size_t)toks[r] * NQKV + kcol + ch * 8;
                uint32_t d = sb + (uint32_t)(r * ASTRIDE + ch * 16);
                CP16(d + KH_OFF, g_qh + src);
                CP16(d + VH_OFF, g_qh + src + HKV * HD);
            }
        }
        CP_COMMIT(); CP_WAIT(0);
        __syncthreads();

        // ---- scores: S = (Qh+Ql) @ Kh^T (64x32), fp16 x2 ----
        float sc[4][4];
#pragma unroll
        for (int i = 0; i < 4; ++i)
#pragma unroll
            for (int j = 0; j < 4; ++j) sc[i][j] = 0.f;

#pragma unroll
        for (int ks = 0; ks < 8; ++ks) {
            const int kc = ks << 4;
            uint32_t ah[4], al[4], kh0[4], kh1[4];
            uint32_t aoff = (uint32_t)((m0 + (lane & 15)) * ASTRIDE)
                          + (uint32_t)((kc + ((lane >> 4) << 3)) * 2);
            ldsm4(ah, sb + QH_OFF + aoff);
            ldsm4(al, sb + QL_OFF + aoff);
            uint32_t boff = (uint32_t)((((lane & 7) + (((lane >> 4) & 1) << 3)) * ASTRIDE))
                          + (uint32_t)((kc + (((lane >> 3) & 1) << 3)) * 2);
            ldsm4(kh0, sb + KH_OFF + boff);
            ldsm4(kh1, sb + KH_OFF + boff + 16 * ASTRIDE);
#pragma unroll
            for (int nt = 0; nt < 4; ++nt)
                mma_f16(sc[nt], ah, (nt < 2) ? &kh0[(nt & 1) << 1] : &kh1[(nt & 1) << 1]);
#pragma unroll
            for (int nt = 0; nt < 4; ++nt)
                mma_f16(sc[nt], al, (nt < 2) ? &kh0[(nt & 1) << 1] : &kh1[(nt & 1) << 1]);
        }

        // ---- scale + causal mask ----
        const int qr0 = q0 + m0 + er;
        const int qr1 = qr0 + 8;
#pragma unroll
        for (int nt = 0; nt < 4; ++nt) {
            int2 tt = *(int2*)&toks[(nt << 3) + ec];
            sc[nt][0] = (tt.x <= qr0) ? sc[nt][0] * SCALE : NEGF;
            sc[nt][1] = (tt.y <= qr0) ? sc[nt][1] * SCALE : NEGF;
            sc[nt][2] = (tt.x <= qr1) ? sc[nt][2] * SCALE : NEGF;
            sc[nt][3] = (tt.y <= qr1) ? sc[nt][3] * SCALE : NEGF;
        }

        // ---- online softmax on fragments (quad reductions) ----
        float mt0 = fmaxf(fmaxf(fmaxf(sc[0][0], sc[0][1]), fmaxf(sc[1][0], sc[1][1])),
                          fmaxf(fmaxf(sc[2][0], sc[2][1]), fmaxf(sc[3][0], sc[3][1])));
        float mt1 = fmaxf(fmaxf(fmaxf(sc[0][2], sc[0][3]), fmaxf(sc[1][2], sc[1][3])),
                          fmaxf(fmaxf(sc[2][2], sc[2][3]), fmaxf(sc[3][2], sc[3][3])));
        mt0 = fmaxf(mt0, __shfl_xor_sync(0xffffffffu, mt0, 1));
        mt0 = fmaxf(mt0, __shfl_xor_sync(0xffffffffu, mt0, 2));
        mt1 = fmaxf(mt1, __shfl_xor_sync(0xffffffffu, mt1, 1));
        mt1 = fmaxf(mt1, __shfl_xor_sync(0xffffffffu, mt1, 2));
        float mn0 = fmaxf(mrow0, mt0);
        float mn1 = fmaxf(mrow1, mt1);
        float cc0 = __expf(mrow0 - mn0);
        float cc1 = __expf(mrow1 - mn1);
        float ls0 = 0.f, ls1 = 0.f;
#pragma unroll
        for (int nt = 0; nt < 4; ++nt) {
            float p0 = (sc[nt][0] > -1e29f) ? __expf(sc[nt][0] - mn0) : 0.f;
            float p1 = (sc[nt][1] > -1e29f) ? __expf(sc[nt][1] - mn0) : 0.f;
            float p2 = (sc[nt][2] > -1e29f) ? __expf(sc[nt][2] - mn1) : 0.f;
            float p3 = (sc[nt][3] > -1e29f) ? __expf(sc[nt][3] - mn1) : 0.f;
            sc[nt][0] = p0; sc[nt][1] = p1; sc[nt][2] = p2; sc[nt][3] = p3;
            ls0 += p0 + p1; ls1 += p2 + p3;
        }
        ls0 += __shfl_xor_sync(0xffffffffu, ls0, 1);
        ls0 += __shfl_xor_sync(0xffffffffu, ls0, 2);
        ls1 += __shfl_xor_sync(0xffffffffu, ls1, 1);
        ls1 += __shfl_xor_sync(0xffffffffu, ls1, 2);
        lrow0 = lrow0 * cc0 + ls0;  mrow0 = mn0;
        lrow1 = lrow1 * cc1 + ls1;  mrow1 = mn1;

#pragma unroll
        for (int nt = 0; nt < 16; ++nt) {
            oacc[nt][0] *= cc0; oacc[nt][1] *= cc0;
            oacc[nt][2] *= cc1; oacc[nt][3] *= cc1;
        }

        // ---- pack P into A fragments (hi/lo, fp16) ----
        uint32_t ph[2][4], pl[2][4];
#pragma unroll
        for (int ks = 0; ks < 2; ++ks) {
#pragma unroll
            for (int hh = 0; hh < 2; ++hh) {
                int nt = (ks << 1) + hh;
                float p0 = sc[nt][0], p1 = sc[nt][1], p2 = sc[nt][2], p3 = sc[nt][3];
                uint32_t h01 = pack_f16(p0, p1);
                uint32_t h23 = pack_f16(p2, p3);
                ph[ks][(hh << 1) + 0] = h01;
                ph[ks][(hh << 1) + 1] = h23;
                __half2 b01 = *(__half2*)&h01;
                __half2 b23 = *(__half2*)&h23;
                pl[ks][(hh << 1) + 0] = pack_f16(p0 - __half2float(b01.x),
                                                 p1 - __half2float(b01.y));
                pl[ks][(hh << 1) + 1] = pack_f16(p2 - __half2float(b23.x),
                                                 p3 - __half2float(b23.y));
            }
        }

        // ---- O += P @ V (64x128), fp16 x2 (V-lo dropped) ----
#pragma unroll
        for (int ks = 0; ks < 2; ++ks) {
#pragma unroll
            for (int ng = 0; ng < 8; ++ng) {
                uint32_t vh[4];
                uint32_t voff = (uint32_t)(((ks << 4) + (lane & 15)) * ASTRIDE)
                              + (uint32_t)(((ng << 4) + ((lane >> 4) << 3)) * 2);
                ldsm4t(vh, sb + VH_OFF + voff);
                mma_f16(oacc[2 * ng],     ph[ks], &vh[0]);
                mma_f16(oacc[2 * ng + 1], ph[ks], &vh[2]);
                mma_f16(oacc[2 * ng],     pl[ks], &vh[0]);
                mma_f16(oacc[2 * ng + 1], pl[ks], &vh[2]);
            }
        }
        __syncthreads();   // protect K/V smem before next tile's cp.async
    }

    // ---- epilogue: normalize, store fp16 (hi only — WO GEMM is fp16 x1) ----
    const float inv0 = 1.f / lrow0;
    const float inv1 = 1.f / lrow1;
    const int row0 = q0 + m0 + er;
    const int row1 = row0 + 8;
#pragma unroll
    for (int nt = 0; nt < 16; ++nt) {
        int col = h * HD + (nt << 3) + ec;
        *(uint32_t*)&g_ath[(size_t)row0 * DIMM + col] =
            pack_f16(oacc[nt][0] * inv0, oacc[nt][1] * inv0);
        *(uint32_t*)&g_ath[(size_t)row1 * DIMM + col] =
            pack_f16(oacc[nt][2] * inv1, oacc[nt][3] * inv1);
    }
}

// ---------------------------------------------------------------------------
// Host launcher
// ---------------------------------------------------------------------------
extern "C" void kernel_launch(void* const* d_in, const int* in_sizes, int n_in,
                              void* d_out, int out_size)
{
    (void)in_sizes; (void)n_in; (void)out_size;
    const float* x    = (const float*)d_in[0];
    const float* fc   = (const float*)d_in[1];
    const float* wqkv = (const float*)d_in[2];
    const float* wo   = (const float*)d_in[3];
    float* y = (float*)d_out;

    float* qkv_p = nullptr;
    __half *xh, *xl, *wqh, *wql, *woh, *ath;
    cudaGetSymbolAddress((void**)&qkv_p, g_qkv);
    cudaGetSymbolAddress((void**)&xh,  g_xh);  cudaGetSymbolAddress((void**)&xl,  g_xl);
    cudaGetSymbolAddress((void**)&wqh, g_wqh); cudaGetSymbolAddress((void**)&wql, g_wql);
    cudaGetSymbolAddress((void**)&woh, g_woh);
    cudaGetSymbolAddress((void**)&ath, g_ath);

    cudaFuncSetAttribute(attn_mma_kernel, cudaFuncAttributeMaxDynamicSharedMemorySize, SMEM_ATTN);
    cudaFuncSetAttribute(gemm_qkv,  cudaFuncAttributeMaxDynamicSharedMemorySize, 3 * 4 * GTILE);
    cudaFuncSetAttribute(gemm_wo64, cudaFuncAttributeMaxDynamicSharedMemorySize, SMEM_WO);

    // 0. split GEMM inputs to fp16 (x, wqkv: hi+lo; wo: hi only)
    {
        int n4x = (S * DIMM) / 4;
        split_kernel<<<(n4x + 255) / 256, 256>>>(x, xh, xl, n4x);
        int n4q = (NQKV * DIMM) / 4;
        split_kernel<<<(n4q + 255) / 256, 256>>>(wqkv, wqh, wql, n4q);
        int n4o = (DIMM * DIMM) / 4;
        split_hi_kernel<<<(n4o + 255) / 256, 256>>>(wo, woh, n4o);
    }

    // 1. QKV projection (q/k: fp16 x3 — selection-exact; v: x2)
    gemm_qkv<<<dim3(NQKV / 128, S / 128), 256, 3 * 4 * GTILE>>>(
        xh, xl, wqh, wql, qkv_p, NQKV, DIMM);

    // 2. fused RoPE + fp16 hi/lo split of roped qkv
    {
        int n4 = (S * NQKV) / 4;
        rope_split_kernel<<<(n4 + 255) / 256, 256>>>(fc);
    }

    // 3. per-block key means + query mean
    kmean_kernel<<<(TB * HKV * HD) / 256, 256>>>();
    qmean_part_kernel<<<dim3(HQ, 16), 128>>>();
    qmean_final_kernel<<<(HQ * HD) / 128, 128>>>();

    // 4. scores + top-k block selection (shuffle-based argmax)
    scores_topk_kernel<<<HQ, TB>>>();

    // 5. tensor-core sparse causal attention (QK x2, PV x2)
    attn_mma_kernel<<<dim3(S / 64, HQ), 128, SMEM_ATTN>>>();

    // 6. output projection (fp16 x1, BK=64 — final op, error unamplified ~4e-4)
    gemm_wo64<<<dim3(DIMM / 128, S / 128), 256, SMEM_WO>>>(
        ath, woh, y, DIMM, DIMM);
}

// round 17
// speedup vs baseline: 1.2419x; 1.0257x over previous
#include <cuda_runtime.h>
#include <cuda_fp16.h>
#include <cstdint>

// ---------------------------------------------------------------------------
// Problem constants (fixed shapes)
// ---------------------------------------------------------------------------
#define S      4096
#define DIMM   4096
#define HQ     32
#define HKV    8
#define HD     128
#define NQKV   6144          // (HQ + 2*HKV) * HD
#define TB     512           // S / 8 blocks
#define SINKB  4             // ceil(30/8)
#define WINST  508           // window start block
#define MBTOP  100           // heavy blocks
#define KLBLK  108           // 4 sink + 4 window + 100 heavy
#define KSEL   (KLBLK * 8)   // 864 selected tokens per head
#define NEGF   (-1e30f)
#define SCALE  0.08838834764831845f   // 1/sqrt(128)
#define VCOL0  ((HQ + HKV) * HD)      // 5120 — first v column

// ---------------------------------------------------------------------------
// Scratch (static device globals — no runtime allocation allowed)
// ---------------------------------------------------------------------------
__device__ float g_qkv[(size_t)S * NQKV];     // qkv projections (fp32, roped in place)
__device__ float g_krep[TB * HKV * HD];       // per-block mean keys
__device__ float g_qmean[HQ * HD];            // mean query per head
__device__ float g_qpart[16][HQ * HD];        // partial q sums (deterministic 2-stage)
__device__ int   g_blk[HQ * KLBLK];           // selected block ids per head

// fp16 hi/lo split operands
__device__ __align__(16) __half g_xh[(size_t)S * DIMM];
__device__ __align__(16) __half g_xl[(size_t)S * DIMM];
__device__ __align__(16) __half g_wqh[(size_t)NQKV * DIMM];
__device__ __align__(16) __half g_wql[(size_t)NQKV * DIMM];
__device__ __align__(16) __half g_woh[(size_t)DIMM * DIMM];   // hi only (WO is fp16 x1)
__device__ __align__(16) __half g_ath[(size_t)S * DIMM];      // attention out (hi only)
__device__ __align__(16) __half g_qh[(size_t)S * NQKV];       // roped qkv hi
__device__ __align__(16) __half g_ql[(size_t)S * NQKV];       // roped qkv lo

// ---------------------------------------------------------------------------
// asm helpers (base-ISA only; no tcgen05 on this toolchain)
// ---------------------------------------------------------------------------
__device__ __forceinline__ uint32_t smem_to_u32(const void* smem_ptr) {
    uint32_t addr;
    asm("{ .reg .u64 tmp; cvta.to.shared.u64 tmp, %1; cvt.u32.u64 %0, tmp; }"
        : "=r"(addr) : "l"(smem_ptr));
    return addr;
}

__device__ __forceinline__ void ldsm4(uint32_t* r, uint32_t addr) {
    asm volatile("ldmatrix.sync.aligned.m8n8.x4.shared.b16 {%0,%1,%2,%3}, [%4];"
        : "=r"(r[0]), "=r"(r[1]), "=r"(r[2]), "=r"(r[3]) : "r"(addr));
}

__device__ __forceinline__ void ldsm4t(uint32_t* r, uint32_t addr) {
    asm volatile("ldmatrix.sync.aligned.m8n8.x4.trans.shared.b16 {%0,%1,%2,%3}, [%4];"
        : "=r"(r[0]), "=r"(r[1]), "=r"(r[2]), "=r"(r[3]) : "r"(addr));
}

__device__ __forceinline__ void mma_f16(float* d, const uint32_t* a, const uint32_t* b) {
    asm volatile("mma.sync.aligned.m16n8k16.row.col.f32.f16.f16.f32 "
        "{%0,%1,%2,%3}, {%4,%5,%6,%7}, {%8,%9}, {%0,%1,%2,%3};"
        : "+f"(d[0]), "+f"(d[1]), "+f"(d[2]), "+f"(d[3])
        : "r"(a[0]), "r"(a[1]), "r"(a[2]), "r"(a[3]), "r"(b[0]), "r"(b[1]));
}

#define CP16(dst, src) \
    asm volatile("cp.async.cg.shared.global [%0], [%1], 16;" :: "r"(dst), "l"(src))
#define CP_COMMIT() asm volatile("cp.async.commit_group;" ::: "memory")
#define CP_WAIT(n)  asm volatile("cp.async.wait_group %0;" :: "n"(n) : "memory")

__device__ __forceinline__ uint32_t pack_f16(float a, float b) {
    __half2 h = __floats2half2_rn(a, b);
    return *(uint32_t*)&h;
}

// ---------------------------------------------------------------------------
// fp32 -> fp16 hi/lo split (pre-pass), float4 per thread
// ---------------------------------------------------------------------------
__global__ void split_kernel(const float* __restrict__ in,
                             __half* __restrict__ hi,
                             __half* __restrict__ lo, int n4)
{
    int i = blockIdx.x * blockDim.x + threadIdx.x;
    if (i >= n4) return;
    float4 v = ((const float4*)in)[i];
    __half h0 = __float2half_rn(v.x);
    __half h1 = __float2half_rn(v.y);
    __half h2 = __float2half_rn(v.z);
    __half h3 = __float2half_rn(v.w);
    __half l0 = __float2half_rn(v.x - __half2float(h0));
    __half l1 = __float2half_rn(v.y - __half2float(h1));
    __half l2 = __float2half_rn(v.z - __half2float(h2));
    __half l3 = __float2half_rn(v.w - __half2float(h3));
    uint2 H, L;
    H.x = ((uint32_t)__half_as_ushort(h1) << 16) | __half_as_ushort(h0);
    H.y = ((uint32_t)__half_as_ushort(h3) << 16) | __half_as_ushort(h2);
    L.x = ((uint32_t)__half_as_ushort(l1) << 16) | __half_as_ushort(l0);
    L.y = ((uint32_t)__half_as_ushort(l3) << 16) | __half_as_ushort(l2);
    ((uint2*)hi)[i] = H;
    ((uint2*)lo)[i] = L;
}

// hi-only variant (for wo weights — WO GEMM runs fp16 x1)
__global__ void split_hi_kernel(const float* __restrict__ in,
                                __half* __restrict__ hi, int n4)
{
    int i = blockIdx.x * blockDim.x + threadIdx.x;
    if (i >= n4) return;
    float4 v = ((const float4*)in)[i];
    uint2 H;
    H.x = pack_f16(v.x, v.y);
    H.y = pack_f16(v.z, v.w);
    ((uint2*)hi)[i] = H;
}

// ---------------------------------------------------------------------------
// Fused RoPE + fp16 hi/lo split of the roped qkv tensor.
// ---------------------------------------------------------------------------
__global__ void rope_split_kernel(const float* __restrict__ fc)
{
    const int n4 = (S * NQKV) / 4;
    int i = blockIdx.x * blockDim.x + threadIdx.x;
    if (i >= n4) return;
    int col4 = i % (NQKV / 4);
    int s    = i / (NQKV / 4);
    int c    = col4 << 2;
    int hh   = c >> 7;             // head index 0..47
    float4 v = *(float4*)&g_qkv[(size_t)s * NQKV + c];
    if (hh < 40) {                 // q (0..31) and k (32..39) get rope
        float4 f = *(const float4*)&fc[s * HD + (c & 127)];
        float x0 = v.x, x1 = v.y, x2 = v.z, x3 = v.w;
        v.x = x0 * f.x - x1 * f.y;
        v.y = x1 * f.x + x0 * f.y;
        v.z = x2 * f.z - x3 * f.w;
        v.w = x3 * f.z + x2 * f.w;
        *(float4*)&g_qkv[(size_t)s * NQKV + c] = v;
    }
    __half h0 = __float2half_rn(v.x);
    __half h1 = __float2half_rn(v.y);
    __half h2 = __float2half_rn(v.z);
    __half h3 = __float2half_rn(v.w);
    __half l0 = __float2half_rn(v.x - __half2float(h0));
    __half l1 = __float2half_rn(v.y - __half2float(h1));
    __half l2 = __float2half_rn(v.z - __half2float(h2));
    __half l3 = __float2half_rn(v.w - __half2float(h3));
    uint2 H, L;
    H.x = ((uint32_t)__half_as_ushort(h1) << 16) | __half_as_ushort(h0);
    H.y = ((uint32_t)__half_as_ushort(h3) << 16) | __half_as_ushort(h2);
    L.x = ((uint32_t)__half_as_ushort(l1) << 16) | __half_as_ushort(l0);
    L.y = ((uint32_t)__half_as_ushort(l3) << 16) | __half_as_ushort(l2);
    size_t base = (size_t)s * NQKV + c;
    *(uint2*)&g_qh[base] = H;
    *(uint2*)&g_ql[base] = L;
}

// ---------------------------------------------------------------------------
// QKV tensor-core GEMM: C = A @ B^T, fp16, fp32 acc.
// q/k column tiles (bn < 5120): x3 (selection-exact). v tiles: x2.
// 128x128 tile, BK=32, 256 threads, swizzled smem, 3-stage pipeline, 2 CTAs/SM.
// ---------------------------------------------------------------------------
#define GTILE 8192                      // 128 rows x 64 bytes per variant

__global__ __launch_bounds__(256, 2)
void gemm_qkv(const __half* __restrict__ Ah, const __half* __restrict__ Al,
              const __half* __restrict__ Bh, const __half* __restrict__ Bl,
              float* __restrict__ C, int N, int K)
{
    constexpr uint32_t AHI = 0;
    constexpr uint32_t ALO = GTILE;
    constexpr uint32_t BHI = 2 * GTILE;
    constexpr uint32_t BLO = 3 * GTILE;
    constexpr uint32_t GB  = 4 * GTILE;

    extern __shared__ char smc[];
    const uint32_t sbase = smem_to_u32(smc);
    const int tid  = threadIdx.x;
    const int lane = tid & 31;
    const int wid  = tid >> 5;
    const int wm0  = (wid >> 2) << 6;
    const int wn0  = (wid & 3) << 5;
    const int bm   = blockIdx.y << 7;
    const int bn   = blockIdx.x << 7;
    const bool vblk = (bn >= VCOL0);    // v-head tile: skip B_lo entirely

    float acc[4][4][4];
#pragma unroll
    for (int i = 0; i < 4; ++i)
#pragma unroll
        for (int j = 0; j < 4; ++j)
#pragma unroll
            for (int q = 0; q < 4; ++q) acc[i][j][q] = 0.f;

    const int nch = K >> 5;

    auto issue = [&](int cc, uint32_t boff) {
        const int kb = cc << 5;
#pragma unroll
        for (int i2 = 0; i2 < 2; ++i2) {
            int u   = tid + (i2 << 8);
            int row = u >> 2;
            int k   = u & 3;
            int sw  = k ^ ((row >> 1) & 3);
            uint32_t d = sbase + boff + (uint32_t)(row * 64 + sw * 16);
            const int ge = kb + (k << 3);
            CP16(d + AHI, Ah + (size_t)(bm + row) * K + ge);
            CP16(d + BHI, Bh + (size_t)(bn + row) * K + ge);
            CP16(d + ALO, Al + (size_t)(bm + row) * K + ge);
            if (!vblk) CP16(d + BLO, Bl + (size_t)(bn + row) * K + ge);
        }
    };

    const int ar = lane & 15;
    const int ac = lane >> 4;
    const int br = (lane & 7) + (((lane >> 4) & 1) << 3);
    const int bc = (lane >> 3) & 1;

    issue(0, 0u);   CP_COMMIT();
    issue(1, GB);   CP_COMMIT();

    for (int c = 0; c < nch; ++c) {
        CP_WAIT(1);
        __syncthreads();

        if (c + 2 < nch) issue(c + 2, (uint32_t)((c + 2) % 3) * GB);
        CP_COMMIT();

        const uint32_t boff = (uint32_t)(c % 3) * GB;
#pragma unroll
        for (int ks = 0; ks < 2; ++ks) {
            uint32_t ahi[4][4], alo[4][4], bhi[2][4], blo[2][4];
            const int kc2 = ks << 1;
#pragma unroll
            for (int mt = 0; mt < 4; ++mt) {
                int r_ = wm0 + (mt << 4) + ar;
                int sw = (kc2 + ac) ^ ((r_ >> 1) & 3);
                uint32_t off = (uint32_t)(r_ * 64 + sw * 16);
                ldsm4(ahi[mt], sbase + boff + AHI + off);
                ldsm4(alo[mt], sbase + boff + ALO + off);
            }
#pragma unroll
            for (int np = 0; np < 2; ++np) {
                int r_ = wn0 + (np << 4) + br;
                int sw = (kc2 + bc) ^ ((r_ >> 1) & 3);
                uint32_t off = (uint32_t)(r_ * 64 + sw * 16);
                ldsm4(bhi[np], sbase + boff + BHI + off);
                if (!vblk) ldsm4(blo[np], sbase + boff + BLO + off);
            }
            // pass 1: hi*hi
#pragma unroll
            for (int mt = 0; mt < 4; ++mt)
#pragma unroll
                for (int nt = 0; nt < 4; ++nt)
                    mma_f16(acc[mt][nt], ahi[mt], &bhi[nt >> 1][(nt & 1) << 1]);
            // pass 2: hi*lo (skipped on v tiles)
            if (!vblk) {
#pragma unroll
                for (int mt = 0; mt < 4; ++mt)
#pragma unroll
                    for (int nt = 0; nt < 4; ++nt)
                        mma_f16(acc[mt][nt], ahi[mt], &blo[nt >> 1][(nt & 1) << 1]);
            }
            // pass 3: lo*hi
#pragma unroll
            for (int mt = 0; mt < 4; ++mt)
#pragma unroll
                for (int nt = 0; nt < 4; ++nt)
                    mma_f16(acc[mt][nt], alo[mt], &bhi[nt >> 1][(nt & 1) << 1]);
        }
    }

    const int er = lane >> 2;
    const int ec = (lane & 3) << 1;
#pragma unroll
    for (int mt = 0; mt < 4; ++mt) {
#pragma unroll
        for (int nt = 0; nt < 4; ++nt) {
            int r0 = bm + wm0 + (mt << 4) + er;
            int c0 = bn + wn0 + (nt << 3) + ec;
            *(float2*)(C + (size_t)r0 * N + c0)       = make_float2(acc[mt][nt][0], acc[mt][nt][1]);
            *(float2*)(C + (size_t)(r0 + 8) * N + c0) = make_float2(acc[mt][nt][2], acc[mt][nt][3]);
        }
    }
}

// ---------------------------------------------------------------------------
// WO tensor-core GEMM: C = Ah @ Bh^T, fp16 x1, fp32 acc, BK=64.
// ---------------------------------------------------------------------------
#define WO_A 0
#define WO_B 16384
#define WO_GB 32768
#define SMEM_WO (3 * WO_GB)            // 98304

__global__ __launch_bounds__(256, 2)
void gemm_wo64(const __half* __restrict__ Ah, const __half* __restrict__ Bh,
               float* __restrict__ C, int N, int K)
{
    extern __shared__ char smc[];
    const uint32_t sbase = smem_to_u32(smc);
    const int tid  = threadIdx.x;
    const int lane = tid & 31;
    const int wid  = tid >> 5;
    const int wm0  = (wid >> 2) << 6;
    const int wn0  = (wid & 3) << 5;
    const int bm   = blockIdx.y << 7;
    const int bn   = blockIdx.x << 7;

    float acc[4][4][4];
#pragma unroll
    for (int i = 0; i < 4; ++i)
#pragma unroll
        for (int j = 0; j < 4; ++j)
#pragma unroll
            for (int q = 0; q < 4; ++q) acc[i][j][q] = 0.f;

    const int nch = K >> 6;            // 64-wide chunks

    auto issue = [&](int cc, uint32_t boff) {
        const int kb = cc << 6;
#pragma unroll
        for (int i2 = 0; i2 < 4; ++i2) {
            int u   = tid + (i2 << 8);      // 0..1023
            int row = u >> 3;
            int k   = u & 7;
            int sub = k >> 2;
            int sw  = (k & 3) ^ ((row >> 1) & 3);
            uint32_t d = sbase + boff + (uint32_t)(sub * 8192 + row * 64 + sw * 16);
            const int ge = kb + (k << 3);
            CP16(d + WO_A, Ah + (size_t)(bm + row) * K + ge);
            CP16(d + WO_B, Bh + (size_t)(bn + row) * K + ge);
        }
    };

    const int ar = lane & 15;
    const int ac = lane >> 4;
    const int br = (lane & 7) + (((lane >> 4) & 1) << 3);
    const int bc = (lane >> 3) & 1;

    issue(0, 0u);       CP_COMMIT();
    issue(1, WO_GB);    CP_COMMIT();

    for (int c = 0; c < nch; ++c) {
        CP_WAIT(1);
        __syncthreads();

        if (c + 2 < nch) issue(c + 2, (uint32_t)((c + 2) % 3) * WO_GB);
        CP_COMMIT();

        const uint32_t boff = (uint32_t)(c % 3) * WO_GB;
#pragma unroll
        for (int ks = 0; ks < 4; ++ks) {
            const uint32_t suboff = (uint32_t)((ks >> 1) * 8192);
            const int kc2 = (ks & 1) << 1;
            uint32_t ahi[4][4], bhi[2][4];
#pragma unroll
            for (int mt = 0; mt < 4; ++mt) {
                int r_ = wm0 + (mt << 4) + ar;
                int sw = (kc2 + ac) ^ ((r_ >> 1) & 3);
                ldsm4(ahi[mt], sbase + boff + WO_A + suboff + (uint32_t)(r_ * 64 + sw * 16));
            }
#pragma unroll
            for (int np = 0; np < 2; ++np) {
                int r_ = wn0 + (np << 4) + br;
                int sw = (kc2 + bc) ^ ((r_ >> 1) & 3);
                ldsm4(bhi[np], sbase + boff + WO_B + suboff + (uint32_t)(r_ * 64 + sw * 16));
            }
#pragma unroll
            for (int mt = 0; mt < 4; ++mt)
#pragma unroll
                for (int nt = 0; nt < 4; ++nt)
                    mma_f16(acc[mt][nt], ahi[mt], &bhi[nt >> 1][(nt & 1) << 1]);
        }
    }

    const int er = lane >> 2;
    const int ec = (lane & 3) << 1;
#pragma unroll
    for (int mt = 0; mt < 4; ++mt) {
#pragma unroll
        for (int nt = 0; nt < 4; ++nt) {
            int r0 = bm + wm0 + (mt << 4) + er;
            int c0 = bn + wn0 + (nt << 3) + ec;
            *(float2*)(C + (size_t)r0 * N + c0)       = make_float2(acc[mt][nt][0], acc[mt][nt][1]);
            *(float2*)(C + (size_t)(r0 + 8) * N + c0) = make_float2(acc[mt][nt][2], acc[mt][nt][3]);
        }
    }
}

// ---------------------------------------------------------------------------
// Per-block key means (8 tokens per block)
// ---------------------------------------------------------------------------
__global__ void kmean_kernel()
{
    int idx = blockIdx.x * blockDim.x + threadIdx.x;
    int d  = idx & 127;
    int hl = (idx >> 7) & 7;
    int t  = idx >> 10;
    const float* p = &g_qkv[(size_t)(t * 8) * NQKV + HQ * HD + hl * HD + d];
    float s = 0.f;
#pragma unroll
    for (int i = 0; i < 8; ++i) s += p[(size_t)i * NQKV];
    g_krep[idx] = s * 0.125f;
}

// ---------------------------------------------------------------------------
// Mean query per head — deterministic 2-stage
// ---------------------------------------------------------------------------
__global__ void qmean_part_kernel()
{
    int h = blockIdx.x, chunk = blockIdx.y, d = threadIdx.x;
    const float* p = &g_qkv[(size_t)(chunk * 256) * NQKV + h * HD + d];
    float s = 0.f;
#pragma unroll 4
    for (int i = 0; i < 256; ++i) s += p[(size_t)i * NQKV];
    g_qpart[chunk][h * HD + d] = s;
}

__global__ void qmean_final_kernel()
{
    int idx = blockIdx.x * blockDim.x + threadIdx.x;
    float s = 0.f;
#pragma unroll
    for (int i = 0; i < 16; ++i) s += g_qpart[i][idx];
    g_qmean[idx] = s * (1.f / 4096.f);
}

// ---------------------------------------------------------------------------
// Scores + top-k block selection. One block per head, 512 threads.
// Shuffle-based argmax. Tie-break = lower index (matches jax.lax.top_k).
// ---------------------------------------------------------------------------
__global__ void scores_topk_kernel()
{
    __shared__ float qm[HD];
    __shared__ float sc[TB];
    __shared__ float wv[16];
    __shared__ int   wi[16];

    const int h    = blockIdx.x;
    const int t    = threadIdx.x;
    const int lane = t & 31;
    const int wrp  = t >> 5;
    const int hl   = h >> 2;

    if (t < HD) qm[t] = g_qmean[h * HD + t];
    __syncthreads();

    float s = 0.f;
    const float* kr = &g_krep[(t * HKV + hl) * HD];
#pragma unroll 8
    for (int d = 0; d < HD; ++d) s += qm[d] * kr[d];
    s *= SCALE;

    bool masked = (t < SINKB) || (t >= WINST);
    sc[t] = masked ? NEGF : s;

    if (t < 4) {
        g_blk[h * KLBLK + t]     = t;
        g_blk[h * KLBLK + 4 + t] = WINST + t;
    }
    __syncthreads();

    for (int pick = 0; pick < MBTOP; ++pick) {
        float v = sc[t];
        int   i = t;
#pragma unroll
        for (int off = 16; off > 0; off >>= 1) {
            float v2 = __shfl_down_sync(0xffffffffu, v, off);
            int   i2 = __shfl_down_sync(0xffffffffu, i, off);
            if (v2 > v || (v2 == v && i2 < i)) { v = v2; i = i2; }
        }
        if (lane == 0) { wv[wrp] = v; wi[wrp] = i; }
        __syncthreads();
        if (t < 32) {
            float fv = (t < 16) ? wv[t] : -3e30f;
            int   fi = (t < 16) ? wi[t] : 0x7fffffff;
#pragma unroll
            for (int off = 8; off > 0; off >>= 1) {
                float v2 = __shfl_down_sync(0xffffffffu, fv, off);
                int   i2 = __shfl_down_sync(0xffffffffu, fi, off);
                if (v2 > fv || (v2 == fv && i2 < fi)) { fv = v2; fi = i2; }
            }
            if (t == 0) {
                g_blk[h * KLBLK + 8 + pick] = fi;
                sc[fi] = -2e30f;
            }
        }
        __syncthreads();
    }
}

// ---------------------------------------------------------------------------
// Tensor-core flash attention over 864 selected tokens per head.
// Pure fp16 x1 inside: scores = Qh·Kh, O += Ph·Vh. All lo-plane errors are
// smooth-path (softmax/PV/WO), each ~2e-4, adding in quadrature; the discrete
// top-k chain runs off fp32 g_qkv and is untouched.
// grid = (S/64, HQ), 128 threads (4 warps x 16 q-rows).
// ---------------------------------------------------------------------------
#define ASTRIDE 272                 // smem row stride in bytes (136 fp16)
#define QH_OFF  0
#define KH_OFF  17408
#define VH_OFF  26112
#define TOK_OFF 34816
#define FLG_OFF 34944
#define SMEM_ATTN 35008

__global__ __launch_bounds__(128)
void attn_mma_kernel()
{
    extern __shared__ char smb[];
    const uint32_t sb = smem_to_u32(smb);
    int* toks = (int*)(smb + TOK_OFF);
    int* sflg = (int*)(smb + FLG_OFF);

    const int tid  = threadIdx.x;
    const int lane = tid & 31;
    const int wid  = tid >> 5;
    const int h    = blockIdx.y;
    const int q0   = blockIdx.x << 6;
    const int hl   = h >> 2;
    const int m0   = wid << 4;

    const int er = lane >> 2;
    const int ec = (lane & 3) << 1;

    // load Q tile rows q0..q0+63, head slice (hi only)
    {
        const size_t qcol = (size_t)h * HD;
        for (int t = tid; t < 1024; t += 128) {
            int r = t >> 4, ch = t & 15;
            uint32_t d = sb + (uint32_t)(r * ASTRIDE + ch * 16);
            const size_t src = (size_t)(q0 + r) * NQKV + qcol + ch * 8;
            CP16(d + QH_OFF, g_qh + src);
        }
    }
    CP_COMMIT();

    float oacc[16][4];
#pragma unroll
    for (int i = 0; i < 16; ++i)
#pragma unroll
        for (int j = 0; j < 4; ++j) oacc[i][j] = 0.f;
    float mrow0 = NEGF, mrow1 = NEGF, lrow0 = 0.f, lrow1 = 0.f;

    CP_WAIT(0);
    __syncthreads();

    for (int kt = 0; kt < KSEL / 32; ++kt) {
        if (tid < 32) {
            int j = kt * 32 + tid;
            int b = g_blk[h * KLBLK + (j >> 3)];
            toks[tid] = (b << 3) + (j & 7);
        }
        __syncthreads();
        if (tid == 0) {
            int mn = toks[0];
#pragma unroll
            for (int i = 1; i < 32; ++i) mn = min(mn, toks[i]);
            sflg[0] = (mn > q0 + 63);
        }
        __syncthreads();
        if (sflg[0]) continue;

        // gather K (hi) and V (hi) rows via cp.async
        {
            const size_t kcol = (size_t)HQ * HD + (size_t)hl * HD;
            for (int t = tid; t < 512; t += 128) {
                int r = t >> 4, ch = t & 15;
                size_t src = (size_t)toks[r] * NQKV + kcol + ch * 8;
                uint32_t d = sb + (uint32_t)(r * ASTRIDE + ch * 16);
                CP16(d + KH_OFF, g_qh + src);
                CP16(d + VH_OFF, g_qh + src + HKV * HD);
            }
        }
        CP_COMMIT(); CP_WAIT(0);
        __syncthreads();

        // ---- scores: S = Qh @ Kh^T (64x32), fp16 x1 ----
        float sc[4][4];
#pragma unroll
        for (int i = 0; i < 4; ++i)
#pragma unroll
            for (int j = 0; j < 4; ++j) sc[i][j] = 0.f;

#pragma unroll
        for (int ks = 0; ks < 8; ++ks) {
            const int kc = ks << 4;
            uint32_t ah[4], kh0[4], kh1[4];
            uint32_t aoff = (uint32_t)((m0 + (lane & 15)) * ASTRIDE)
                          + (uint32_t)((kc + ((lane >> 4) << 3)) * 2);
            ldsm4(ah, sb + QH_OFF + aoff);
            uint32_t boff = (uint32_t)((((lane & 7) + (((lane >> 4) & 1) << 3)) * ASTRIDE))
                          + (uint32_t)((kc + (((lane >> 3) & 1) << 3)) * 2);
            ldsm4(kh0, sb + KH_OFF + boff);
            ldsm4(kh1, sb + KH_OFF + boff + 16 * ASTRIDE);
#pragma unroll
            for (int nt = 0; nt < 4; ++nt)
                mma_f16(sc[nt], ah, (nt < 2) ? &kh0[(nt & 1) << 1] : &kh1[(nt & 1) << 1]);
        }

        // ---- scale + causal mask ----
        const int qr0 = q0 + m0 + er;
        const int qr1 = qr0 + 8;
#pragma unroll
        for (int nt = 0; nt < 4; ++nt) {
            int2 tt = *(int2*)&toks[(nt << 3) + ec];
            sc[nt][0] = (tt.x <= qr0) ? sc[nt][0] * SCALE : NEGF;
            sc[nt][1] = (tt.y <= qr0) ? sc[nt][1] * SCALE : NEGF;
            sc[nt][2] = (tt.x <= qr1) ? sc[nt][2] * SCALE : NEGF;
            sc[nt][3] = (tt.y <= qr1) ? sc[nt][3] * SCALE : NEGF;
        }

        // ---- online softmax on fragments (quad reductions) ----
        float mt0 = fmaxf(fmaxf(fmaxf(sc[0][0], sc[0][1]), fmaxf(sc[1][0], sc[1][1])),
                          fmaxf(fmaxf(sc[2][0], sc[2][1]), fmaxf(sc[3][0], sc[3][1])));
        float mt1 = fmaxf(fmaxf(fmaxf(sc[0][2], sc[0][3]), fmaxf(sc[1][2], sc[1][3])),
                          fmaxf(fmaxf(sc[2][2], sc[2][3]), fmaxf(sc[3][2], sc[3][3])));
        mt0 = fmaxf(mt0, __shfl_xor_sync(0xffffffffu, mt0, 1));
        mt0 = fmaxf(mt0, __shfl_xor_sync(0xffffffffu, mt0, 2));
        mt1 = fmaxf(mt1, __shfl_xor_sync(0xffffffffu, mt1, 1));
        mt1 = fmaxf(mt1, __shfl_xor_sync(0xffffffffu, mt1, 2));
        float mn0 = fmaxf(mrow0, mt0);
        float mn1 = fmaxf(mrow1, mt1);
        float cc0 = __expf(mrow0 - mn0);
        float cc1 = __expf(mrow1 - mn1);
        float ls0 = 0.f, ls1 = 0.f;
#pragma unroll
        for (int nt = 0; nt < 4; ++nt) {
            float p0 = (sc[nt][0] > -1e29f) ? __expf(sc[nt][0] - mn0) : 0.f;
            float p1 = (sc[nt][1] > -1e29f) ? __expf(sc[nt][1] - mn0) : 0.f;
            float p2 = (sc[nt][2] > -1e29f) ? __expf(sc[nt][2] - mn1) : 0.f;
            float p3 = (sc[nt][3] > -1e29f) ? __expf(sc[nt][3] - mn1) : 0.f;
            sc[nt][0] = p0; sc[nt][1] = p1; sc[nt][2] = p2; sc[nt][3] = p3;
            ls0 += p0 + p1; ls1 += p2 + p3;
        }
        ls0 += __shfl_xor_sync(0xffffffffu, ls0, 1);
        ls0 += __shfl_xor_sync(0xffffffffu, ls0, 2);
        ls1 += __shfl_xor_sync(0xffffffffu, ls1, 1);
        ls1 += __shfl_xor_sync(0xffffffffu, ls1, 2);
        lrow0 = lrow0 * cc0 + ls0;  mrow0 = mn0;
        lrow1 = lrow1 * cc1 + ls1;  mrow1 = mn1;

#pragma unroll
        for (int nt = 0; nt < 16; ++nt) {
            oacc[nt][0] *= cc0; oacc[nt][1] *= cc0;
            oacc[nt][2] *= cc1; oacc[nt][3] *= cc1;
        }

        // ---- pack P into A fragments (hi only, fp16) ----
        uint32_t ph[2][4];
#pragma unroll
        for (int ks = 0; ks < 2; ++ks) {
#pragma unroll
            for (int hh = 0; hh < 2; ++hh) {
                int nt = (ks << 1) + hh;
                ph[ks][(hh << 1) + 0] = pack_f16(sc[nt][0], sc[nt][1]);
                ph[ks][(hh << 1) + 1] = pack_f16(sc[nt][2], sc[nt][3]);
            }
        }

        // ---- O += P @ V (64x128), fp16 x1 ----
#pragma unroll
        for (int ks = 0; ks < 2; ++ks) {
#pragma unroll
            for (int ng = 0; ng < 8; ++ng) {
                uint32_t vh[4];
                uint32_t voff = (uint32_t)(((ks << 4) + (lane & 15)) * ASTRIDE)
                              + (uint32_t)(((ng << 4) + ((lane >> 4) << 3)) * 2);
                ldsm4t(vh, sb + VH_OFF + voff);
                mma_f16(oacc[2 * ng],     ph[ks], &vh[0]);
                mma_f16(oacc[2 * ng + 1], ph[ks], &vh[2]);
            }
        }
        __syncthreads();   // protect K/V smem before next tile's cp.async
    }

    // ---- epilogue: normalize, store fp16 (hi only — WO GEMM is fp16 x1) ----
    const float inv0 = 1.f / lrow0;
    const float inv1 = 1.f / lrow1;
    const int row0 = q0 + m0 + er;
    const int row1 = row0 + 8;
#pragma unroll
    for (int nt = 0; nt < 16; ++nt) {
        int col = h * HD + (nt << 3) + ec;
        *(uint32_t*)&g_ath[(size_t)row0 * DIMM + col] =
            pack_f16(oacc[nt][0] * inv0, oacc[nt][1] * inv0);
        *(uint32_t*)&g_ath[(size_t)row1 * DIMM + col] =
            pack_f16(oacc[nt][2] * inv1, oacc[nt][3] * inv1);
    }
}

// ---------------------------------------------------------------------------
// Host launcher
// ---------------------------------------------------------------------------
extern "C" void kernel_launch(void* const* d_in, const int* in_sizes, int n_in,
                              void* d_out, int out_size)
{
    (void)in_sizes; (void)n_in; (void)out_size;
    const float* x    = (const float*)d_in[0];
    const float* fc   = (const float*)d_in[1];
    const float* wqkv = (const float*)d_in[2];
    const float* wo   = (const float*)d_in[3];
    float* y = (float*)d_out;

    float* qkv_p = nullptr;
    __half *xh, *xl, *wqh, *wql, *woh, *ath;
    cudaGetSymbolAddress((void**)&qkv_p, g_qkv);
    cudaGetSymbolAddress((void**)&xh,  g_xh);  cudaGetSymbolAddress((void**)&xl,  g_xl);
    cudaGetSymbolAddress((void**)&wqh, g_wqh); cudaGetSymbolAddress((void**)&wql, g_wql);
    cudaGetSymbolAddress((void**)&woh, g_woh);
    cudaGetSymbolAddress((void**)&ath, g_ath);

    cudaFuncSetAttribute(attn_mma_kernel, cudaFuncAttributeMaxDynamicSharedMemorySize, SMEM_ATTN);
    cudaFuncSetAttribute(gemm_qkv,  cudaFuncAttributeMaxDynamicSharedMemorySize, 3 * 4 * GTILE);
    cudaFuncSetAttribute(gemm_wo64, cudaFuncAttributeMaxDynamicSharedMemorySize, SMEM_WO);

    // 0. split GEMM inputs to fp16 (x, wqkv: hi+lo; wo: hi only)
    {
        int n4x = (S * DIMM) / 4;
        split_kernel<<<(n4x + 255) / 256, 256>>>(x, xh, xl, n4x);
        int n4q = (NQKV * DIMM) / 4;
        split_kernel<<<(n4q + 255) / 256, 256>>>(wqkv, wqh, wql, n4q);
        int n4o = (DIMM * DIMM) / 4;
        split_hi_kernel<<<(n4o + 255) / 256, 256>>>(wo, woh, n4o);
    }

    // 1. QKV projection (q/k: fp16 x3 — selection-exact; v: x2)
    gemm_qkv<<<dim3(NQKV / 128, S / 128), 256, 3 * 4 * GTILE>>>(
        xh, xl, wqh, wql, qkv_p, NQKV, DIMM);

    // 2. fused RoPE + fp16 hi/lo split of roped qkv
    {
        int n4 = (S * NQKV) / 4;
        rope_split_kernel<<<(n4 + 255) / 256, 256>>>(fc);
    }

    // 3. per-block key means + query mean
    kmean_kernel<<<(TB * HKV * HD) / 256, 256>>>();
    qmean_part_kernel<<<dim3(HQ, 16), 128>>>();
    qmean_final_kernel<<<(HQ * HD) / 128, 128>>>();

    // 4. scores + top-k block selection (shuffle-based argmax)
    scores_topk_kernel<<<HQ, TB>>>();

    // 5. tensor-core sparse causal attention (QK x1, PV x1)
    attn_mma_kernel<<<dim3(S / 64, HQ), 128, SMEM_ATTN>>>();

    // 6. output projection (fp16 x1, BK=64 — final op, error unamplified ~4e-4)
    gemm_wo64<<<dim3(DIMM / 128, S / 128), 256, SMEM_WO>>>(
        ath, woh, y, DIMM, DIMM);
}